// round 1
// baseline (speedup 1.0000x reference)
#include <cuda_runtime.h>
#include <math.h>

#define BATCH 4
#define S_LEN 1024
#define EMB   1024
#define NH    16
#define HD    64

// ---------------- scratch (no allocations allowed) ----------------
__device__ float g_qkv [BATCH * S_LEN * 3 * EMB];   // [B,S,3E]
__device__ float g_kdeq[BATCH * NH * S_LEN * HD];   // [B*H, S, 64]
__device__ float g_attn[BATCH * S_LEN * EMB];       // [B,S,E]

// ---------------- GEMM: C[M,N] = A[M,K] * B[K,N] + bias ----------------
// BM=BN=128, BK=8, 256 threads, 8x8 microtile, register prefetch.
__global__ __launch_bounds__(256) void gemm_bias_kernel(
    const float* __restrict__ A, const float* __restrict__ B,
    const float* __restrict__ bias, float* __restrict__ C,
    int M, int N, int K)
{
    __shared__ float As[8][128];   // As[k][m]
    __shared__ float Bs[8][128];   // Bs[k][n]

    const int tid = threadIdx.x;
    const int bx = blockIdx.x, by = blockIdx.y;

    const float* Ablk = A + (size_t)by * 128 * K;
    const float* Bblk = B + (size_t)bx * 128;

    const int a_row = tid >> 1;            // 0..127
    const int a_col = (tid & 1) * 4;       // 0 or 4 (within BK)
    const int b_row = tid >> 5;            // 0..7
    const int b_col = (tid & 31) * 4;      // 0..124
    const int ty = tid >> 4;               // 0..15
    const int tx = tid & 15;               // 0..15

    float acc[8][8];
    #pragma unroll
    for (int i = 0; i < 8; i++)
        #pragma unroll
        for (int j = 0; j < 8; j++) acc[i][j] = 0.0f;

    float4 a_pref = *(const float4*)(Ablk + (size_t)a_row * K + a_col);
    float4 b_pref = *(const float4*)(Bblk + (size_t)b_row * N + b_col);

    const int nt = K >> 3;
    for (int t = 0; t < nt; ++t) {
        As[a_col + 0][a_row] = a_pref.x;
        As[a_col + 1][a_row] = a_pref.y;
        As[a_col + 2][a_row] = a_pref.z;
        As[a_col + 3][a_row] = a_pref.w;
        *(float4*)&Bs[b_row][b_col] = b_pref;
        __syncthreads();

        if (t + 1 < nt) {
            a_pref = *(const float4*)(Ablk + (size_t)a_row * K + (t + 1) * 8 + a_col);
            b_pref = *(const float4*)(Bblk + (size_t)((t + 1) * 8 + b_row) * N + b_col);
        }

        #pragma unroll
        for (int k = 0; k < 8; ++k) {
            float4 a0 = *(const float4*)&As[k][ty * 4];
            float4 a1 = *(const float4*)&As[k][64 + ty * 4];
            float4 b0 = *(const float4*)&Bs[k][tx * 4];
            float4 b1 = *(const float4*)&Bs[k][64 + tx * 4];
            float af[8] = {a0.x, a0.y, a0.z, a0.w, a1.x, a1.y, a1.z, a1.w};
            float bf[8] = {b0.x, b0.y, b0.z, b0.w, b1.x, b1.y, b1.z, b1.w};
            #pragma unroll
            for (int i = 0; i < 8; i++)
                #pragma unroll
                for (int j = 0; j < 8; j++)
                    acc[i][j] += af[i] * bf[j];
        }
        __syncthreads();
    }

    const int col0 = bx * 128 + tx * 4;
    float4 bv0 = *(const float4*)&bias[col0];
    float4 bv1 = *(const float4*)&bias[col0 + 64];

    #pragma unroll
    for (int half = 0; half < 2; ++half) {
        #pragma unroll
        for (int i = 0; i < 4; ++i) {
            int row = by * 128 + half * 64 + ty * 4 + i;
            int ii = half * 4 + i;
            float* cp = C + (size_t)row * N;
            float4 o0 = make_float4(acc[ii][0] + bv0.x, acc[ii][1] + bv0.y,
                                    acc[ii][2] + bv0.z, acc[ii][3] + bv0.w);
            float4 o1 = make_float4(acc[ii][4] + bv1.x, acc[ii][5] + bv1.y,
                                    acc[ii][6] + bv1.z, acc[ii][7] + bv1.w);
            *(float4*)(cp + col0)      = o0;
            *(float4*)(cp + col0 + 64) = o1;
        }
    }
}

// ---------------- KIVI 2-bit fake quant of K ----------------
// One thread per group of 4 consecutive head-dim elements.
__global__ __launch_bounds__(256) void quant_kernel(
    const float* __restrict__ qkv, float* __restrict__ kdeq)
{
    int gid = blockIdx.x * blockDim.x + threadIdx.x;   // 0 .. B*H*S*16-1
    int o = gid << 2;                                  // element index in kdeq
    int d  = o & 63;
    int s  = (o >> 6) & (S_LEN - 1);
    int bh = o >> 16;                                  // S_LEN*HD = 65536
    int h  = bh & (NH - 1);
    int b  = bh >> 4;

    const float4 v = *(const float4*)(qkv + ((size_t)(b * S_LEN + s)) * (3 * EMB)
                                          + EMB + h * HD + d);
    float ma = fmaxf(fmaxf(fabsf(v.x), fabsf(v.y)), fmaxf(fabsf(v.z), fabsf(v.w)));
    float scale = ma * (1.0f / 1.5f);
    float safe = (scale == 0.0f) ? 1.0f : scale;

    float4 r;
    float cx = fminf(fmaxf(rintf(v.x / safe + 1.5f), 0.0f), 3.0f);
    float cy = fminf(fmaxf(rintf(v.y / safe + 1.5f), 0.0f), 3.0f);
    float cz = fminf(fmaxf(rintf(v.z / safe + 1.5f), 0.0f), 3.0f);
    float cw = fminf(fmaxf(rintf(v.w / safe + 1.5f), 0.0f), 3.0f);
    r.x = (cx - 1.5f) * scale;
    r.y = (cy - 1.5f) * scale;
    r.z = (cz - 1.5f) * scale;
    r.w = (cw - 1.5f) * scale;
    *(float4*)(kdeq + o) = r;
}

// ---------------- Flash attention (fp32, online softmax) ----------------
// Grid: B*H*(S/64) blocks, 128 threads. Q tile 64 rows, KV tile 64 rows.
// Thread (r,c): r=tid/8 owns 4 Q rows, c=tid%8 owns 8 score/O columns.
#define ATT_STRIDE 65
#define ATT_SMEM_FLOATS (4 * 64 * ATT_STRIDE + 64)

__global__ __launch_bounds__(128) void attention_kernel(
    const float* __restrict__ qkv, const float* __restrict__ kdeq,
    const float* __restrict__ mask, float* __restrict__ out)
{
    extern __shared__ float sm[];
    float* Qs = sm;
    float* Ks = Qs + 64 * ATT_STRIDE;
    float* Vs = Ks + 64 * ATT_STRIDE;
    float* Ps = Vs + 64 * ATT_STRIDE;
    float* Ms = Ps + 64 * ATT_STRIDE;

    const int tid = threadIdx.x;
    const int r = tid >> 3, c = tid & 7;
    const int r4 = r * 4, c8 = c * 8;

    const int bid = blockIdx.x;
    const int qt = bid & 15;
    const int h  = (bid >> 4) & 15;
    const int b  = bid >> 8;

    const size_t qbase = ((size_t)(b * S_LEN) + qt * 64) * (3 * EMB) + h * HD;
    const size_t vbase = ((size_t)(b * S_LEN)) * (3 * EMB) + 2 * EMB + h * HD;
    const float* kd = kdeq + ((size_t)(b * NH + h)) * S_LEN * HD;
    const float* mp = mask + b * S_LEN;

    for (int idx = tid; idx < 64 * 64; idx += 128) {
        int row = idx >> 6, dd = idx & 63;
        Qs[row * ATT_STRIDE + dd] = qkv[qbase + (size_t)row * (3 * EMB) + dd];
    }

    float m_i[4], l_i[4], o_acc[4][8];
    #pragma unroll
    for (int i = 0; i < 4; i++) {
        m_i[i] = -INFINITY; l_i[i] = 0.0f;
        #pragma unroll
        for (int j = 0; j < 8; j++) o_acc[i][j] = 0.0f;
    }
    __syncthreads();

    for (int kt = 0; kt < S_LEN / 64; ++kt) {
        for (int idx = tid; idx < 64 * 64; idx += 128) {
            int row = idx >> 6, dd = idx & 63;
            int krow = (kt << 6) + row;
            Ks[row * ATT_STRIDE + dd] = kd[(size_t)krow * HD + dd];
            Vs[row * ATT_STRIDE + dd] = qkv[vbase + (size_t)krow * (3 * EMB) + dd];
        }
        if (tid < 64) Ms[tid] = mp[(kt << 6) + tid];
        __syncthreads();

        // S = Q K^T
        float s[4][8];
        #pragma unroll
        for (int i = 0; i < 4; i++)
            #pragma unroll
            for (int j = 0; j < 8; j++) s[i][j] = 0.0f;

        for (int dd = 0; dd < 64; ++dd) {
            float qv[4], kv[8];
            #pragma unroll
            for (int i = 0; i < 4; i++) qv[i] = Qs[(r4 + i) * ATT_STRIDE + dd];
            #pragma unroll
            for (int j = 0; j < 8; j++) kv[j] = Ks[(c8 + j) * ATT_STRIDE + dd];
            #pragma unroll
            for (int i = 0; i < 4; i++)
                #pragma unroll
                for (int j = 0; j < 8; j++)
                    s[i][j] += qv[i] * kv[j];
        }

        // (scores + mask) * 1/sqrt(d), online softmax
        #pragma unroll
        for (int i = 0; i < 4; i++) {
            float rowmax = -INFINITY;
            #pragma unroll
            for (int j = 0; j < 8; j++) {
                s[i][j] = (s[i][j] + Ms[c8 + j]) * 0.125f;
                rowmax = fmaxf(rowmax, s[i][j]);
            }
            #pragma unroll
            for (int off = 1; off < 8; off <<= 1)
                rowmax = fmaxf(rowmax, __shfl_xor_sync(0xffffffffu, rowmax, off));

            float mnew = fmaxf(m_i[i], rowmax);
            float alpha = __expf(m_i[i] - mnew);
            float rsum = 0.0f;
            #pragma unroll
            for (int j = 0; j < 8; j++) {
                float p = __expf(s[i][j] - mnew);
                Ps[(r4 + i) * ATT_STRIDE + c8 + j] = p;
                rsum += p;
            }
            #pragma unroll
            for (int off = 1; off < 8; off <<= 1)
                rsum += __shfl_xor_sync(0xffffffffu, rsum, off);

            l_i[i] = l_i[i] * alpha + rsum;
            m_i[i] = mnew;
            #pragma unroll
            for (int j = 0; j < 8; j++) o_acc[i][j] *= alpha;
        }
        __syncthreads();

        // O += P V
        for (int kk = 0; kk < 64; ++kk) {
            float pv[4], vv[8];
            #pragma unroll
            for (int i = 0; i < 4; i++) pv[i] = Ps[(r4 + i) * ATT_STRIDE + kk];
            #pragma unroll
            for (int j = 0; j < 8; j++) vv[j] = Vs[kk * ATT_STRIDE + c8 + j];
            #pragma unroll
            for (int i = 0; i < 4; i++)
                #pragma unroll
                for (int j = 0; j < 8; j++)
                    o_acc[i][j] += pv[i] * vv[j];
        }
        __syncthreads();
    }

    // write O (merged heads layout [B,S,E])
    #pragma unroll
    for (int i = 0; i < 4; i++) {
        float linv = 1.0f / l_i[i];
        int srow = qt * 64 + r4 + i;
        float* op = out + ((size_t)(b * S_LEN + srow)) * EMB + h * HD + c8;
        float4 o0 = make_float4(o_acc[i][0] * linv, o_acc[i][1] * linv,
                                o_acc[i][2] * linv, o_acc[i][3] * linv);
        float4 o1 = make_float4(o_acc[i][4] * linv, o_acc[i][5] * linv,
                                o_acc[i][6] * linv, o_acc[i][7] * linv);
        *(float4*)(op)     = o0;
        *(float4*)(op + 4) = o1;
    }
}

// ---------------- launch ----------------
extern "C" void kernel_launch(void* const* d_in, const int* in_sizes, int n_in,
                              void* d_out, int out_size)
{
    const float* hidden = (const float*)d_in[0];
    const float* mask   = (const float*)d_in[1];
    const float* w_attn = (const float*)d_in[2];
    const float* b_attn = (const float*)d_in[3];
    const float* w_proj = (const float*)d_in[4];
    const float* b_proj = (const float*)d_in[5];
    float* out = (float*)d_out;

    float *qkv, *kdeq, *attn;
    cudaGetSymbolAddress((void**)&qkv,  g_qkv);
    cudaGetSymbolAddress((void**)&kdeq, g_kdeq);
    cudaGetSymbolAddress((void**)&attn, g_attn);

    const int att_smem = ATT_SMEM_FLOATS * (int)sizeof(float);
    cudaFuncSetAttribute(attention_kernel,
                         cudaFuncAttributeMaxDynamicSharedMemorySize, att_smem);

    // 1) QKV GEMM: [4096,1024] x [1024,3072] + b
    dim3 g1(3 * EMB / 128, BATCH * S_LEN / 128);
    gemm_bias_kernel<<<g1, 256>>>(hidden, w_attn, b_attn, qkv,
                                  BATCH * S_LEN, 3 * EMB, EMB);

    // 2) KIVI fake-quant K
    int ngroups = BATCH * NH * S_LEN * (HD / 4);
    quant_kernel<<<ngroups / 256, 256>>>(qkv, kdeq);

    // 3) attention
    attention_kernel<<<BATCH * NH * (S_LEN / 64), 128, att_smem>>>(qkv, kdeq, mask, attn);

    // 4) out projection: [4096,1024] x [1024,1024] + b
    dim3 g2(EMB / 128, BATCH * S_LEN / 128);
    gemm_bias_kernel<<<g2, 256>>>(attn, w_proj, b_proj, out,
                                  BATCH * S_LEN, EMB, EMB);
}

// round 2
// speedup vs baseline: 1.0023x; 1.0023x over previous
#include <cuda_runtime.h>
#include <math.h>

#define BATCH 4
#define S_LEN 1024
#define EMB   1024
#define NH    16
#define HD    64

// ---------------- scratch (no allocations allowed) ----------------
__device__ float g_qkv [BATCH * S_LEN * 3 * EMB];   // [B,S,3E]
__device__ float g_kdeq[BATCH * NH * S_LEN * HD];   // [B*H, S, 64]
__device__ float g_attn[BATCH * S_LEN * EMB];       // [B,S,E]

// ---------------- GEMM: C[M,N] = A[M,K] * B[K,N] + bias ----------------
// BM=BN=128, BK=8, 256 threads, 8x8 microtile, register prefetch.
__global__ __launch_bounds__(256) void gemm_bias_kernel(
    const float* __restrict__ A, const float* __restrict__ B,
    const float* __restrict__ bias, float* __restrict__ C,
    int M, int N, int K)
{
    __shared__ float As[8][128];   // As[k][m]
    __shared__ float Bs[8][128];   // Bs[k][n]

    const int tid = threadIdx.x;
    const int bx = blockIdx.x, by = blockIdx.y;

    const float* Ablk = A + (size_t)by * 128 * K;
    const float* Bblk = B + (size_t)bx * 128;

    const int a_row = tid >> 1;            // 0..127
    const int a_col = (tid & 1) * 4;       // 0 or 4 (within BK)
    const int b_row = tid >> 5;            // 0..7
    const int b_col = (tid & 31) * 4;      // 0..124
    const int ty = tid >> 4;               // 0..15
    const int tx = tid & 15;               // 0..15

    float acc[8][8];
    #pragma unroll
    for (int i = 0; i < 8; i++)
        #pragma unroll
        for (int j = 0; j < 8; j++) acc[i][j] = 0.0f;

    float4 a_pref = *(const float4*)(Ablk + (size_t)a_row * K + a_col);
    float4 b_pref = *(const float4*)(Bblk + (size_t)b_row * N + b_col);

    const int nt = K >> 3;
    for (int t = 0; t < nt; ++t) {
        As[a_col + 0][a_row] = a_pref.x;
        As[a_col + 1][a_row] = a_pref.y;
        As[a_col + 2][a_row] = a_pref.z;
        As[a_col + 3][a_row] = a_pref.w;
        *(float4*)&Bs[b_row][b_col] = b_pref;
        __syncthreads();

        if (t + 1 < nt) {
            a_pref = *(const float4*)(Ablk + (size_t)a_row * K + (t + 1) * 8 + a_col);
            b_pref = *(const float4*)(Bblk + (size_t)((t + 1) * 8 + b_row) * N + b_col);
        }

        #pragma unroll
        for (int k = 0; k < 8; ++k) {
            float4 a0 = *(const float4*)&As[k][ty * 4];
            float4 a1 = *(const float4*)&As[k][64 + ty * 4];
            float4 b0 = *(const float4*)&Bs[k][tx * 4];
            float4 b1 = *(const float4*)&Bs[k][64 + tx * 4];
            float af[8] = {a0.x, a0.y, a0.z, a0.w, a1.x, a1.y, a1.z, a1.w};
            float bf[8] = {b0.x, b0.y, b0.z, b0.w, b1.x, b1.y, b1.z, b1.w};
            #pragma unroll
            for (int i = 0; i < 8; i++)
                #pragma unroll
                for (int j = 0; j < 8; j++)
                    acc[i][j] += af[i] * bf[j];
        }
        __syncthreads();
    }

    const int col0 = bx * 128 + tx * 4;
    float4 bv0 = *(const float4*)&bias[col0];
    float4 bv1 = *(const float4*)&bias[col0 + 64];

    #pragma unroll
    for (int half = 0; half < 2; ++half) {
        #pragma unroll
        for (int i = 0; i < 4; ++i) {
            int row = by * 128 + half * 64 + ty * 4 + i;
            int ii = half * 4 + i;
            float* cp = C + (size_t)row * N;
            float4 o0 = make_float4(acc[ii][0] + bv0.x, acc[ii][1] + bv0.y,
                                    acc[ii][2] + bv0.z, acc[ii][3] + bv0.w);
            float4 o1 = make_float4(acc[ii][4] + bv1.x, acc[ii][5] + bv1.y,
                                    acc[ii][6] + bv1.z, acc[ii][7] + bv1.w);
            *(float4*)(cp + col0)      = o0;
            *(float4*)(cp + col0 + 64) = o1;
        }
    }
}

// ---------------- KIVI 2-bit fake quant of K ----------------
// One thread per group of 4 consecutive head-dim elements.
__global__ __launch_bounds__(256) void quant_kernel(
    const float* __restrict__ qkv, float* __restrict__ kdeq)
{
    int gid = blockIdx.x * blockDim.x + threadIdx.x;   // 0 .. B*H*S*16-1
    int o = gid << 2;                                  // element index in kdeq
    int d  = o & 63;
    int s  = (o >> 6) & (S_LEN - 1);
    int bh = o >> 16;                                  // S_LEN*HD = 65536
    int h  = bh & (NH - 1);
    int b  = bh >> 4;

    const float4 v = *(const float4*)(qkv + ((size_t)(b * S_LEN + s)) * (3 * EMB)
                                          + EMB + h * HD + d);
    float ma = fmaxf(fmaxf(fabsf(v.x), fabsf(v.y)), fmaxf(fabsf(v.z), fabsf(v.w)));
    float scale = ma * (1.0f / 1.5f);
    float safe = (scale == 0.0f) ? 1.0f : scale;

    float4 r;
    float cx = fminf(fmaxf(rintf(v.x / safe + 1.5f), 0.0f), 3.0f);
    float cy = fminf(fmaxf(rintf(v.y / safe + 1.5f), 0.0f), 3.0f);
    float cz = fminf(fmaxf(rintf(v.z / safe + 1.5f), 0.0f), 3.0f);
    float cw = fminf(fmaxf(rintf(v.w / safe + 1.5f), 0.0f), 3.0f);
    r.x = (cx - 1.5f) * scale;
    r.y = (cy - 1.5f) * scale;
    r.z = (cz - 1.5f) * scale;
    r.w = (cw - 1.5f) * scale;
    *(float4*)(kdeq + o) = r;
}

// ---------------- Flash attention (fp32, online softmax) ----------------
// Grid: B*H*(S/64) blocks, 128 threads. Q tile 64 rows, KV tile 64 rows.
// Thread (r,c): r=tid/8 owns 4 Q rows, c=tid%8 owns 8 score/O columns.
#define ATT_STRIDE 65
#define ATT_SMEM_FLOATS (4 * 64 * ATT_STRIDE + 64)

__global__ __launch_bounds__(128) void attention_kernel(
    const float* __restrict__ qkv, const float* __restrict__ kdeq,
    const float* __restrict__ mask, float* __restrict__ out)
{
    extern __shared__ float sm[];
    float* Qs = sm;
    float* Ks = Qs + 64 * ATT_STRIDE;
    float* Vs = Ks + 64 * ATT_STRIDE;
    float* Ps = Vs + 64 * ATT_STRIDE;
    float* Ms = Ps + 64 * ATT_STRIDE;

    const int tid = threadIdx.x;
    const int r = tid >> 3, c = tid & 7;
    const int r4 = r * 4, c8 = c * 8;

    const int bid = blockIdx.x;
    const int qt = bid & 15;
    const int h  = (bid >> 4) & 15;
    const int b  = bid >> 8;

    const size_t qbase = ((size_t)(b * S_LEN) + qt * 64) * (3 * EMB) + h * HD;
    const size_t vbase = ((size_t)(b * S_LEN)) * (3 * EMB) + 2 * EMB + h * HD;
    const float* kd = kdeq + ((size_t)(b * NH + h)) * S_LEN * HD;
    const float* mp = mask + b * S_LEN;

    for (int idx = tid; idx < 64 * 64; idx += 128) {
        int row = idx >> 6, dd = idx & 63;
        Qs[row * ATT_STRIDE + dd] = qkv[qbase + (size_t)row * (3 * EMB) + dd];
    }

    float m_i[4], l_i[4], o_acc[4][8];
    #pragma unroll
    for (int i = 0; i < 4; i++) {
        m_i[i] = -INFINITY; l_i[i] = 0.0f;
        #pragma unroll
        for (int j = 0; j < 8; j++) o_acc[i][j] = 0.0f;
    }
    __syncthreads();

    for (int kt = 0; kt < S_LEN / 64; ++kt) {
        for (int idx = tid; idx < 64 * 64; idx += 128) {
            int row = idx >> 6, dd = idx & 63;
            int krow = (kt << 6) + row;
            Ks[row * ATT_STRIDE + dd] = kd[(size_t)krow * HD + dd];
            Vs[row * ATT_STRIDE + dd] = qkv[vbase + (size_t)krow * (3 * EMB) + dd];
        }
        if (tid < 64) Ms[tid] = mp[(kt << 6) + tid];
        __syncthreads();

        // S = Q K^T
        float s[4][8];
        #pragma unroll
        for (int i = 0; i < 4; i++)
            #pragma unroll
            for (int j = 0; j < 8; j++) s[i][j] = 0.0f;

        for (int dd = 0; dd < 64; ++dd) {
            float qv[4], kv[8];
            #pragma unroll
            for (int i = 0; i < 4; i++) qv[i] = Qs[(r4 + i) * ATT_STRIDE + dd];
            #pragma unroll
            for (int j = 0; j < 8; j++) kv[j] = Ks[(c8 + j) * ATT_STRIDE + dd];
            #pragma unroll
            for (int i = 0; i < 4; i++)
                #pragma unroll
                for (int j = 0; j < 8; j++)
                    s[i][j] += qv[i] * kv[j];
        }

        // (scores + mask) * 1/sqrt(d), online softmax
        #pragma unroll
        for (int i = 0; i < 4; i++) {
            float rowmax = -INFINITY;
            #pragma unroll
            for (int j = 0; j < 8; j++) {
                s[i][j] = (s[i][j] + Ms[c8 + j]) * 0.125f;
                rowmax = fmaxf(rowmax, s[i][j]);
            }
            #pragma unroll
            for (int off = 1; off < 8; off <<= 1)
                rowmax = fmaxf(rowmax, __shfl_xor_sync(0xffffffffu, rowmax, off));

            float mnew = fmaxf(m_i[i], rowmax);
            float alpha = __expf(m_i[i] - mnew);
            float rsum = 0.0f;
            #pragma unroll
            for (int j = 0; j < 8; j++) {
                float p = __expf(s[i][j] - mnew);
                Ps[(r4 + i) * ATT_STRIDE + c8 + j] = p;
                rsum += p;
            }
            #pragma unroll
            for (int off = 1; off < 8; off <<= 1)
                rsum += __shfl_xor_sync(0xffffffffu, rsum, off);

            l_i[i] = l_i[i] * alpha + rsum;
            m_i[i] = mnew;
            #pragma unroll
            for (int j = 0; j < 8; j++) o_acc[i][j] *= alpha;
        }
        __syncthreads();

        // O += P V
        for (int kk = 0; kk < 64; ++kk) {
            float pv[4], vv[8];
            #pragma unroll
            for (int i = 0; i < 4; i++) pv[i] = Ps[(r4 + i) * ATT_STRIDE + kk];
            #pragma unroll
            for (int j = 0; j < 8; j++) vv[j] = Vs[kk * ATT_STRIDE + c8 + j];
            #pragma unroll
            for (int i = 0; i < 4; i++)
                #pragma unroll
                for (int j = 0; j < 8; j++)
                    o_acc[i][j] += pv[i] * vv[j];
        }
        __syncthreads();
    }

    // write O (merged heads layout [B,S,E])
    #pragma unroll
    for (int i = 0; i < 4; i++) {
        float linv = 1.0f / l_i[i];
        int srow = qt * 64 + r4 + i;
        float* op = out + ((size_t)(b * S_LEN + srow)) * EMB + h * HD + c8;
        float4 o0 = make_float4(o_acc[i][0] * linv, o_acc[i][1] * linv,
                                o_acc[i][2] * linv, o_acc[i][3] * linv);
        float4 o1 = make_float4(o_acc[i][4] * linv, o_acc[i][5] * linv,
                                o_acc[i][6] * linv, o_acc[i][7] * linv);
        *(float4*)(op)     = o0;
        *(float4*)(op + 4) = o1;
    }
}

// ---------------- launch ----------------
extern "C" void kernel_launch(void* const* d_in, const int* in_sizes, int n_in,
                              void* d_out, int out_size)
{
    const float* hidden = (const float*)d_in[0];
    const float* mask   = (const float*)d_in[1];
    const float* w_attn = (const float*)d_in[2];
    const float* b_attn = (const float*)d_in[3];
    const float* w_proj = (const float*)d_in[4];
    const float* b_proj = (const float*)d_in[5];
    float* out = (float*)d_out;

    float *qkv, *kdeq, *attn;
    cudaGetSymbolAddress((void**)&qkv,  g_qkv);
    cudaGetSymbolAddress((void**)&kdeq, g_kdeq);
    cudaGetSymbolAddress((void**)&attn, g_attn);

    const int att_smem = ATT_SMEM_FLOATS * (int)sizeof(float);
    cudaFuncSetAttribute(attention_kernel,
                         cudaFuncAttributeMaxDynamicSharedMemorySize, att_smem);

    // 1) QKV GEMM: [4096,1024] x [1024,3072] + b
    dim3 g1(3 * EMB / 128, BATCH * S_LEN / 128);
    gemm_bias_kernel<<<g1, 256>>>(hidden, w_attn, b_attn, qkv,
                                  BATCH * S_LEN, 3 * EMB, EMB);

    // 2) KIVI fake-quant K
    int ngroups = BATCH * NH * S_LEN * (HD / 4);
    quant_kernel<<<ngroups / 256, 256>>>(qkv, kdeq);

    // 3) attention
    attention_kernel<<<BATCH * NH * (S_LEN / 64), 128, att_smem>>>(qkv, kdeq, mask, attn);

    // 4) out projection: [4096,1024] x [1024,1024] + b
    dim3 g2(EMB / 128, BATCH * S_LEN / 128);
    gemm_bias_kernel<<<g2, 256>>>(attn, w_proj, b_proj, out,
                                  BATCH * S_LEN, EMB, EMB);
}

// round 4
// speedup vs baseline: 1.6019x; 1.5983x over previous
#include <cuda_runtime.h>
#include <math.h>
#include <stdint.h>

#define BATCH 4
#define S_LEN 1024
#define EMB   1024
#define NH    16
#define HD    64

// ---------------- scratch (no allocations allowed) ----------------
__device__ float g_qkv [BATCH * S_LEN * 3 * EMB];   // [B,S,3E]
__device__ float g_kdeq[BATCH * NH * S_LEN * HD];   // [B*H, S, 64]
__device__ float g_attn[BATCH * S_LEN * EMB];       // [B,S,E]

// ---------------- tf32 helpers ----------------
__device__ __forceinline__ uint32_t f2tf(float x) {
    uint32_t u;
    asm("cvt.rna.tf32.f32 %0, %1;" : "=r"(u) : "f"(x));
    return u;
}

// split x into hi (tf32) + lo (tf32 of residual): ~22 mantissa bits combined
__device__ __forceinline__ void split_tf(float x, uint32_t& h, uint32_t& l) {
    h = f2tf(x);
    l = f2tf(x - __uint_as_float(h));
}

__device__ __forceinline__ void mma8(float* d, const uint32_t* a, const uint32_t* b) {
    asm volatile(
        "mma.sync.aligned.m16n8k8.row.col.f32.tf32.tf32.f32 "
        "{%0,%1,%2,%3}, {%4,%5,%6,%7}, {%8,%9}, {%0,%1,%2,%3};"
        : "+f"(d[0]), "+f"(d[1]), "+f"(d[2]), "+f"(d[3])
        : "r"(a[0]), "r"(a[1]), "r"(a[2]), "r"(a[3]), "r"(b[0]), "r"(b[1]));
}

// ---------------- GEMM (3xTF32 tensor core): C = A*B + bias ----------------
// BM=BN=128, BK=16. 256 threads (8 warps, 2x4), warp tile 64x32.
// As row-major [m][k] stride 20 (=4 mod 32), Bs row-major [k][n] stride 136
// (=8 mod 32): all fragment LDS conflict-free, no transposes.
#define GA_S 20
#define GB_S 136
#define GA_BUF (128 * GA_S)
#define GB_BUF (16 * GB_S)
#define GEMM_SMEM_BYTES ((2 * GA_BUF * 2 + 2 * GB_BUF * 2) * 4)

__global__ __launch_bounds__(256) void gemm_tf32x3(
    const float* __restrict__ A, const float* __restrict__ B,
    const float* __restrict__ bias, float* __restrict__ C,
    int M, int N, int K)
{
    extern __shared__ uint32_t gsm[];
    uint32_t* Ah = gsm;                 // [2][GA_BUF]
    uint32_t* Al = Ah + 2 * GA_BUF;
    uint32_t* Bh = Al + 2 * GA_BUF;     // [2][GB_BUF]
    uint32_t* Bl = Bh + 2 * GB_BUF;

    const int tid = threadIdx.x;
    const int bx = blockIdx.x, by = blockIdx.y;
    const int lane = tid & 31, wid = tid >> 5;
    const int g = lane >> 2, tg = lane & 3;
    const int wm = (wid >> 2) * 64, wn = (wid & 3) * 32;

    const float* Ablk = A + (size_t)by * 128 * K;
    const float* Bblk = B + (size_t)bx * 128;

    float acc[4][4][4];
    #pragma unroll
    for (int mt = 0; mt < 4; mt++)
        #pragma unroll
        for (int nt = 0; nt < 4; nt++)
            #pragma unroll
            for (int i = 0; i < 4; i++) acc[mt][nt][i] = 0.0f;

    float4 pa[2], pb[2];
    #pragma unroll
    for (int i = 0; i < 2; i++) {
        int f = tid + 256 * i;
        pa[i] = *(const float4*)(Ablk + (size_t)(f >> 2) * K + (f & 3) * 4);
        pb[i] = *(const float4*)(Bblk + (size_t)(f >> 5) * N + (f & 31) * 4);
    }
    #pragma unroll
    for (int i = 0; i < 2; i++) {
        int f = tid + 256 * i;
        uint32_t* dah = &Ah[(f >> 2) * GA_S + (f & 3) * 4];
        uint32_t* dal = &Al[(f >> 2) * GA_S + (f & 3) * 4];
        split_tf(pa[i].x, dah[0], dal[0]); split_tf(pa[i].y, dah[1], dal[1]);
        split_tf(pa[i].z, dah[2], dal[2]); split_tf(pa[i].w, dah[3], dal[3]);
        uint32_t* dbh = &Bh[(f >> 5) * GB_S + (f & 31) * 4];
        uint32_t* dbl = &Bl[(f >> 5) * GB_S + (f & 31) * 4];
        split_tf(pb[i].x, dbh[0], dbl[0]); split_tf(pb[i].y, dbh[1], dbl[1]);
        split_tf(pb[i].z, dbh[2], dbl[2]); split_tf(pb[i].w, dbh[3], dbl[3]);
    }
    __syncthreads();

    const int ntiles = K >> 4;
    int buf = 0;
    for (int t = 0; t < ntiles; ++t) {
        if (t + 1 < ntiles) {
            #pragma unroll
            for (int i = 0; i < 2; i++) {
                int f = tid + 256 * i;
                pa[i] = *(const float4*)(Ablk + (size_t)(f >> 2) * K + (t + 1) * 16 + (f & 3) * 4);
                pb[i] = *(const float4*)(Bblk + (size_t)((t + 1) * 16 + (f >> 5)) * N + (f & 31) * 4);
            }
        }

        const uint32_t* ah = Ah + buf * GA_BUF;
        const uint32_t* al = Al + buf * GA_BUF;
        const uint32_t* bh = Bh + buf * GB_BUF;
        const uint32_t* bl = Bl + buf * GB_BUF;

        #pragma unroll
        for (int ks = 0; ks < 2; ++ks) {
            const int k0 = ks * 8;
            uint32_t afh[4][4], afl[4][4], bfh[4][2], bfl[4][2];
            #pragma unroll
            for (int mt = 0; mt < 4; mt++) {
                const int m0 = wm + mt * 16;
                afh[mt][0] = ah[(m0 + g) * GA_S + k0 + tg];
                afh[mt][1] = ah[(m0 + g + 8) * GA_S + k0 + tg];
                afh[mt][2] = ah[(m0 + g) * GA_S + k0 + tg + 4];
                afh[mt][3] = ah[(m0 + g + 8) * GA_S + k0 + tg + 4];
                afl[mt][0] = al[(m0 + g) * GA_S + k0 + tg];
                afl[mt][1] = al[(m0 + g + 8) * GA_S + k0 + tg];
                afl[mt][2] = al[(m0 + g) * GA_S + k0 + tg + 4];
                afl[mt][3] = al[(m0 + g + 8) * GA_S + k0 + tg + 4];
            }
            #pragma unroll
            for (int nt = 0; nt < 4; nt++) {
                const int n0 = wn + nt * 8;
                bfh[nt][0] = bh[(k0 + tg) * GB_S + n0 + g];
                bfh[nt][1] = bh[(k0 + tg + 4) * GB_S + n0 + g];
                bfl[nt][0] = bl[(k0 + tg) * GB_S + n0 + g];
                bfl[nt][1] = bl[(k0 + tg + 4) * GB_S + n0 + g];
            }
            #pragma unroll
            for (int mt = 0; mt < 4; mt++)
                #pragma unroll
                for (int nt = 0; nt < 4; nt++) {
                    mma8(acc[mt][nt], afh[mt], bfh[nt]);
                    mma8(acc[mt][nt], afh[mt], bfl[nt]);
                    mma8(acc[mt][nt], afl[mt], bfh[nt]);
                }
        }

        if (t + 1 < ntiles) {
            const int nb = buf ^ 1;
            #pragma unroll
            for (int i = 0; i < 2; i++) {
                int f = tid + 256 * i;
                uint32_t* dah = &Ah[nb * GA_BUF + (f >> 2) * GA_S + (f & 3) * 4];
                uint32_t* dal = &Al[nb * GA_BUF + (f >> 2) * GA_S + (f & 3) * 4];
                split_tf(pa[i].x, dah[0], dal[0]); split_tf(pa[i].y, dah[1], dal[1]);
                split_tf(pa[i].z, dah[2], dal[2]); split_tf(pa[i].w, dah[3], dal[3]);
                uint32_t* dbh = &Bh[nb * GB_BUF + (f >> 5) * GB_S + (f & 31) * 4];
                uint32_t* dbl = &Bl[nb * GB_BUF + (f >> 5) * GB_S + (f & 31) * 4];
                split_tf(pb[i].x, dbh[0], dbl[0]); split_tf(pb[i].y, dbh[1], dbl[1]);
                split_tf(pb[i].z, dbh[2], dbl[2]); split_tf(pb[i].w, dbh[3], dbl[3]);
            }
            __syncthreads();
            buf = nb;
        }
    }

    // epilogue: fragment (g,tg): rows g,g+8; cols 2tg,2tg+1
    #pragma unroll
    for (int mt = 0; mt < 4; mt++) {
        #pragma unroll
        for (int nt = 0; nt < 4; nt++) {
            const int col = bx * 128 + wn + nt * 8 + 2 * tg;
            const float bv0 = bias[col], bv1 = bias[col + 1];
            const int row0 = by * 128 + wm + mt * 16 + g;
            float2 v0 = make_float2(acc[mt][nt][0] + bv0, acc[mt][nt][1] + bv1);
            float2 v1 = make_float2(acc[mt][nt][2] + bv0, acc[mt][nt][3] + bv1);
            *(float2*)(C + (size_t)row0 * N + col)       = v0;
            *(float2*)(C + (size_t)(row0 + 8) * N + col) = v1;
        }
    }
}

// ---------------- KIVI 2-bit fake quant of K (fp32) ----------------
__global__ __launch_bounds__(256) void quant_kernel(
    const float* __restrict__ qkv, float* __restrict__ kdeq)
{
    int gid = blockIdx.x * blockDim.x + threadIdx.x;
    int o = gid << 2;
    int d  = o & 63;
    int s  = (o >> 6) & (S_LEN - 1);
    int bh = o >> 16;
    int h  = bh & (NH - 1);
    int b  = bh >> 4;

    const float4 v = *(const float4*)(qkv + ((size_t)(b * S_LEN + s)) * (3 * EMB)
                                          + EMB + h * HD + d);
    float ma = fmaxf(fmaxf(fabsf(v.x), fabsf(v.y)), fmaxf(fabsf(v.z), fabsf(v.w)));
    float scale = ma * (1.0f / 1.5f);
    float safe = (scale == 0.0f) ? 1.0f : scale;

    float4 r;
    float cx = fminf(fmaxf(rintf(v.x / safe + 1.5f), 0.0f), 3.0f);
    float cy = fminf(fmaxf(rintf(v.y / safe + 1.5f), 0.0f), 3.0f);
    float cz = fminf(fmaxf(rintf(v.z / safe + 1.5f), 0.0f), 3.0f);
    float cw = fminf(fmaxf(rintf(v.w / safe + 1.5f), 0.0f), 3.0f);
    r.x = (cx - 1.5f) * scale;
    r.y = (cy - 1.5f) * scale;
    r.z = (cz - 1.5f) * scale;
    r.w = (cw - 1.5f) * scale;
    *(float4*)(kdeq + o) = r;
}

// ---------------- Flash attention (3xTF32 QK^T, 2xTF32 PV) ----------------
// Grid: B*H*(S/128), 256 threads (8 warps). Warp w owns q-rows [16w,16w+16).
// Q tile 128x64, KV tile 64x64. Strides: 68 (=4 mod 32) for A-side tiles,
// 72 (=8 mod 32) for V: all fragment LDS conflict-free, no transposes.
#define SQ 68
#define SV 72
// Qh,Ql: 128*68 each; Kh,Kl: 64*68 each; P: 128*68; Vh,Vl: 64*72 each; M: 64
#define ATT_FLOATS (2 * 128 * SQ + 2 * 64 * SQ + 128 * SQ + 2 * 64 * SV + 64)

__global__ __launch_bounds__(256) void attn_tf32x3(
    const float* __restrict__ qkv, const float* __restrict__ kdeq,
    const float* __restrict__ mask, float* __restrict__ out)
{
    extern __shared__ uint32_t smu[];
    uint32_t* Qh = smu;
    uint32_t* Ql = Qh + 128 * SQ;
    uint32_t* Kh = Ql + 128 * SQ;
    uint32_t* Kl = Kh + 64 * SQ;
    uint32_t* Ps = Kl + 64 * SQ;
    uint32_t* Vh = Ps + 128 * SQ;
    uint32_t* Vl = Vh + 64 * SV;
    float*    Ms = (float*)(Vl + 64 * SV);

    const int tid = threadIdx.x, lane = tid & 31, wid = tid >> 5;
    const int g = lane >> 2, tg = lane & 3;
    const int m0 = wid * 16;

    const int bid = blockIdx.x;
    const int qt = bid & 7;
    const int h  = (bid >> 3) & 15;
    const int b  = bid >> 7;

    const size_t qbase = ((size_t)(b * S_LEN) + qt * 128) * (3 * EMB) + h * HD;
    const size_t vbase = ((size_t)(b * S_LEN)) * (3 * EMB) + 2 * EMB + h * HD;
    const float* kd = kdeq + ((size_t)(b * NH + h)) * S_LEN * HD;
    const float* mp = mask + b * S_LEN;

    // load Q tile (128x64) split hi/lo
    #pragma unroll
    for (int i = 0; i < 8; i++) {
        int f = tid + 256 * i;
        int row = f >> 4, d4 = (f & 15) * 4;
        float4 v = *(const float4*)(qkv + qbase + (size_t)row * (3 * EMB) + d4);
        uint32_t* dh = &Qh[row * SQ + d4];
        uint32_t* dl = &Ql[row * SQ + d4];
        split_tf(v.x, dh[0], dl[0]); split_tf(v.y, dh[1], dl[1]);
        split_tf(v.z, dh[2], dl[2]); split_tf(v.w, dh[3], dl[3]);
    }

    float m_i[2] = {-INFINITY, -INFINITY}, l_i[2] = {0.0f, 0.0f};
    float oa[8][4];
    #pragma unroll
    for (int nt = 0; nt < 8; nt++)
        #pragma unroll
        for (int i = 0; i < 4; i++) oa[nt][i] = 0.0f;

    for (int kt = 0; kt < S_LEN / 64; ++kt) {
        #pragma unroll
        for (int i = 0; i < 4; i++) {
            int f = tid + 256 * i;
            int row = f >> 4, d4 = (f & 15) * 4;
            int key = (kt << 6) + row;
            float4 kv = *(const float4*)(kd + (size_t)key * HD + d4);
            uint32_t* dkh = &Kh[row * SQ + d4];
            uint32_t* dkl = &Kl[row * SQ + d4];
            split_tf(kv.x, dkh[0], dkl[0]); split_tf(kv.y, dkh[1], dkl[1]);
            split_tf(kv.z, dkh[2], dkl[2]); split_tf(kv.w, dkh[3], dkl[3]);
            float4 vv = *(const float4*)(qkv + vbase + (size_t)key * (3 * EMB) + d4);
            uint32_t* dvh = &Vh[row * SV + d4];
            uint32_t* dvl = &Vl[row * SV + d4];
            split_tf(vv.x, dvh[0], dvl[0]); split_tf(vv.y, dvh[1], dvl[1]);
            split_tf(vv.z, dvh[2], dvl[2]); split_tf(vv.w, dvh[3], dvl[3]);
        }
        if (tid < 64) Ms[tid] = mp[(kt << 6) + tid];
        __syncthreads();

        // ---- S = Q K^T : m=16, n=64 (8 nt), k=64 (8 ks), 3xTF32 ----
        float sacc[8][4];
        #pragma unroll
        for (int nt = 0; nt < 8; nt++)
            #pragma unroll
            for (int i = 0; i < 4; i++) sacc[nt][i] = 0.0f;

        #pragma unroll
        for (int ks = 0; ks < 8; ++ks) {
            const int k0 = ks * 8;
            uint32_t ah[4], al[4];
            ah[0] = Qh[(m0 + g) * SQ + k0 + tg];
            ah[1] = Qh[(m0 + g + 8) * SQ + k0 + tg];
            ah[2] = Qh[(m0 + g) * SQ + k0 + tg + 4];
            ah[3] = Qh[(m0 + g + 8) * SQ + k0 + tg + 4];
            al[0] = Ql[(m0 + g) * SQ + k0 + tg];
            al[1] = Ql[(m0 + g + 8) * SQ + k0 + tg];
            al[2] = Ql[(m0 + g) * SQ + k0 + tg + 4];
            al[3] = Ql[(m0 + g + 8) * SQ + k0 + tg + 4];
            #pragma unroll
            for (int nt = 0; nt < 8; ++nt) {
                uint32_t bh[2], bl[2];
                bh[0] = Kh[(nt * 8 + g) * SQ + k0 + tg];
                bh[1] = Kh[(nt * 8 + g) * SQ + k0 + tg + 4];
                bl[0] = Kl[(nt * 8 + g) * SQ + k0 + tg];
                bl[1] = Kl[(nt * 8 + g) * SQ + k0 + tg + 4];
                mma8(sacc[nt], ah, bh);
                mma8(sacc[nt], ah, bl);
                mma8(sacc[nt], al, bh);
            }
        }

        // ---- online softmax: rows g (regs 0,1) and g+8 (regs 2,3) ----
        #pragma unroll
        for (int rr = 0; rr < 2; ++rr) {
            float mx = -INFINITY;
            #pragma unroll
            for (int nt = 0; nt < 8; nt++) {
                const int c0 = nt * 8 + 2 * tg;
                float s0 = (sacc[nt][rr * 2 + 0] + Ms[c0]) * 0.125f;
                float s1 = (sacc[nt][rr * 2 + 1] + Ms[c0 + 1]) * 0.125f;
                sacc[nt][rr * 2 + 0] = s0;
                sacc[nt][rr * 2 + 1] = s1;
                mx = fmaxf(mx, fmaxf(s0, s1));
            }
            mx = fmaxf(mx, __shfl_xor_sync(0xffffffffu, mx, 1));
            mx = fmaxf(mx, __shfl_xor_sync(0xffffffffu, mx, 2));
            const float mnew = fmaxf(m_i[rr], mx);
            const float alpha = __expf(m_i[rr] - mnew);
            float rs = 0.0f;
            const int row = m0 + g + rr * 8;
            #pragma unroll
            for (int nt = 0; nt < 8; nt++) {
                float p0 = __expf(sacc[nt][rr * 2 + 0] - mnew);
                float p1 = __expf(sacc[nt][rr * 2 + 1] - mnew);
                rs += p0 + p1;
                uint32_t* pp = &Ps[row * SQ + nt * 8 + 2 * tg];
                pp[0] = f2tf(p0); pp[1] = f2tf(p1);
            }
            rs += __shfl_xor_sync(0xffffffffu, rs, 1);
            rs += __shfl_xor_sync(0xffffffffu, rs, 2);
            l_i[rr] = l_i[rr] * alpha + rs;
            m_i[rr] = mnew;
            #pragma unroll
            for (int nt = 0; nt < 8; nt++) {
                oa[nt][rr * 2 + 0] *= alpha;
                oa[nt][rr * 2 + 1] *= alpha;
            }
        }
        __syncwarp();   // P rows are warp-private

        // ---- O += P V : k=64 keys (8 ks), n=64 dims (8 nt), P-hi x (Vh+Vl) ----
        #pragma unroll
        for (int ks = 0; ks < 8; ++ks) {
            const int k0 = ks * 8;
            uint32_t ap[4];
            ap[0] = Ps[(m0 + g) * SQ + k0 + tg];
            ap[1] = Ps[(m0 + g + 8) * SQ + k0 + tg];
            ap[2] = Ps[(m0 + g) * SQ + k0 + tg + 4];
            ap[3] = Ps[(m0 + g + 8) * SQ + k0 + tg + 4];
            #pragma unroll
            for (int nt = 0; nt < 8; ++nt) {
                uint32_t bh[2], bl[2];
                bh[0] = Vh[(k0 + tg) * SV + nt * 8 + g];
                bh[1] = Vh[(k0 + tg + 4) * SV + nt * 8 + g];
                bl[0] = Vl[(k0 + tg) * SV + nt * 8 + g];
                bl[1] = Vl[(k0 + tg + 4) * SV + nt * 8 + g];
                mma8(oa[nt], ap, bh);
                mma8(oa[nt], ap, bl);
            }
        }
        __syncthreads();   // before K/V/M tiles are overwritten
    }

    // ---- epilogue: normalize and write merged-head layout [B,S,E] ----
    #pragma unroll
    for (int rr = 0; rr < 2; ++rr) {
        const float inv = 1.0f / l_i[rr];
        const int srow = qt * 128 + m0 + g + rr * 8;
        float* op = out + ((size_t)(b * S_LEN + srow)) * EMB + h * HD;
        #pragma unroll
        for (int nt = 0; nt < 8; nt++) {
            float2 v = make_float2(oa[nt][rr * 2 + 0] * inv, oa[nt][rr * 2 + 1] * inv);
            *(float2*)(op + nt * 8 + 2 * tg) = v;
        }
    }
}

// ---------------- launch ----------------
extern "C" void kernel_launch(void* const* d_in, const int* in_sizes, int n_in,
                              void* d_out, int out_size)
{
    const float* hidden = (const float*)d_in[0];
    const float* mask   = (const float*)d_in[1];
    const float* w_attn = (const float*)d_in[2];
    const float* b_attn = (const float*)d_in[3];
    const float* w_proj = (const float*)d_in[4];
    const float* b_proj = (const float*)d_in[5];
    float* out = (float*)d_out;

    float *qkv, *kdeq, *attn;
    cudaGetSymbolAddress((void**)&qkv,  g_qkv);
    cudaGetSymbolAddress((void**)&kdeq, g_kdeq);
    cudaGetSymbolAddress((void**)&attn, g_attn);

    const int att_smem = ATT_FLOATS * (int)sizeof(float);
    cudaFuncSetAttribute(attn_tf32x3,
                         cudaFuncAttributeMaxDynamicSharedMemorySize, att_smem);
    cudaFuncSetAttribute(gemm_tf32x3,
                         cudaFuncAttributeMaxDynamicSharedMemorySize, GEMM_SMEM_BYTES);

    // 1) QKV GEMM: [4096,1024] x [1024,3072] + b
    dim3 g1(3 * EMB / 128, BATCH * S_LEN / 128);
    gemm_tf32x3<<<g1, 256, GEMM_SMEM_BYTES>>>(hidden, w_attn, b_attn, qkv,
                                              BATCH * S_LEN, 3 * EMB, EMB);

    // 2) KIVI fake-quant K
    int ngroups = BATCH * NH * S_LEN * (HD / 4);
    quant_kernel<<<ngroups / 256, 256>>>(qkv, kdeq);

    // 3) attention
    attn_tf32x3<<<BATCH * NH * (S_LEN / 128), 256, att_smem>>>(qkv, kdeq, mask, attn);

    // 4) out projection: [4096,1024] x [1024,1024] + b
    dim3 g2(EMB / 128, BATCH * S_LEN / 128);
    gemm_tf32x3<<<g2, 256, GEMM_SMEM_BYTES>>>(attn, w_proj, b_proj, out,
                                              BATCH * S_LEN, EMB, EMB);
}

// round 5
// speedup vs baseline: 2.1171x; 1.3216x over previous
#include <cuda_runtime.h>
#include <math.h>
#include <stdint.h>

#define BATCH 4
#define S_LEN 1024
#define EMB   1024
#define NH    16
#define HD    64

// ---------------- scratch (no allocations allowed) ----------------
__device__ float g_qkv [BATCH * S_LEN * 3 * EMB];   // [B,S,3E]
__device__ float g_attn[BATCH * S_LEN * EMB];       // [B,S,E]

// ---------------- tf32 helpers ----------------
__device__ __forceinline__ uint32_t f2tf(float x) {
    uint32_t u;
    asm("cvt.rna.tf32.f32 %0, %1;" : "=r"(u) : "f"(x));
    return u;
}

__device__ __forceinline__ void split_tf(float x, uint32_t& h, uint32_t& l) {
    h = f2tf(x);
    l = f2tf(x - __uint_as_float(h));
}

__device__ __forceinline__ void mma8(float* d, const uint32_t* a, const uint32_t* b) {
    asm volatile(
        "mma.sync.aligned.m16n8k8.row.col.f32.tf32.tf32.f32 "
        "{%0,%1,%2,%3}, {%4,%5,%6,%7}, {%8,%9}, {%0,%1,%2,%3};"
        : "+f"(d[0]), "+f"(d[1]), "+f"(d[2]), "+f"(d[3])
        : "r"(a[0]), "r"(a[1]), "r"(a[2]), "r"(a[3]), "r"(b[0]), "r"(b[1]));
}

// ---------------- GEMM with per-block-column precision ----------------
// BM=BN=128, BK=16, 256 threads (8 warps 2x4), warp tile 64x32.
// Block-cols in [c3lo,c3hi) use 3xTF32 (split hi/lo), others plain 1xTF32.
// As row-major [m][k] stride 20 (=4 mod 32), Bs row-major [k][n] stride 136
// (=8 mod 32): all fragment LDS conflict-free.
#define GA_S 20
#define GB_S 136
#define GA_BUF (128 * GA_S)
#define GB_BUF (16 * GB_S)
#define GEMM_SMEM_BYTES ((2 * GA_BUF * 2 + 2 * GB_BUF * 2) * 4)

__global__ __launch_bounds__(256) void gemm_tf32_mix(
    const float* __restrict__ A, const float* __restrict__ B,
    const float* __restrict__ bias, float* __restrict__ C,
    int M, int N, int K, int c3lo, int c3hi)
{
    extern __shared__ uint32_t gsm[];
    uint32_t* Ah = gsm;                 // [2][GA_BUF]
    uint32_t* Al = Ah + 2 * GA_BUF;
    uint32_t* Bh = Al + 2 * GA_BUF;     // [2][GB_BUF]
    uint32_t* Bl = Bh + 2 * GB_BUF;

    const int tid = threadIdx.x;
    const int bx = blockIdx.x, by = blockIdx.y;
    const bool use3x = (bx >= c3lo) && (bx < c3hi);
    const int lane = tid & 31, wid = tid >> 5;
    const int g = lane >> 2, tg = lane & 3;
    const int wm = (wid >> 2) * 64, wn = (wid & 3) * 32;

    const float* Ablk = A + (size_t)by * 128 * K;
    const float* Bblk = B + (size_t)bx * 128;

    float acc[4][4][4];
    #pragma unroll
    for (int mt = 0; mt < 4; mt++)
        #pragma unroll
        for (int nt = 0; nt < 4; nt++)
            #pragma unroll
            for (int i = 0; i < 4; i++) acc[mt][nt][i] = 0.0f;

    float4 pa[2], pb[2];
    #pragma unroll
    for (int i = 0; i < 2; i++) {
        int f = tid + 256 * i;
        pa[i] = *(const float4*)(Ablk + (size_t)(f >> 2) * K + (f & 3) * 4);
        pb[i] = *(const float4*)(Bblk + (size_t)(f >> 5) * N + (f & 31) * 4);
    }
    #pragma unroll
    for (int i = 0; i < 2; i++) {
        int f = tid + 256 * i;
        uint32_t* dah = &Ah[(f >> 2) * GA_S + (f & 3) * 4];
        uint32_t* dbh = &Bh[(f >> 5) * GB_S + (f & 31) * 4];
        if (use3x) {
            uint32_t* dal = &Al[(f >> 2) * GA_S + (f & 3) * 4];
            uint32_t* dbl = &Bl[(f >> 5) * GB_S + (f & 31) * 4];
            split_tf(pa[i].x, dah[0], dal[0]); split_tf(pa[i].y, dah[1], dal[1]);
            split_tf(pa[i].z, dah[2], dal[2]); split_tf(pa[i].w, dah[3], dal[3]);
            split_tf(pb[i].x, dbh[0], dbl[0]); split_tf(pb[i].y, dbh[1], dbl[1]);
            split_tf(pb[i].z, dbh[2], dbl[2]); split_tf(pb[i].w, dbh[3], dbl[3]);
        } else {
            dah[0] = f2tf(pa[i].x); dah[1] = f2tf(pa[i].y);
            dah[2] = f2tf(pa[i].z); dah[3] = f2tf(pa[i].w);
            dbh[0] = f2tf(pb[i].x); dbh[1] = f2tf(pb[i].y);
            dbh[2] = f2tf(pb[i].z); dbh[3] = f2tf(pb[i].w);
        }
    }
    __syncthreads();

    const int ntiles = K >> 4;
    int buf = 0;
    for (int t = 0; t < ntiles; ++t) {
        if (t + 1 < ntiles) {
            #pragma unroll
            for (int i = 0; i < 2; i++) {
                int f = tid + 256 * i;
                pa[i] = *(const float4*)(Ablk + (size_t)(f >> 2) * K + (t + 1) * 16 + (f & 3) * 4);
                pb[i] = *(const float4*)(Bblk + (size_t)((t + 1) * 16 + (f >> 5)) * N + (f & 31) * 4);
            }
        }

        const uint32_t* ah = Ah + buf * GA_BUF;
        const uint32_t* al = Al + buf * GA_BUF;
        const uint32_t* bh = Bh + buf * GB_BUF;
        const uint32_t* bl = Bl + buf * GB_BUF;

        #pragma unroll
        for (int ks = 0; ks < 2; ++ks) {
            const int k0 = ks * 8;
            uint32_t afh[4][4], bfh[4][2];
            #pragma unroll
            for (int mt = 0; mt < 4; mt++) {
                const int m0 = wm + mt * 16;
                afh[mt][0] = ah[(m0 + g) * GA_S + k0 + tg];
                afh[mt][1] = ah[(m0 + g + 8) * GA_S + k0 + tg];
                afh[mt][2] = ah[(m0 + g) * GA_S + k0 + tg + 4];
                afh[mt][3] = ah[(m0 + g + 8) * GA_S + k0 + tg + 4];
            }
            #pragma unroll
            for (int nt = 0; nt < 4; nt++) {
                const int n0 = wn + nt * 8;
                bfh[nt][0] = bh[(k0 + tg) * GB_S + n0 + g];
                bfh[nt][1] = bh[(k0 + tg + 4) * GB_S + n0 + g];
            }
            if (use3x) {
                uint32_t afl[4][4], bfl[4][2];
                #pragma unroll
                for (int mt = 0; mt < 4; mt++) {
                    const int m0 = wm + mt * 16;
                    afl[mt][0] = al[(m0 + g) * GA_S + k0 + tg];
                    afl[mt][1] = al[(m0 + g + 8) * GA_S + k0 + tg];
                    afl[mt][2] = al[(m0 + g) * GA_S + k0 + tg + 4];
                    afl[mt][3] = al[(m0 + g + 8) * GA_S + k0 + tg + 4];
                }
                #pragma unroll
                for (int nt = 0; nt < 4; nt++) {
                    const int n0 = wn + nt * 8;
                    bfl[nt][0] = bl[(k0 + tg) * GB_S + n0 + g];
                    bfl[nt][1] = bl[(k0 + tg + 4) * GB_S + n0 + g];
                }
                #pragma unroll
                for (int mt = 0; mt < 4; mt++)
                    #pragma unroll
                    for (int nt = 0; nt < 4; nt++) {
                        mma8(acc[mt][nt], afh[mt], bfh[nt]);
                        mma8(acc[mt][nt], afh[mt], bfl[nt]);
                        mma8(acc[mt][nt], afl[mt], bfh[nt]);
                    }
            } else {
                #pragma unroll
                for (int mt = 0; mt < 4; mt++)
                    #pragma unroll
                    for (int nt = 0; nt < 4; nt++)
                        mma8(acc[mt][nt], afh[mt], bfh[nt]);
            }
        }

        if (t + 1 < ntiles) {
            const int nb = buf ^ 1;
            #pragma unroll
            for (int i = 0; i < 2; i++) {
                int f = tid + 256 * i;
                uint32_t* dah = &Ah[nb * GA_BUF + (f >> 2) * GA_S + (f & 3) * 4];
                uint32_t* dbh = &Bh[nb * GB_BUF + (f >> 5) * GB_S + (f & 31) * 4];
                if (use3x) {
                    uint32_t* dal = &Al[nb * GA_BUF + (f >> 2) * GA_S + (f & 3) * 4];
                    uint32_t* dbl = &Bl[nb * GB_BUF + (f >> 5) * GB_S + (f & 31) * 4];
                    split_tf(pa[i].x, dah[0], dal[0]); split_tf(pa[i].y, dah[1], dal[1]);
                    split_tf(pa[i].z, dah[2], dal[2]); split_tf(pa[i].w, dah[3], dal[3]);
                    split_tf(pb[i].x, dbh[0], dbl[0]); split_tf(pb[i].y, dbh[1], dbl[1]);
                    split_tf(pb[i].z, dbh[2], dbl[2]); split_tf(pb[i].w, dbh[3], dbl[3]);
                } else {
                    dah[0] = f2tf(pa[i].x); dah[1] = f2tf(pa[i].y);
                    dah[2] = f2tf(pa[i].z); dah[3] = f2tf(pa[i].w);
                    dbh[0] = f2tf(pb[i].x); dbh[1] = f2tf(pb[i].y);
                    dbh[2] = f2tf(pb[i].z); dbh[3] = f2tf(pb[i].w);
                }
            }
            __syncthreads();
            buf = nb;
        }
    }

    // epilogue: fragment (g,tg): rows g,g+8; cols 2tg,2tg+1
    #pragma unroll
    for (int mt = 0; mt < 4; mt++) {
        #pragma unroll
        for (int nt = 0; nt < 4; nt++) {
            const int col = bx * 128 + wn + nt * 8 + 2 * tg;
            const float bv0 = bias[col], bv1 = bias[col + 1];
            const int row0 = by * 128 + wm + mt * 16 + g;
            float2 v0 = make_float2(acc[mt][nt][0] + bv0, acc[mt][nt][1] + bv1);
            float2 v1 = make_float2(acc[mt][nt][2] + bv0, acc[mt][nt][3] + bv1);
            *(float2*)(C + (size_t)row0 * N + col)       = v0;
            *(float2*)(C + (size_t)(row0 + 8) * N + col) = v1;
        }
    }
}

// ---------------- Flash attention (1xTF32) with fused KIVI quant ----------------
// Grid: B*H*(S/128), 256 threads (8 warps), 2 CTAs/SM (smem ~106KB).
// Q tile 128x64, KV tile 64x64. K dequantized on the fly: each float4 along D
// is exactly one KIVI group of 4.
#define SQ 68
#define SV 72
#define ATT_FLOATS (128 * SQ + 64 * SQ + 128 * SQ + 64 * SV + 64)

__global__ __launch_bounds__(256, 2) void attn_tf32_fused(
    const float* __restrict__ qkv, const float* __restrict__ mask,
    float* __restrict__ out)
{
    extern __shared__ uint32_t smu[];
    uint32_t* Qs = smu;
    uint32_t* Ks = Qs + 128 * SQ;
    uint32_t* Ps = Ks + 64 * SQ;
    uint32_t* Vs = Ps + 128 * SQ;
    float*    Ms = (float*)(Vs + 64 * SV);

    const int tid = threadIdx.x, lane = tid & 31, wid = tid >> 5;
    const int g = lane >> 2, tg = lane & 3;
    const int m0 = wid * 16;

    const int bid = blockIdx.x;
    const int qt = bid & 7;
    const int h  = (bid >> 3) & 15;
    const int b  = bid >> 7;

    const size_t qbase = ((size_t)(b * S_LEN) + qt * 128) * (3 * EMB) + h * HD;
    const size_t kbase = ((size_t)(b * S_LEN)) * (3 * EMB) + EMB + h * HD;
    const size_t vbase = ((size_t)(b * S_LEN)) * (3 * EMB) + 2 * EMB + h * HD;
    const float* mp = mask + b * S_LEN;

    // load Q tile (128x64)
    #pragma unroll
    for (int i = 0; i < 8; i++) {
        int f = tid + 256 * i;
        int row = f >> 4, d4 = (f & 15) * 4;
        float4 v = *(const float4*)(qkv + qbase + (size_t)row * (3 * EMB) + d4);
        uint32_t* dst = &Qs[row * SQ + d4];
        dst[0] = f2tf(v.x); dst[1] = f2tf(v.y); dst[2] = f2tf(v.z); dst[3] = f2tf(v.w);
    }

    float m_i[2] = {-INFINITY, -INFINITY}, l_i[2] = {0.0f, 0.0f};
    float oa[8][4];
    #pragma unroll
    for (int nt = 0; nt < 8; nt++)
        #pragma unroll
        for (int i = 0; i < 4; i++) oa[nt][i] = 0.0f;

    for (int kt = 0; kt < S_LEN / 64; ++kt) {
        #pragma unroll
        for (int i = 0; i < 4; i++) {
            int f = tid + 256 * i;
            int row = f >> 4, d4 = (f & 15) * 4;
            int key = (kt << 6) + row;

            // K: load group of 4, KIVI 2-bit fake quant, store tf32
            float4 kv = *(const float4*)(qkv + kbase + (size_t)key * (3 * EMB) + d4);
            float ma = fmaxf(fmaxf(fabsf(kv.x), fabsf(kv.y)),
                             fmaxf(fabsf(kv.z), fabsf(kv.w)));
            float scale = ma * (1.0f / 1.5f);
            float safe = (scale == 0.0f) ? 1.0f : scale;
            float cx = fminf(fmaxf(rintf(kv.x / safe + 1.5f), 0.0f), 3.0f);
            float cy = fminf(fmaxf(rintf(kv.y / safe + 1.5f), 0.0f), 3.0f);
            float cz = fminf(fmaxf(rintf(kv.z / safe + 1.5f), 0.0f), 3.0f);
            float cw = fminf(fmaxf(rintf(kv.w / safe + 1.5f), 0.0f), 3.0f);
            uint32_t* dk = &Ks[row * SQ + d4];
            dk[0] = f2tf((cx - 1.5f) * scale);
            dk[1] = f2tf((cy - 1.5f) * scale);
            dk[2] = f2tf((cz - 1.5f) * scale);
            dk[3] = f2tf((cw - 1.5f) * scale);

            // V: plain tf32
            float4 vv = *(const float4*)(qkv + vbase + (size_t)key * (3 * EMB) + d4);
            uint32_t* dv = &Vs[row * SV + d4];
            dv[0] = f2tf(vv.x); dv[1] = f2tf(vv.y);
            dv[2] = f2tf(vv.z); dv[3] = f2tf(vv.w);
        }
        if (tid < 64) Ms[tid] = mp[(kt << 6) + tid];
        __syncthreads();

        // ---- S = Q K^T : m=16, n=64 (8 nt), k=64 (8 ks) ----
        float sacc[8][4];
        #pragma unroll
        for (int nt = 0; nt < 8; nt++)
            #pragma unroll
            for (int i = 0; i < 4; i++) sacc[nt][i] = 0.0f;

        #pragma unroll
        for (int ks = 0; ks < 8; ++ks) {
            const int k0 = ks * 8;
            uint32_t af[4];
            af[0] = Qs[(m0 + g) * SQ + k0 + tg];
            af[1] = Qs[(m0 + g + 8) * SQ + k0 + tg];
            af[2] = Qs[(m0 + g) * SQ + k0 + tg + 4];
            af[3] = Qs[(m0 + g + 8) * SQ + k0 + tg + 4];
            #pragma unroll
            for (int nt = 0; nt < 8; ++nt) {
                uint32_t bf[2];
                bf[0] = Ks[(nt * 8 + g) * SQ + k0 + tg];
                bf[1] = Ks[(nt * 8 + g) * SQ + k0 + tg + 4];
                mma8(sacc[nt], af, bf);
            }
        }

        // ---- online softmax ----
        #pragma unroll
        for (int rr = 0; rr < 2; ++rr) {
            float mx = -INFINITY;
            #pragma unroll
            for (int nt = 0; nt < 8; nt++) {
                const int c0 = nt * 8 + 2 * tg;
                float s0 = (sacc[nt][rr * 2 + 0] + Ms[c0]) * 0.125f;
                float s1 = (sacc[nt][rr * 2 + 1] + Ms[c0 + 1]) * 0.125f;
                sacc[nt][rr * 2 + 0] = s0;
                sacc[nt][rr * 2 + 1] = s1;
                mx = fmaxf(mx, fmaxf(s0, s1));
            }
            mx = fmaxf(mx, __shfl_xor_sync(0xffffffffu, mx, 1));
            mx = fmaxf(mx, __shfl_xor_sync(0xffffffffu, mx, 2));
            const float mnew = fmaxf(m_i[rr], mx);
            const float alpha = __expf(m_i[rr] - mnew);
            float rs = 0.0f;
            const int row = m0 + g + rr * 8;
            #pragma unroll
            for (int nt = 0; nt < 8; nt++) {
                float p0 = __expf(sacc[nt][rr * 2 + 0] - mnew);
                float p1 = __expf(sacc[nt][rr * 2 + 1] - mnew);
                rs += p0 + p1;
                uint32_t* pp = &Ps[row * SQ + nt * 8 + 2 * tg];
                pp[0] = f2tf(p0); pp[1] = f2tf(p1);
            }
            rs += __shfl_xor_sync(0xffffffffu, rs, 1);
            rs += __shfl_xor_sync(0xffffffffu, rs, 2);
            l_i[rr] = l_i[rr] * alpha + rs;
            m_i[rr] = mnew;
            #pragma unroll
            for (int nt = 0; nt < 8; nt++) {
                oa[nt][rr * 2 + 0] *= alpha;
                oa[nt][rr * 2 + 1] *= alpha;
            }
        }
        __syncwarp();   // P rows are warp-private

        // ---- O += P V : k=64 keys (8 ks), n=64 dims (8 nt) ----
        #pragma unroll
        for (int ks = 0; ks < 8; ++ks) {
            const int k0 = ks * 8;
            uint32_t ap[4];
            ap[0] = Ps[(m0 + g) * SQ + k0 + tg];
            ap[1] = Ps[(m0 + g + 8) * SQ + k0 + tg];
            ap[2] = Ps[(m0 + g) * SQ + k0 + tg + 4];
            ap[3] = Ps[(m0 + g + 8) * SQ + k0 + tg + 4];
            #pragma unroll
            for (int nt = 0; nt < 8; ++nt) {
                uint32_t bf[2];
                bf[0] = Vs[(k0 + tg) * SV + nt * 8 + g];
                bf[1] = Vs[(k0 + tg + 4) * SV + nt * 8 + g];
                mma8(oa[nt], ap, bf);
            }
        }
        __syncthreads();   // before K/V/M tiles are overwritten
    }

    // ---- epilogue ----
    #pragma unroll
    for (int rr = 0; rr < 2; ++rr) {
        const float inv = 1.0f / l_i[rr];
        const int srow = qt * 128 + m0 + g + rr * 8;
        float* op = out + ((size_t)(b * S_LEN + srow)) * EMB + h * HD;
        #pragma unroll
        for (int nt = 0; nt < 8; nt++) {
            float2 v = make_float2(oa[nt][rr * 2 + 0] * inv, oa[nt][rr * 2 + 1] * inv);
            *(float2*)(op + nt * 8 + 2 * tg) = v;
        }
    }
}

// ---------------- launch ----------------
extern "C" void kernel_launch(void* const* d_in, const int* in_sizes, int n_in,
                              void* d_out, int out_size)
{
    const float* hidden = (const float*)d_in[0];
    const float* mask   = (const float*)d_in[1];
    const float* w_attn = (const float*)d_in[2];
    const float* b_attn = (const float*)d_in[3];
    const float* w_proj = (const float*)d_in[4];
    const float* b_proj = (const float*)d_in[5];
    float* out = (float*)d_out;

    float *qkv, *attn;
    cudaGetSymbolAddress((void**)&qkv,  g_qkv);
    cudaGetSymbolAddress((void**)&attn, g_attn);

    const int att_smem = ATT_FLOATS * (int)sizeof(float);
    cudaFuncSetAttribute(attn_tf32_fused,
                         cudaFuncAttributeMaxDynamicSharedMemorySize, att_smem);
    cudaFuncSetAttribute(gemm_tf32_mix,
                         cudaFuncAttributeMaxDynamicSharedMemorySize, GEMM_SMEM_BYTES);

    // 1) QKV GEMM: 3x precision only for K columns [1024,2048) (block-cols 8..15)
    dim3 g1(3 * EMB / 128, BATCH * S_LEN / 128);
    gemm_tf32_mix<<<g1, 256, GEMM_SMEM_BYTES>>>(hidden, w_attn, b_attn, qkv,
                                                BATCH * S_LEN, 3 * EMB, EMB, 8, 16);

    // 2) attention with fused KIVI quant
    attn_tf32_fused<<<BATCH * NH * (S_LEN / 128), 256, att_smem>>>(qkv, mask, attn);

    // 3) out projection: all 3x
    dim3 g2(EMB / 128, BATCH * S_LEN / 128);
    gemm_tf32_mix<<<g2, 256, GEMM_SMEM_BYTES>>>(attn, w_proj, b_proj, out,
                                                BATCH * S_LEN, EMB, EMB, 0, 8);
}

// round 6
// speedup vs baseline: 2.9389x; 1.3882x over previous
#include <cuda_runtime.h>
#include <cuda_bf16.h>
#include <math.h>
#include <stdint.h>

#define BATCH 4
#define S_LEN 1024
#define EMB   1024
#define NH    16
#define HD    64

// ---------------- scratch (no allocations allowed) ----------------
__device__ float    g_qkv [BATCH * S_LEN * 3 * EMB];   // [B,S,3E]
__device__ float    g_attn[BATCH * S_LEN * EMB];       // [B,S,E]
__device__ uint32_t g_wkh [EMB * (EMB / 2)];           // Wk hi, [n][kpair]
__device__ uint32_t g_wkl [EMB * (EMB / 2)];           // Wk lo, [n][kpair]

// ---------------- helpers ----------------
__device__ __forceinline__ uint32_t f2tf(float x) {
    uint32_t u;
    asm("cvt.rna.tf32.f32 %0, %1;" : "=r"(u) : "f"(x));
    return u;
}

__device__ __forceinline__ void mma8(float* d, const uint32_t* a, const uint32_t* b) {
    asm volatile(
        "mma.sync.aligned.m16n8k8.row.col.f32.tf32.tf32.f32 "
        "{%0,%1,%2,%3}, {%4,%5,%6,%7}, {%8,%9}, {%0,%1,%2,%3};"
        : "+f"(d[0]), "+f"(d[1]), "+f"(d[2]), "+f"(d[3])
        : "r"(a[0]), "r"(a[1]), "r"(a[2]), "r"(a[3]), "r"(b[0]), "r"(b[1]));
}

__device__ __forceinline__ void mma16bf(float* d, const uint32_t* a, const uint32_t* b) {
    asm volatile(
        "mma.sync.aligned.m16n8k16.row.col.f32.bf16.bf16.f32 "
        "{%0,%1,%2,%3}, {%4,%5,%6,%7}, {%8,%9}, {%0,%1,%2,%3};"
        : "+f"(d[0]), "+f"(d[1]), "+f"(d[2]), "+f"(d[3])
        : "r"(a[0]), "r"(a[1]), "r"(a[2]), "r"(a[3]), "r"(b[0]), "r"(b[1]));
}

__device__ __forceinline__ uint32_t pack_bf2(float x0, float x1) {
    __nv_bfloat162 p = __floats2bfloat162_rn(x0, x1);   // .x = x0 = low half
    return *(uint32_t*)&p;
}

__device__ __forceinline__ void split_bf(float x, float& h, float& l) {
    __nv_bfloat16 hb = __float2bfloat16_rn(x);
    h = __bfloat162float(hb);
    l = x - h;
}

// ---------------- prep: Wk (cols [1024,2048) of w_attn) -> packed bf16 ----------------
// Output [n][kp] uint32: pair {Wk[2kp][n] lo-half, Wk[2kp+1][n] hi-half}.
__global__ __launch_bounds__(256) void prep_wk(
    const float* __restrict__ w, uint32_t* __restrict__ wh, uint32_t* __restrict__ wl)
{
    int idx = blockIdx.x * 256 + threadIdx.x;     // 0 .. 1024*512-1
    int kp = idx & 511;
    int n  = idx >> 9;
    float x0 = w[(size_t)(2 * kp)     * (3 * EMB) + EMB + n];
    float x1 = w[(size_t)(2 * kp + 1) * (3 * EMB) + EMB + n];
    float h0, l0, h1, l1;
    split_bf(x0, h0, l0);
    split_bf(x1, h1, l1);
    wh[(size_t)n * 512 + kp] = pack_bf2(h0, h1);
    wl[(size_t)n * 512 + kp] = pack_bf2(l0, l1);
}

// ---------------- 1xTF32 GEMM: C = A*B + bias ----------------
// BM=BN=128, BK=16, 256 threads (8 warps 2x4), warp tile 64x32, 2 CTAs/SM.
// Block-cols >= nsplit get +gap added to their column base (QV fusion).
#define GA_S 20
#define GB_S 136
#define GA_BUF (128 * GA_S)
#define GB_BUF (16 * GB_S)

__global__ __launch_bounds__(256, 2) void gemm_1x(
    const float* __restrict__ A, const float* __restrict__ B,
    const float* __restrict__ bias, float* __restrict__ C,
    int lda, int ldb, int ldc, int K, int nsplit, int gap)
{
    __shared__ uint32_t Ah[2][GA_BUF];
    __shared__ uint32_t Bh[2][GB_BUF];

    const int tid = threadIdx.x;
    const int bx = blockIdx.x, by = blockIdx.y;
    const int bcol = bx * 128 + ((bx >= nsplit) ? gap : 0);
    const int lane = tid & 31, wid = tid >> 5;
    const int g = lane >> 2, tg = lane & 3;
    const int wm = (wid >> 2) * 64, wn = (wid & 3) * 32;

    const float* Ablk = A + (size_t)by * 128 * lda;
    const float* Bblk = B + bcol;

    float acc[4][4][4];
    #pragma unroll
    for (int mt = 0; mt < 4; mt++)
        #pragma unroll
        for (int nt = 0; nt < 4; nt++)
            #pragma unroll
            for (int i = 0; i < 4; i++) acc[mt][nt][i] = 0.0f;

    float4 pa[2], pb[2];
    #pragma unroll
    for (int i = 0; i < 2; i++) {
        int f = tid + 256 * i;
        pa[i] = *(const float4*)(Ablk + (size_t)(f >> 2) * lda + (f & 3) * 4);
        pb[i] = *(const float4*)(Bblk + (size_t)(f >> 5) * ldb + (f & 31) * 4);
    }
    #pragma unroll
    for (int i = 0; i < 2; i++) {
        int f = tid + 256 * i;
        uint32_t* da = &Ah[0][(f >> 2) * GA_S + (f & 3) * 4];
        da[0] = f2tf(pa[i].x); da[1] = f2tf(pa[i].y);
        da[2] = f2tf(pa[i].z); da[3] = f2tf(pa[i].w);
        uint32_t* db = &Bh[0][(f >> 5) * GB_S + (f & 31) * 4];
        db[0] = f2tf(pb[i].x); db[1] = f2tf(pb[i].y);
        db[2] = f2tf(pb[i].z); db[3] = f2tf(pb[i].w);
    }
    __syncthreads();

    const int ntiles = K >> 4;
    int buf = 0;
    for (int t = 0; t < ntiles; ++t) {
        if (t + 1 < ntiles) {
            #pragma unroll
            for (int i = 0; i < 2; i++) {
                int f = tid + 256 * i;
                pa[i] = *(const float4*)(Ablk + (size_t)(f >> 2) * lda + (t + 1) * 16 + (f & 3) * 4);
                pb[i] = *(const float4*)(Bblk + (size_t)((t + 1) * 16 + (f >> 5)) * ldb + (f & 31) * 4);
            }
        }

        #pragma unroll
        for (int ks = 0; ks < 2; ++ks) {
            const int k0 = ks * 8;
            uint32_t af[4][4], bf[4][2];
            #pragma unroll
            for (int mt = 0; mt < 4; mt++) {
                const int m0 = wm + mt * 16;
                af[mt][0] = Ah[buf][(m0 + g) * GA_S + k0 + tg];
                af[mt][1] = Ah[buf][(m0 + g + 8) * GA_S + k0 + tg];
                af[mt][2] = Ah[buf][(m0 + g) * GA_S + k0 + tg + 4];
                af[mt][3] = Ah[buf][(m0 + g + 8) * GA_S + k0 + tg + 4];
            }
            #pragma unroll
            for (int nt = 0; nt < 4; nt++) {
                const int n0 = wn + nt * 8;
                bf[nt][0] = Bh[buf][(k0 + tg) * GB_S + n0 + g];
                bf[nt][1] = Bh[buf][(k0 + tg + 4) * GB_S + n0 + g];
            }
            #pragma unroll
            for (int mt = 0; mt < 4; mt++)
                #pragma unroll
                for (int nt = 0; nt < 4; nt++)
                    mma8(acc[mt][nt], af[mt], bf[nt]);
        }

        if (t + 1 < ntiles) {
            const int nb = buf ^ 1;
            #pragma unroll
            for (int i = 0; i < 2; i++) {
                int f = tid + 256 * i;
                uint32_t* da = &Ah[nb][(f >> 2) * GA_S + (f & 3) * 4];
                da[0] = f2tf(pa[i].x); da[1] = f2tf(pa[i].y);
                da[2] = f2tf(pa[i].z); da[3] = f2tf(pa[i].w);
                uint32_t* db = &Bh[nb][(f >> 5) * GB_S + (f & 31) * 4];
                db[0] = f2tf(pb[i].x); db[1] = f2tf(pb[i].y);
                db[2] = f2tf(pb[i].z); db[3] = f2tf(pb[i].w);
            }
            __syncthreads();
            buf = nb;
        }
    }

    #pragma unroll
    for (int mt = 0; mt < 4; mt++) {
        #pragma unroll
        for (int nt = 0; nt < 4; nt++) {
            const int col = bcol + wn + nt * 8 + 2 * tg;
            const float bv0 = bias[col], bv1 = bias[col + 1];
            const int row0 = by * 128 + wm + mt * 16 + g;
            float2 v0 = make_float2(acc[mt][nt][0] + bv0, acc[mt][nt][1] + bv1);
            float2 v1 = make_float2(acc[mt][nt][2] + bv0, acc[mt][nt][3] + bv1);
            *(float2*)(C + (size_t)row0 * ldc + col)       = v0;
            *(float2*)(C + (size_t)(row0 + 8) * ldc + col) = v1;
        }
    }
}

// ---------------- bf16x3 GEMM for the K section ----------------
// C[:,1024:2048) of qkv = hidden @ Wk + bias, with fp32 emulated via
// bf16 hi/lo split: ah*bh + ah*bl + al*bh. BK=16 (one k16 mma per tile).
// A tiles [m][kp] stride 12, B tiles [n][kp] stride 12 (both conflict-free).
#define G3_S 12
#define G3_BUF (128 * G3_S)
#define G3_SMEM_BYTES (8 * G3_BUF * 4)   // Ah,Al,Bh,Bl x 2 buffers

__global__ __launch_bounds__(256, 2) void gemm_bf16k(
    const float* __restrict__ A, const uint32_t* __restrict__ Bhg,
    const uint32_t* __restrict__ Blg, const float* __restrict__ bias,
    float* __restrict__ C, int lda, int ldc, int K)
{
    extern __shared__ uint32_t s3[];
    uint32_t* Ah = s3;                    // [2][G3_BUF]
    uint32_t* Al = Ah + 2 * G3_BUF;
    uint32_t* Bh = Al + 2 * G3_BUF;
    uint32_t* Bl = Bh + 2 * G3_BUF;

    const int tid = threadIdx.x;
    const int bx = blockIdx.x, by = blockIdx.y;
    const int lane = tid & 31, wid = tid >> 5;
    const int g = lane >> 2, tg = lane & 3;
    const int wm = (wid >> 2) * 64, wn = (wid & 3) * 32;

    const int arow = tid >> 1, akb = (tid & 1) * 8;         // 8 k per thread
    const int brow = tid >> 1, bkp = (tid & 1) * 4;         // 4 kp per thread
    const float*    Ap  = A + (size_t)(by * 128 + arow) * lda + akb;
    const uint32_t* Bhp = Bhg + (size_t)(bx * 128 + brow) * 512 + bkp;
    const uint32_t* Blp = Blg + (size_t)(bx * 128 + brow) * 512 + bkp;

    float acc[4][4][4];
    #pragma unroll
    for (int mt = 0; mt < 4; mt++)
        #pragma unroll
        for (int nt = 0; nt < 4; nt++)
            #pragma unroll
            for (int i = 0; i < 4; i++) acc[mt][nt][i] = 0.0f;

    float4 pa0, pa1;
    uint4  pbh, pbl;
    pa0 = *(const float4*)(Ap);
    pa1 = *(const float4*)(Ap + 4);
    pbh = *(const uint4*)(Bhp);
    pbl = *(const uint4*)(Blp);

    const int ntiles = K >> 4;
    int buf = 0;
    // store tile 0
    {
        float hv[8], lv[8];
        float src[8] = {pa0.x, pa0.y, pa0.z, pa0.w, pa1.x, pa1.y, pa1.z, pa1.w};
        #pragma unroll
        for (int j = 0; j < 8; j++) split_bf(src[j], hv[j], lv[j]);
        uint4 uh = make_uint4(pack_bf2(hv[0], hv[1]), pack_bf2(hv[2], hv[3]),
                              pack_bf2(hv[4], hv[5]), pack_bf2(hv[6], hv[7]));
        uint4 ul = make_uint4(pack_bf2(lv[0], lv[1]), pack_bf2(lv[2], lv[3]),
                              pack_bf2(lv[4], lv[5]), pack_bf2(lv[6], lv[7]));
        *(uint4*)&Ah[arow * G3_S + akb / 2] = uh;
        *(uint4*)&Al[arow * G3_S + akb / 2] = ul;
        *(uint4*)&Bh[brow * G3_S + bkp] = pbh;
        *(uint4*)&Bl[brow * G3_S + bkp] = pbl;
    }
    __syncthreads();

    for (int t = 0; t < ntiles; ++t) {
        if (t + 1 < ntiles) {
            pa0 = *(const float4*)(Ap + (t + 1) * 16);
            pa1 = *(const float4*)(Ap + (t + 1) * 16 + 4);
            pbh = *(const uint4*)(Bhp + (t + 1) * 8);
            pbl = *(const uint4*)(Blp + (t + 1) * 8);
        }

        const uint32_t* ah = Ah + buf * G3_BUF;
        const uint32_t* al = Al + buf * G3_BUF;
        const uint32_t* bh = Bh + buf * G3_BUF;
        const uint32_t* bl = Bl + buf * G3_BUF;

        uint32_t afh[4][4], afl[4][4], bfh[4][2], bfl[4][2];
        #pragma unroll
        for (int mt = 0; mt < 4; mt++) {
            const int m0 = wm + mt * 16;
            afh[mt][0] = ah[(m0 + g) * G3_S + tg];
            afh[mt][1] = ah[(m0 + g + 8) * G3_S + tg];
            afh[mt][2] = ah[(m0 + g) * G3_S + tg + 4];
            afh[mt][3] = ah[(m0 + g + 8) * G3_S + tg + 4];
            afl[mt][0] = al[(m0 + g) * G3_S + tg];
            afl[mt][1] = al[(m0 + g + 8) * G3_S + tg];
            afl[mt][2] = al[(m0 + g) * G3_S + tg + 4];
            afl[mt][3] = al[(m0 + g + 8) * G3_S + tg + 4];
        }
        #pragma unroll
        for (int nt = 0; nt < 4; nt++) {
            const int n0 = wn + nt * 8;
            bfh[nt][0] = bh[(n0 + g) * G3_S + tg];
            bfh[nt][1] = bh[(n0 + g) * G3_S + tg + 4];
            bfl[nt][0] = bl[(n0 + g) * G3_S + tg];
            bfl[nt][1] = bl[(n0 + g) * G3_S + tg + 4];
        }
        #pragma unroll
        for (int mt = 0; mt < 4; mt++)
            #pragma unroll
            for (int nt = 0; nt < 4; nt++) {
                mma16bf(acc[mt][nt], afh[mt], bfh[nt]);
                mma16bf(acc[mt][nt], afh[mt], bfl[nt]);
                mma16bf(acc[mt][nt], afl[mt], bfh[nt]);
            }

        if (t + 1 < ntiles) {
            const int nb = buf ^ 1;
            float hv[8], lv[8];
            float src[8] = {pa0.x, pa0.y, pa0.z, pa0.w, pa1.x, pa1.y, pa1.z, pa1.w};
            #pragma unroll
            for (int j = 0; j < 8; j++) split_bf(src[j], hv[j], lv[j]);
            uint4 uh = make_uint4(pack_bf2(hv[0], hv[1]), pack_bf2(hv[2], hv[3]),
                                  pack_bf2(hv[4], hv[5]), pack_bf2(hv[6], hv[7]));
            uint4 ul = make_uint4(pack_bf2(lv[0], lv[1]), pack_bf2(lv[2], lv[3]),
                                  pack_bf2(lv[4], lv[5]), pack_bf2(lv[6], lv[7]));
            __syncthreads();
            *(uint4*)&Ah[nb * G3_BUF + arow * G3_S + akb / 2] = uh;
            *(uint4*)&Al[nb * G3_BUF + arow * G3_S + akb / 2] = ul;
            *(uint4*)&Bh[nb * G3_BUF + brow * G3_S + bkp] = pbh;
            *(uint4*)&Bl[nb * G3_BUF + brow * G3_S + bkp] = pbl;
            __syncthreads();
            buf = nb;
        }
    }

    #pragma unroll
    for (int mt = 0; mt < 4; mt++) {
        #pragma unroll
        for (int nt = 0; nt < 4; nt++) {
            const int coll = bx * 128 + wn + nt * 8 + 2 * tg;
            const float bv0 = bias[coll], bv1 = bias[coll + 1];
            const int row0 = by * 128 + wm + mt * 16 + g;
            const int col = EMB + coll;   // K section lives at cols [1024,2048)
            float2 v0 = make_float2(acc[mt][nt][0] + bv0, acc[mt][nt][1] + bv1);
            float2 v1 = make_float2(acc[mt][nt][2] + bv0, acc[mt][nt][3] + bv1);
            *(float2*)(C + (size_t)row0 * ldc + col)       = v0;
            *(float2*)(C + (size_t)(row0 + 8) * ldc + col) = v1;
        }
    }
}

// ---------------- Flash attention (1xTF32) with fused KIVI quant ----------------
#define SQ 68
#define SV 72
#define ATT_FLOATS (128 * SQ + 64 * SQ + 128 * SQ + 64 * SV + 64)

__global__ __launch_bounds__(256, 2) void attn_tf32_fused(
    const float* __restrict__ qkv, const float* __restrict__ mask,
    float* __restrict__ out)
{
    extern __shared__ uint32_t smu[];
    uint32_t* Qs = smu;
    uint32_t* Ks = Qs + 128 * SQ;
    uint32_t* Ps = Ks + 64 * SQ;
    uint32_t* Vs = Ps + 128 * SQ;
    float*    Ms = (float*)(Vs + 64 * SV);

    const int tid = threadIdx.x, lane = tid & 31, wid = tid >> 5;
    const int g = lane >> 2, tg = lane & 3;
    const int m0 = wid * 16;

    const int bid = blockIdx.x;
    const int qt = bid & 7;
    const int h  = (bid >> 3) & 15;
    const int b  = bid >> 7;

    const size_t qbase = ((size_t)(b * S_LEN) + qt * 128) * (3 * EMB) + h * HD;
    const size_t kbase = ((size_t)(b * S_LEN)) * (3 * EMB) + EMB + h * HD;
    const size_t vbase = ((size_t)(b * S_LEN)) * (3 * EMB) + 2 * EMB + h * HD;
    const float* mp = mask + b * S_LEN;

    #pragma unroll
    for (int i = 0; i < 8; i++) {
        int f = tid + 256 * i;
        int row = f >> 4, d4 = (f & 15) * 4;
        float4 v = *(const float4*)(qkv + qbase + (size_t)row * (3 * EMB) + d4);
        uint32_t* dst = &Qs[row * SQ + d4];
        dst[0] = f2tf(v.x); dst[1] = f2tf(v.y); dst[2] = f2tf(v.z); dst[3] = f2tf(v.w);
    }

    float m_i[2] = {-INFINITY, -INFINITY}, l_i[2] = {0.0f, 0.0f};
    float oa[8][4];
    #pragma unroll
    for (int nt = 0; nt < 8; nt++)
        #pragma unroll
        for (int i = 0; i < 4; i++) oa[nt][i] = 0.0f;

    for (int kt = 0; kt < S_LEN / 64; ++kt) {
        #pragma unroll
        for (int i = 0; i < 4; i++) {
            int f = tid + 256 * i;
            int row = f >> 4, d4 = (f & 15) * 4;
            int key = (kt << 6) + row;

            float4 kv = *(const float4*)(qkv + kbase + (size_t)key * (3 * EMB) + d4);
            float ma = fmaxf(fmaxf(fabsf(kv.x), fabsf(kv.y)),
                             fmaxf(fabsf(kv.z), fabsf(kv.w)));
            float scale = ma * (1.0f / 1.5f);
            float safe = (scale == 0.0f) ? 1.0f : scale;
            float cx = fminf(fmaxf(rintf(kv.x / safe + 1.5f), 0.0f), 3.0f);
            float cy = fminf(fmaxf(rintf(kv.y / safe + 1.5f), 0.0f), 3.0f);
            float cz = fminf(fmaxf(rintf(kv.z / safe + 1.5f), 0.0f), 3.0f);
            float cw = fminf(fmaxf(rintf(kv.w / safe + 1.5f), 0.0f), 3.0f);
            uint32_t* dk = &Ks[row * SQ + d4];
            dk[0] = f2tf((cx - 1.5f) * scale);
            dk[1] = f2tf((cy - 1.5f) * scale);
            dk[2] = f2tf((cz - 1.5f) * scale);
            dk[3] = f2tf((cw - 1.5f) * scale);

            float4 vv = *(const float4*)(qkv + vbase + (size_t)key * (3 * EMB) + d4);
            uint32_t* dv = &Vs[row * SV + d4];
            dv[0] = f2tf(vv.x); dv[1] = f2tf(vv.y);
            dv[2] = f2tf(vv.z); dv[3] = f2tf(vv.w);
        }
        if (tid < 64) Ms[tid] = mp[(kt << 6) + tid];
        __syncthreads();

        float sacc[8][4];
        #pragma unroll
        for (int nt = 0; nt < 8; nt++)
            #pragma unroll
            for (int i = 0; i < 4; i++) sacc[nt][i] = 0.0f;

        #pragma unroll
        for (int ks = 0; ks < 8; ++ks) {
            const int k0 = ks * 8;
            uint32_t af[4];
            af[0] = Qs[(m0 + g) * SQ + k0 + tg];
            af[1] = Qs[(m0 + g + 8) * SQ + k0 + tg];
            af[2] = Qs[(m0 + g) * SQ + k0 + tg + 4];
            af[3] = Qs[(m0 + g + 8) * SQ + k0 + tg + 4];
            #pragma unroll
            for (int nt = 0; nt < 8; ++nt) {
                uint32_t bf[2];
                bf[0] = Ks[(nt * 8 + g) * SQ + k0 + tg];
                bf[1] = Ks[(nt * 8 + g) * SQ + k0 + tg + 4];
                mma8(sacc[nt], af, bf);
            }
        }

        #pragma unroll
        for (int rr = 0; rr < 2; ++rr) {
            float mx = -INFINITY;
            #pragma unroll
            for (int nt = 0; nt < 8; nt++) {
                const int c0 = nt * 8 + 2 * tg;
                float s0 = (sacc[nt][rr * 2 + 0] + Ms[c0]) * 0.125f;
                float s1 = (sacc[nt][rr * 2 + 1] + Ms[c0 + 1]) * 0.125f;
                sacc[nt][rr * 2 + 0] = s0;
                sacc[nt][rr * 2 + 1] = s1;
                mx = fmaxf(mx, fmaxf(s0, s1));
            }
            mx = fmaxf(mx, __shfl_xor_sync(0xffffffffu, mx, 1));
            mx = fmaxf(mx, __shfl_xor_sync(0xffffffffu, mx, 2));
            const float mnew = fmaxf(m_i[rr], mx);
            const float alpha = __expf(m_i[rr] - mnew);
            float rs = 0.0f;
            const int row = m0 + g + rr * 8;
            #pragma unroll
            for (int nt = 0; nt < 8; nt++) {
                float p0 = __expf(sacc[nt][rr * 2 + 0] - mnew);
                float p1 = __expf(sacc[nt][rr * 2 + 1] - mnew);
                rs += p0 + p1;
                uint32_t* pp = &Ps[row * SQ + nt * 8 + 2 * tg];
                pp[0] = f2tf(p0); pp[1] = f2tf(p1);
            }
            rs += __shfl_xor_sync(0xffffffffu, rs, 1);
            rs += __shfl_xor_sync(0xffffffffu, rs, 2);
            l_i[rr] = l_i[rr] * alpha + rs;
            m_i[rr] = mnew;
            #pragma unroll
            for (int nt = 0; nt < 8; nt++) {
                oa[nt][rr * 2 + 0] *= alpha;
                oa[nt][rr * 2 + 1] *= alpha;
            }
        }
        __syncwarp();

        #pragma unroll
        for (int ks = 0; ks < 8; ++ks) {
            const int k0 = ks * 8;
            uint32_t ap[4];
            ap[0] = Ps[(m0 + g) * SQ + k0 + tg];
            ap[1] = Ps[(m0 + g + 8) * SQ + k0 + tg];
            ap[2] = Ps[(m0 + g) * SQ + k0 + tg + 4];
            ap[3] = Ps[(m0 + g + 8) * SQ + k0 + tg + 4];
            #pragma unroll
            for (int nt = 0; nt < 8; ++nt) {
                uint32_t bf[2];
                bf[0] = Vs[(k0 + tg) * SV + nt * 8 + g];
                bf[1] = Vs[(k0 + tg + 4) * SV + nt * 8 + g];
                mma8(oa[nt], ap, bf);
            }
        }
        __syncthreads();
    }

    #pragma unroll
    for (int rr = 0; rr < 2; ++rr) {
        const float inv = 1.0f / l_i[rr];
        const int srow = qt * 128 + m0 + g + rr * 8;
        float* op = out + ((size_t)(b * S_LEN + srow)) * EMB + h * HD;
        #pragma unroll
        for (int nt = 0; nt < 8; nt++) {
            float2 v = make_float2(oa[nt][rr * 2 + 0] * inv, oa[nt][rr * 2 + 1] * inv);
            *(float2*)(op + nt * 8 + 2 * tg) = v;
        }
    }
}

// ---------------- launch ----------------
extern "C" void kernel_launch(void* const* d_in, const int* in_sizes, int n_in,
                              void* d_out, int out_size)
{
    const float* hidden = (const float*)d_in[0];
    const float* mask   = (const float*)d_in[1];
    const float* w_attn = (const float*)d_in[2];
    const float* b_attn = (const float*)d_in[3];
    const float* w_proj = (const float*)d_in[4];
    const float* b_proj = (const float*)d_in[5];
    float* out = (float*)d_out;

    float *qkv, *attn;
    uint32_t *wkh, *wkl;
    cudaGetSymbolAddress((void**)&qkv,  g_qkv);
    cudaGetSymbolAddress((void**)&attn, g_attn);
    cudaGetSymbolAddress((void**)&wkh,  g_wkh);
    cudaGetSymbolAddress((void**)&wkl,  g_wkl);

    const int att_smem = ATT_FLOATS * (int)sizeof(float);
    cudaFuncSetAttribute(attn_tf32_fused,
                         cudaFuncAttributeMaxDynamicSharedMemorySize, att_smem);
    cudaFuncSetAttribute(gemm_bf16k,
                         cudaFuncAttributeMaxDynamicSharedMemorySize, G3_SMEM_BYTES);

    // 0) prep packed bf16 Wk (transpose + hi/lo split)
    prep_wk<<<EMB * (EMB / 2) / 256, 256>>>(w_attn, wkh, wkl);

    // 1) Q and V sections, 1xTF32 (bx>=8 maps to cols +1024 -> V at [2048,3072))
    dim3 gqv(16, BATCH * S_LEN / 128);
    gemm_1x<<<gqv, 256>>>(hidden, w_attn, b_attn, qkv,
                          EMB, 3 * EMB, 3 * EMB, EMB, 8, 1024);

    // 2) K section, bf16x3
    dim3 gk(EMB / 128, BATCH * S_LEN / 128);
    gemm_bf16k<<<gk, 256, G3_SMEM_BYTES>>>(hidden, wkh, wkl, b_attn + EMB,
                                           qkv, EMB, 3 * EMB, EMB);

    // 3) attention with fused KIVI quant
    attn_tf32_fused<<<BATCH * NH * (S_LEN / 128), 256, att_smem>>>(qkv, mask, attn);

    // 4) out projection, 1xTF32
    dim3 gp(EMB / 128, BATCH * S_LEN / 128);
    gemm_1x<<<gp, 256>>>(attn, w_proj, b_proj, out,
                         EMB, EMB, EMB, EMB, 8, 0);
}

// round 8
// speedup vs baseline: 3.2104x; 1.0924x over previous
#include <cuda_runtime.h>
#include <cuda_bf16.h>
#include <cuda_fp16.h>
#include <math.h>
#include <stdint.h>

#define BATCH 4
#define S_LEN 1024
#define EMB   1024
#define NH    16
#define HD    64

// ---------------- scratch (no allocations allowed) ----------------
__device__ float    g_qkv [BATCH * S_LEN * 3 * EMB];   // [B,S,3E]
__device__ float    g_attn[BATCH * S_LEN * EMB];       // [B,S,E]
__device__ uint32_t g_wkh [EMB * (EMB / 2)];           // Wk bf16 hi, [n][kpair]
__device__ uint32_t g_wkl [EMB * (EMB / 2)];           // Wk bf16 lo, [n][kpair]
__device__ uint32_t g_wqv [2048 * (EMB / 2)];          // Wq|Wv fp16,  [n][kpair]
__device__ uint32_t g_wp  [EMB * (EMB / 2)];           // Wproj fp16,  [n][kpair]

// ---------------- helpers ----------------
__device__ __forceinline__ uint32_t f2tf(float x) {
    uint32_t u;
    asm("cvt.rna.tf32.f32 %0, %1;" : "=r"(u) : "f"(x));
    return u;
}

__device__ __forceinline__ void mma8(float* d, const uint32_t* a, const uint32_t* b) {
    asm volatile(
        "mma.sync.aligned.m16n8k8.row.col.f32.tf32.tf32.f32 "
        "{%0,%1,%2,%3}, {%4,%5,%6,%7}, {%8,%9}, {%0,%1,%2,%3};"
        : "+f"(d[0]), "+f"(d[1]), "+f"(d[2]), "+f"(d[3])
        : "r"(a[0]), "r"(a[1]), "r"(a[2]), "r"(a[3]), "r"(b[0]), "r"(b[1]));
}

__device__ __forceinline__ void mma16bf(float* d, const uint32_t* a, const uint32_t* b) {
    asm volatile(
        "mma.sync.aligned.m16n8k16.row.col.f32.bf16.bf16.f32 "
        "{%0,%1,%2,%3}, {%4,%5,%6,%7}, {%8,%9}, {%0,%1,%2,%3};"
        : "+f"(d[0]), "+f"(d[1]), "+f"(d[2]), "+f"(d[3])
        : "r"(a[0]), "r"(a[1]), "r"(a[2]), "r"(a[3]), "r"(b[0]), "r"(b[1]));
}

__device__ __forceinline__ void mma16f(float* d, const uint32_t* a, const uint32_t* b) {
    asm volatile(
        "mma.sync.aligned.m16n8k16.row.col.f32.f16.f16.f32 "
        "{%0,%1,%2,%3}, {%4,%5,%6,%7}, {%8,%9}, {%0,%1,%2,%3};"
        : "+f"(d[0]), "+f"(d[1]), "+f"(d[2]), "+f"(d[3])
        : "r"(a[0]), "r"(a[1]), "r"(a[2]), "r"(a[3]), "r"(b[0]), "r"(b[1]));
}

__device__ __forceinline__ uint32_t pack_bf2(float x0, float x1) {
    __nv_bfloat162 p = __floats2bfloat162_rn(x0, x1);   // .x = low half
    return *(uint32_t*)&p;
}

__device__ __forceinline__ uint32_t pack_h2(float x0, float x1) {
    __half2 p = __floats2half2_rn(x0, x1);              // .x = low half
    return *(uint32_t*)&p;
}

__device__ __forceinline__ void split_bf(float x, float& h, float& l) {
    __nv_bfloat16 hb = __float2bfloat16_rn(x);
    h = __bfloat162float(hb);
    l = x - h;
}

// ---------------- prep: Wk (cols [1024,2048)) -> packed bf16 hi/lo ----------------
__global__ __launch_bounds__(256) void prep_wk(
    const float* __restrict__ w, uint32_t* __restrict__ wh, uint32_t* __restrict__ wl)
{
    int idx = blockIdx.x * 256 + threadIdx.x;
    int n  = idx & 1023;
    int kp = idx >> 10;
    float x0 = w[(size_t)(2 * kp)     * (3 * EMB) + EMB + n];
    float x1 = w[(size_t)(2 * kp + 1) * (3 * EMB) + EMB + n];
    float h0, l0, h1, l1;
    split_bf(x0, h0, l0);
    split_bf(x1, h1, l1);
    wh[(size_t)n * 512 + kp] = pack_bf2(h0, h1);
    wl[(size_t)n * 512 + kp] = pack_bf2(l0, l1);
}

// ---------------- prep: pack a weight section to fp16 [n][kpair] ----------------
// n = idx & nmask, kp = idx >> nshift (nshift = log2(nmask+1)).
// Output row n maps to source col (n + (n>=nswitch)*1024). ldw = source row stride.
__global__ __launch_bounds__(256) void prep_pack_f16(
    const float* __restrict__ w, int ldw, int nmask, int nshift, int nswitch,
    uint32_t* __restrict__ out)
{
    int idx = blockIdx.x * 256 + threadIdx.x;
    int n  = idx & nmask;
    int kp = idx >> nshift;
    int col = n + ((n >= nswitch) ? 1024 : 0);
    float x0 = w[(size_t)(2 * kp)     * ldw + col];
    float x1 = w[(size_t)(2 * kp + 1) * ldw + col];
    out[(size_t)n * 512 + kp] = pack_h2(x0, x1);
}

// ---------------- fp16 GEMM: C = A*B + bias, B pre-packed [n][kp] ----------------
// BM=BN=128, BK=16, 256 threads (8 warps 2x4), warp tile 64x32, 2 CTAs/SM.
// A tiles [m][kp] stride 12, B tiles [n][kp] stride 12 (both conflict-free).
#define GF_S 12
#define GF_BUF (128 * GF_S)

__global__ __launch_bounds__(256, 2) void gemm_f16(
    const float* __restrict__ A, const uint32_t* __restrict__ Bp,
    const float* __restrict__ bias, float* __restrict__ C,
    int lda, int ldc, int K, int nsplit, int gap)
{
    __shared__ uint32_t As[2][GF_BUF];
    __shared__ uint32_t Bs[2][GF_BUF];

    const int tid = threadIdx.x;
    const int bx = blockIdx.x, by = blockIdx.y;
    const int bcol = bx * 128 + ((bx >= nsplit) ? gap : 0);
    const int lane = tid & 31, wid = tid >> 5;
    const int g = lane >> 2, tg = lane & 3;
    const int wm = (wid >> 2) * 64, wn = (wid & 3) * 32;

    const int arow = tid >> 1, akb = (tid & 1) * 8;     // 8 k floats per thread
    const int brow = tid >> 1, bkp = (tid & 1) * 4;     // 4 kp per thread
    const float*    Ap  = A  + (size_t)(by * 128 + arow) * lda + akb;
    const uint32_t* Bpp = Bp + (size_t)(bx * 128 + brow) * 512 + bkp;

    float acc[4][4][4];
    #pragma unroll
    for (int mt = 0; mt < 4; mt++)
        #pragma unroll
        for (int nt = 0; nt < 4; nt++)
            #pragma unroll
            for (int i = 0; i < 4; i++) acc[mt][nt][i] = 0.0f;

    float4 pa0 = *(const float4*)(Ap);
    float4 pa1 = *(const float4*)(Ap + 4);
    uint4  pb  = *(const uint4*)(Bpp);

    const int ntiles = K >> 4;
    int buf = 0;
    {
        uint4 ua = make_uint4(pack_h2(pa0.x, pa0.y), pack_h2(pa0.z, pa0.w),
                              pack_h2(pa1.x, pa1.y), pack_h2(pa1.z, pa1.w));
        *(uint4*)&As[0][arow * GF_S + akb / 2] = ua;
        *(uint4*)&Bs[0][brow * GF_S + bkp] = pb;
    }
    __syncthreads();

    for (int t = 0; t < ntiles; ++t) {
        if (t + 1 < ntiles) {
            pa0 = *(const float4*)(Ap + (t + 1) * 16);
            pa1 = *(const float4*)(Ap + (t + 1) * 16 + 4);
            pb  = *(const uint4*)(Bpp + (t + 1) * 8);
        }

        const uint32_t* as = As[buf];
        const uint32_t* bs = Bs[buf];

        uint32_t af[4][4], bf[4][2];
        #pragma unroll
        for (int mt = 0; mt < 4; mt++) {
            const int m0 = wm + mt * 16;
            af[mt][0] = as[(m0 + g) * GF_S + tg];
            af[mt][1] = as[(m0 + g + 8) * GF_S + tg];
            af[mt][2] = as[(m0 + g) * GF_S + tg + 4];
            af[mt][3] = as[(m0 + g + 8) * GF_S + tg + 4];
        }
        #pragma unroll
        for (int nt = 0; nt < 4; nt++) {
            const int n0 = wn + nt * 8;
            bf[nt][0] = bs[(n0 + g) * GF_S + tg];
            bf[nt][1] = bs[(n0 + g) * GF_S + tg + 4];
        }
        #pragma unroll
        for (int mt = 0; mt < 4; mt++)
            #pragma unroll
            for (int nt = 0; nt < 4; nt++)
                mma16f(acc[mt][nt], af[mt], bf[nt]);

        if (t + 1 < ntiles) {
            const int nb = buf ^ 1;
            uint4 ua = make_uint4(pack_h2(pa0.x, pa0.y), pack_h2(pa0.z, pa0.w),
                                  pack_h2(pa1.x, pa1.y), pack_h2(pa1.z, pa1.w));
            __syncthreads();
            *(uint4*)&As[nb][arow * GF_S + akb / 2] = ua;
            *(uint4*)&Bs[nb][brow * GF_S + bkp] = pb;
            __syncthreads();
            buf = nb;
        }
    }

    #pragma unroll
    for (int mt = 0; mt < 4; mt++) {
        #pragma unroll
        for (int nt = 0; nt < 4; nt++) {
            const int col = bcol + wn + nt * 8 + 2 * tg;
            const float bv0 = bias[col], bv1 = bias[col + 1];
            const int row0 = by * 128 + wm + mt * 16 + g;
            float2 v0 = make_float2(acc[mt][nt][0] + bv0, acc[mt][nt][1] + bv1);
            float2 v1 = make_float2(acc[mt][nt][2] + bv0, acc[mt][nt][3] + bv1);
            *(float2*)(C + (size_t)row0 * ldc + col)       = v0;
            *(float2*)(C + (size_t)(row0 + 8) * ldc + col) = v1;
        }
    }
}

// ---------------- bf16x3 GEMM for the K section ----------------
#define G3_S 12
#define G3_BUF (128 * G3_S)
#define G3_SMEM_BYTES (8 * G3_BUF * 4)

__global__ __launch_bounds__(256, 2) void gemm_bf16k(
    const float* __restrict__ A, const uint32_t* __restrict__ Bhg,
    const uint32_t* __restrict__ Blg, const float* __restrict__ bias,
    float* __restrict__ C, int lda, int ldc, int K)
{
    extern __shared__ uint32_t s3[];
    uint32_t* Ah = s3;
    uint32_t* Al = Ah + 2 * G3_BUF;
    uint32_t* Bh = Al + 2 * G3_BUF;
    uint32_t* Bl = Bh + 2 * G3_BUF;

    const int tid = threadIdx.x;
    const int bx = blockIdx.x, by = blockIdx.y;
    const int lane = tid & 31, wid = tid >> 5;
    const int g = lane >> 2, tg = lane & 3;
    const int wm = (wid >> 2) * 64, wn = (wid & 3) * 32;

    const int arow = tid >> 1, akb = (tid & 1) * 8;
    const int brow = tid >> 1, bkp = (tid & 1) * 4;
    const float*    Ap  = A + (size_t)(by * 128 + arow) * lda + akb;
    const uint32_t* Bhp = Bhg + (size_t)(bx * 128 + brow) * 512 + bkp;
    const uint32_t* Blp = Blg + (size_t)(bx * 128 + brow) * 512 + bkp;

    float acc[4][4][4];
    #pragma unroll
    for (int mt = 0; mt < 4; mt++)
        #pragma unroll
        for (int nt = 0; nt < 4; nt++)
            #pragma unroll
            for (int i = 0; i < 4; i++) acc[mt][nt][i] = 0.0f;

    float4 pa0 = *(const float4*)(Ap);
    float4 pa1 = *(const float4*)(Ap + 4);
    uint4  pbh = *(const uint4*)(Bhp);
    uint4  pbl = *(const uint4*)(Blp);

    const int ntiles = K >> 4;
    int buf = 0;
    {
        float hv[8], lv[8];
        float src[8] = {pa0.x, pa0.y, pa0.z, pa0.w, pa1.x, pa1.y, pa1.z, pa1.w};
        #pragma unroll
        for (int j = 0; j < 8; j++) split_bf(src[j], hv[j], lv[j]);
        uint4 uh = make_uint4(pack_bf2(hv[0], hv[1]), pack_bf2(hv[2], hv[3]),
                              pack_bf2(hv[4], hv[5]), pack_bf2(hv[6], hv[7]));
        uint4 ul = make_uint4(pack_bf2(lv[0], lv[1]), pack_bf2(lv[2], lv[3]),
                              pack_bf2(lv[4], lv[5]), pack_bf2(lv[6], lv[7]));
        *(uint4*)&Ah[arow * G3_S + akb / 2] = uh;
        *(uint4*)&Al[arow * G3_S + akb / 2] = ul;
        *(uint4*)&Bh[brow * G3_S + bkp] = pbh;
        *(uint4*)&Bl[brow * G3_S + bkp] = pbl;
    }
    __syncthreads();

    for (int t = 0; t < ntiles; ++t) {
        if (t + 1 < ntiles) {
            pa0 = *(const float4*)(Ap + (t + 1) * 16);
            pa1 = *(const float4*)(Ap + (t + 1) * 16 + 4);
            pbh = *(const uint4*)(Bhp + (t + 1) * 8);
            pbl = *(const uint4*)(Blp + (t + 1) * 8);
        }

        const uint32_t* ah = Ah + buf * G3_BUF;
        const uint32_t* al = Al + buf * G3_BUF;
        const uint32_t* bh = Bh + buf * G3_BUF;
        const uint32_t* bl = Bl + buf * G3_BUF;

        uint32_t afh[4][4], afl[4][4], bfh[4][2], bfl[4][2];
        #pragma unroll
        for (int mt = 0; mt < 4; mt++) {
            const int m0 = wm + mt * 16;
            afh[mt][0] = ah[(m0 + g) * G3_S + tg];
            afh[mt][1] = ah[(m0 + g + 8) * G3_S + tg];
            afh[mt][2] = ah[(m0 + g) * G3_S + tg + 4];
            afh[mt][3] = ah[(m0 + g + 8) * G3_S + tg + 4];
            afl[mt][0] = al[(m0 + g) * G3_S + tg];
            afl[mt][1] = al[(m0 + g + 8) * G3_S + tg];
            afl[mt][2] = al[(m0 + g) * G3_S + tg + 4];
            afl[mt][3] = al[(m0 + g + 8) * G3_S + tg + 4];
        }
        #pragma unroll
        for (int nt = 0; nt < 4; nt++) {
            const int n0 = wn + nt * 8;
            bfh[nt][0] = bh[(n0 + g) * G3_S + tg];
            bfh[nt][1] = bh[(n0 + g) * G3_S + tg + 4];
            bfl[nt][0] = bl[(n0 + g) * G3_S + tg];
            bfl[nt][1] = bl[(n0 + g) * G3_S + tg + 4];
        }
        #pragma unroll
        for (int mt = 0; mt < 4; mt++)
            #pragma unroll
            for (int nt = 0; nt < 4; nt++) {
                mma16bf(acc[mt][nt], afh[mt], bfh[nt]);
                mma16bf(acc[mt][nt], afh[mt], bfl[nt]);
                mma16bf(acc[mt][nt], afl[mt], bfh[nt]);
            }

        if (t + 1 < ntiles) {
            const int nb = buf ^ 1;
            float hv[8], lv[8];
            float src[8] = {pa0.x, pa0.y, pa0.z, pa0.w, pa1.x, pa1.y, pa1.z, pa1.w};
            #pragma unroll
            for (int j = 0; j < 8; j++) split_bf(src[j], hv[j], lv[j]);
            uint4 uh = make_uint4(pack_bf2(hv[0], hv[1]), pack_bf2(hv[2], hv[3]),
                                  pack_bf2(hv[4], hv[5]), pack_bf2(hv[6], hv[7]));
            uint4 ul = make_uint4(pack_bf2(lv[0], lv[1]), pack_bf2(lv[2], lv[3]),
                                  pack_bf2(lv[4], lv[5]), pack_bf2(lv[6], lv[7]));
            __syncthreads();
            *(uint4*)&Ah[nb * G3_BUF + arow * G3_S + akb / 2] = uh;
            *(uint4*)&Al[nb * G3_BUF + arow * G3_S + akb / 2] = ul;
            *(uint4*)&Bh[nb * G3_BUF + brow * G3_S + bkp] = pbh;
            *(uint4*)&Bl[nb * G3_BUF + brow * G3_S + bkp] = pbl;
            __syncthreads();
            buf = nb;
        }
    }

    #pragma unroll
    for (int mt = 0; mt < 4; mt++) {
        #pragma unroll
        for (int nt = 0; nt < 4; nt++) {
            const int coll = bx * 128 + wn + nt * 8 + 2 * tg;
            const float bv0 = bias[coll], bv1 = bias[coll + 1];
            const int row0 = by * 128 + wm + mt * 16 + g;
            const int col = EMB + coll;
            float2 v0 = make_float2(acc[mt][nt][0] + bv0, acc[mt][nt][1] + bv1);
            float2 v1 = make_float2(acc[mt][nt][2] + bv0, acc[mt][nt][3] + bv1);
            *(float2*)(C + (size_t)row0 * ldc + col)       = v0;
            *(float2*)(C + (size_t)(row0 + 8) * ldc + col) = v1;
        }
    }
}

// ---------------- Flash attention: fp16 QK^T, tf32 PV, fused KIVI quant ----------------
// Q/K packed half2 [row][kp], stride 36 words (=4 mod 32, conflict-free).
#define SQH 36
#define SP  68
#define SV  72
#define ATT_FLOATS (128 * SQH + 64 * SQH + 128 * SP + 64 * SV + 64)

__global__ __launch_bounds__(256, 2) void attn_f16qk(
    const float* __restrict__ qkv, const float* __restrict__ mask,
    float* __restrict__ out)
{
    extern __shared__ uint32_t smu[];
    uint32_t* Qs = smu;                  // 128 x 32 pairs
    uint32_t* Ks = Qs + 128 * SQH;       // 64 x 32 pairs
    uint32_t* Ps = Ks + 64 * SQH;        // 128 x 64 tf32
    uint32_t* Vs = Ps + 128 * SP;        // 64 x 64 tf32
    float*    Ms = (float*)(Vs + 64 * SV);

    const int tid = threadIdx.x, lane = tid & 31, wid = tid >> 5;
    const int g = lane >> 2, tg = lane & 3;
    const int m0 = wid * 16;

    const int bid = blockIdx.x;
    const int qt = bid & 7;
    const int h  = (bid >> 3) & 15;
    const int b  = bid >> 7;

    const size_t qbase = ((size_t)(b * S_LEN) + qt * 128) * (3 * EMB) + h * HD;
    const size_t kbase = ((size_t)(b * S_LEN)) * (3 * EMB) + EMB + h * HD;
    const size_t vbase = ((size_t)(b * S_LEN)) * (3 * EMB) + 2 * EMB + h * HD;
    const float* mp = mask + b * S_LEN;

    // load Q tile (128x64) as packed fp16 pairs
    #pragma unroll
    for (int i = 0; i < 8; i++) {
        int f = tid + 256 * i;
        int row = f >> 4, d4 = (f & 15) * 4;
        float4 v = *(const float4*)(qkv + qbase + (size_t)row * (3 * EMB) + d4);
        uint2 u = make_uint2(pack_h2(v.x, v.y), pack_h2(v.z, v.w));
        *(uint2*)&Qs[row * SQH + d4 / 2] = u;
    }

    float m_i[2] = {-INFINITY, -INFINITY}, l_i[2] = {0.0f, 0.0f};
    float oa[8][4];
    #pragma unroll
    for (int nt = 0; nt < 8; nt++)
        #pragma unroll
        for (int i = 0; i < 4; i++) oa[nt][i] = 0.0f;

    for (int kt = 0; kt < S_LEN / 64; ++kt) {
        #pragma unroll
        for (int i = 0; i < 4; i++) {
            int f = tid + 256 * i;
            int row = f >> 4, d4 = (f & 15) * 4;
            int key = (kt << 6) + row;

            // K: KIVI 2-bit fake quant on the fly, store packed fp16
            float4 kv = *(const float4*)(qkv + kbase + (size_t)key * (3 * EMB) + d4);
            float ma = fmaxf(fmaxf(fabsf(kv.x), fabsf(kv.y)),
                             fmaxf(fabsf(kv.z), fabsf(kv.w)));
            float scale = ma * (1.0f / 1.5f);
            float safe = (scale == 0.0f) ? 1.0f : scale;
            float cx = fminf(fmaxf(rintf(kv.x / safe + 1.5f), 0.0f), 3.0f);
            float cy = fminf(fmaxf(rintf(kv.y / safe + 1.5f), 0.0f), 3.0f);
            float cz = fminf(fmaxf(rintf(kv.z / safe + 1.5f), 0.0f), 3.0f);
            float cw = fminf(fmaxf(rintf(kv.w / safe + 1.5f), 0.0f), 3.0f);
            uint2 uk = make_uint2(pack_h2((cx - 1.5f) * scale, (cy - 1.5f) * scale),
                                  pack_h2((cz - 1.5f) * scale, (cw - 1.5f) * scale));
            *(uint2*)&Ks[row * SQH + d4 / 2] = uk;

            // V: tf32
            float4 vv = *(const float4*)(qkv + vbase + (size_t)key * (3 * EMB) + d4);
            uint32_t* dv = &Vs[row * SV + d4];
            dv[0] = f2tf(vv.x); dv[1] = f2tf(vv.y);
            dv[2] = f2tf(vv.z); dv[3] = f2tf(vv.w);
        }
        if (tid < 64) Ms[tid] = mp[(kt << 6) + tid];
        __syncthreads();

        // ---- S = Q K^T : m=16, n=64 (8 nt), k=64 (4 k16 steps), fp16 ----
        float sacc[8][4];
        #pragma unroll
        for (int nt = 0; nt < 8; nt++)
            #pragma unroll
            for (int i = 0; i < 4; i++) sacc[nt][i] = 0.0f;

        #pragma unroll
        for (int ks = 0; ks < 4; ++ks) {
            const int kb = ks * 8;   // pair base
            uint32_t af[4];
            af[0] = Qs[(m0 + g) * SQH + kb + tg];
            af[1] = Qs[(m0 + g + 8) * SQH + kb + tg];
            af[2] = Qs[(m0 + g) * SQH + kb + tg + 4];
            af[3] = Qs[(m0 + g + 8) * SQH + kb + tg + 4];
            #pragma unroll
            for (int nt = 0; nt < 8; ++nt) {
                uint32_t bf[2];
                bf[0] = Ks[(nt * 8 + g) * SQH + kb + tg];
                bf[1] = Ks[(nt * 8 + g) * SQH + kb + tg + 4];
                mma16f(sacc[nt], af, bf);
            }
        }

        // ---- online softmax ----
        #pragma unroll
        for (int rr = 0; rr < 2; ++rr) {
            float mx = -INFINITY;
            #pragma unroll
            for (int nt = 0; nt < 8; nt++) {
                const int c0 = nt * 8 + 2 * tg;
                float s0 = (sacc[nt][rr * 2 + 0] + Ms[c0]) * 0.125f;
                float s1 = (sacc[nt][rr * 2 + 1] + Ms[c0 + 1]) * 0.125f;
                sacc[nt][rr * 2 + 0] = s0;
                sacc[nt][rr * 2 + 1] = s1;
                mx = fmaxf(mx, fmaxf(s0, s1));
            }
            mx = fmaxf(mx, __shfl_xor_sync(0xffffffffu, mx, 1));
            mx = fmaxf(mx, __shfl_xor_sync(0xffffffffu, mx, 2));
            const float mnew = fmaxf(m_i[rr], mx);
            const float alpha = __expf(m_i[rr] - mnew);
            float rs = 0.0f;
            const int row = m0 + g + rr * 8;
            #pragma unroll
            for (int nt = 0; nt < 8; nt++) {
                float p0 = __expf(sacc[nt][rr * 2 + 0] - mnew);
                float p1 = __expf(sacc[nt][rr * 2 + 1] - mnew);
                rs += p0 + p1;
                uint32_t* pp = &Ps[row * SP + nt * 8 + 2 * tg];
                pp[0] = f2tf(p0); pp[1] = f2tf(p1);
            }
            rs += __shfl_xor_sync(0xffffffffu, rs, 1);
            rs += __shfl_xor_sync(0xffffffffu, rs, 2);
            l_i[rr] = l_i[rr] * alpha + rs;
            m_i[rr] = mnew;
            #pragma unroll
            for (int nt = 0; nt < 8; nt++) {
                oa[nt][rr * 2 + 0] *= alpha;
                oa[nt][rr * 2 + 1] *= alpha;
            }
        }
        __syncwarp();   // P rows are warp-private

        // ---- O += P V : tf32, k=64 keys (8 ks), n=64 dims (8 nt) ----
        #pragma unroll
        for (int ks = 0; ks < 8; ++ks) {
            const int k0 = ks * 8;
            uint32_t ap[4];
            ap[0] = Ps[(m0 + g) * SP + k0 + tg];
            ap[1] = Ps[(m0 + g + 8) * SP + k0 + tg];
            ap[2] = Ps[(m0 + g) * SP + k0 + tg + 4];
            ap[3] = Ps[(m0 + g + 8) * SP + k0 + tg + 4];
            #pragma unroll
            for (int nt = 0; nt < 8; ++nt) {
                uint32_t bf[2];
                bf[0] = Vs[(k0 + tg) * SV + nt * 8 + g];
                bf[1] = Vs[(k0 + tg + 4) * SV + nt * 8 + g];
                mma8(oa[nt], ap, bf);
            }
        }
        __syncthreads();
    }

    #pragma unroll
    for (int rr = 0; rr < 2; ++rr) {
        const float inv = 1.0f / l_i[rr];
        const int srow = qt * 128 + m0 + g + rr * 8;
        float* op = out + ((size_t)(b * S_LEN + srow)) * EMB + h * HD;
        #pragma unroll
        for (int nt = 0; nt < 8; nt++) {
            float2 v = make_float2(oa[nt][rr * 2 + 0] * inv, oa[nt][rr * 2 + 1] * inv);
            *(float2*)(op + nt * 8 + 2 * tg) = v;
        }
    }
}

// ---------------- launch ----------------
extern "C" void kernel_launch(void* const* d_in, const int* in_sizes, int n_in,
                              void* d_out, int out_size)
{
    const float* hidden = (const float*)d_in[0];
    const float* mask   = (const float*)d_in[1];
    const float* w_attn = (const float*)d_in[2];
    const float* b_attn = (const float*)d_in[3];
    const float* w_proj = (const float*)d_in[4];
    const float* b_proj = (const float*)d_in[5];
    float* out = (float*)d_out;

    float *qkv, *attn;
    uint32_t *wkh, *wkl, *wqv, *wp;
    cudaGetSymbolAddress((void**)&qkv,  g_qkv);
    cudaGetSymbolAddress((void**)&attn, g_attn);
    cudaGetSymbolAddress((void**)&wkh,  g_wkh);
    cudaGetSymbolAddress((void**)&wkl,  g_wkl);
    cudaGetSymbolAddress((void**)&wqv,  g_wqv);
    cudaGetSymbolAddress((void**)&wp,   g_wp);

    const int att_smem = ATT_FLOATS * (int)sizeof(float);
    cudaFuncSetAttribute(attn_f16qk,
                         cudaFuncAttributeMaxDynamicSharedMemorySize, att_smem);
    cudaFuncSetAttribute(gemm_bf16k,
                         cudaFuncAttributeMaxDynamicSharedMemorySize, G3_SMEM_BYTES);

    // 0) prep packed weights
    prep_wk<<<EMB * (EMB / 2) / 256, 256>>>(w_attn, wkh, wkl);
    // wqv: n in [0,2048): n<1024 -> Q col n; n>=1024 -> V col n+1024. shift=11.
    prep_pack_f16<<<2048 * 512 / 256, 256>>>(w_attn, 3 * EMB, 2047, 11, 1024, wqv);
    // wp: n in [0,1024) -> proj col n. shift=10.
    prep_pack_f16<<<1024 * 512 / 256, 256>>>(w_proj, EMB, 1023, 10, 4096, wp);

    // 1) Q and V sections, fp16 (bx>=8 -> V cols at [2048,3072))
    dim3 gqv(16, BATCH * S_LEN / 128);
    gemm_f16<<<gqv, 256>>>(hidden, wqv, b_attn, qkv,
                           EMB, 3 * EMB, EMB, 8, 1024);

    // 2) K section, bf16x3
    dim3 gk(EMB / 128, BATCH * S_LEN / 128);
    gemm_bf16k<<<gk, 256, G3_SMEM_BYTES>>>(hidden, wkh, wkl, b_attn + EMB,
                                           qkv, EMB, 3 * EMB, EMB);

    // 3) attention (fp16 QK^T, fused KIVI quant)
    attn_f16qk<<<BATCH * NH * (S_LEN / 128), 256, att_smem>>>(qkv, mask, attn);

    // 4) out projection, fp16
    dim3 gp(EMB / 128, BATCH * S_LEN / 128);
    gemm_f16<<<gp, 256>>>(attn, wp, b_proj, out,
                          EMB, EMB, EMB, 16, 0);
}

// round 9
// speedup vs baseline: 3.4346x; 1.0698x over previous
#include <cuda_runtime.h>
#include <cuda_bf16.h>
#include <cuda_fp16.h>
#include <math.h>
#include <stdint.h>

#define BATCH 4
#define S_LEN 1024
#define EMB   1024
#define NH    16
#define HD    64

// ---------------- scratch (no allocations allowed) ----------------
__device__ float    g_qkv [BATCH * S_LEN * 3 * EMB];   // [B,S,3E]
__device__ float    g_attn[BATCH * S_LEN * EMB];       // [B,S,E]
__device__ uint32_t g_wkh [EMB * (EMB / 2)];           // Wk bf16 hi, [n][kpair]
__device__ uint32_t g_wkl [EMB * (EMB / 2)];           // Wk bf16 lo, [n][kpair]
__device__ uint32_t g_wqv [2048 * (EMB / 2)];          // Wq|Wv fp16,  [n][kpair]
__device__ uint32_t g_wp  [EMB * (EMB / 2)];           // Wproj fp16,  [n][kpair]

// ---------------- helpers ----------------
__device__ __forceinline__ void mma16bf(float* d, const uint32_t* a, const uint32_t* b) {
    asm volatile(
        "mma.sync.aligned.m16n8k16.row.col.f32.bf16.bf16.f32 "
        "{%0,%1,%2,%3}, {%4,%5,%6,%7}, {%8,%9}, {%0,%1,%2,%3};"
        : "+f"(d[0]), "+f"(d[1]), "+f"(d[2]), "+f"(d[3])
        : "r"(a[0]), "r"(a[1]), "r"(a[2]), "r"(a[3]), "r"(b[0]), "r"(b[1]));
}

__device__ __forceinline__ void mma16f(float* d, const uint32_t* a, const uint32_t* b) {
    asm volatile(
        "mma.sync.aligned.m16n8k16.row.col.f32.f16.f16.f32 "
        "{%0,%1,%2,%3}, {%4,%5,%6,%7}, {%8,%9}, {%0,%1,%2,%3};"
        : "+f"(d[0]), "+f"(d[1]), "+f"(d[2]), "+f"(d[3])
        : "r"(a[0]), "r"(a[1]), "r"(a[2]), "r"(a[3]), "r"(b[0]), "r"(b[1]));
}

__device__ __forceinline__ uint32_t pack_bf2(float x0, float x1) {
    __nv_bfloat162 p = __floats2bfloat162_rn(x0, x1);   // .x = low half
    return *(uint32_t*)&p;
}

__device__ __forceinline__ uint32_t pack_h2(float x0, float x1) {
    __half2 p = __floats2half2_rn(x0, x1);              // .x = low half
    return *(uint32_t*)&p;
}

__device__ __forceinline__ void split_bf(float x, float& h, float& l) {
    __nv_bfloat16 hb = __float2bfloat16_rn(x);
    h = __bfloat162float(hb);
    l = x - h;
}

// ---------------- prep: Wk (cols [1024,2048)) -> packed bf16 hi/lo ----------------
__global__ __launch_bounds__(256) void prep_wk(
    const float* __restrict__ w, uint32_t* __restrict__ wh, uint32_t* __restrict__ wl)
{
    int idx = blockIdx.x * 256 + threadIdx.x;
    int n  = idx & 1023;
    int kp = idx >> 10;
    float x0 = w[(size_t)(2 * kp)     * (3 * EMB) + EMB + n];
    float x1 = w[(size_t)(2 * kp + 1) * (3 * EMB) + EMB + n];
    float h0, l0, h1, l1;
    split_bf(x0, h0, l0);
    split_bf(x1, h1, l1);
    wh[(size_t)n * 512 + kp] = pack_bf2(h0, h1);
    wl[(size_t)n * 512 + kp] = pack_bf2(l0, l1);
}

// ---------------- prep: pack a weight section to fp16 [n][kpair] ----------------
__global__ __launch_bounds__(256) void prep_pack_f16(
    const float* __restrict__ w, int ldw, int nmask, int nshift, int nswitch,
    uint32_t* __restrict__ out)
{
    int idx = blockIdx.x * 256 + threadIdx.x;
    int n  = idx & nmask;
    int kp = idx >> nshift;
    int col = n + ((n >= nswitch) ? 1024 : 0);
    float x0 = w[(size_t)(2 * kp)     * ldw + col];
    float x1 = w[(size_t)(2 * kp + 1) * ldw + col];
    out[(size_t)n * 512 + kp] = pack_h2(x0, x1);
}

// ---------------- fp16 GEMM: C = A*B + bias, B pre-packed [n][kp] ----------------
// BM=BN=128, BK=32 (2 k16 steps/tile), 256 threads (8 warps 2x4), warp 64x32.
// Tiles [row][kp] stride 20 (=4 mod 32): all fragment LDS conflict-free.
#define GF_S 20
#define GF_BUF (128 * GF_S)

__global__ __launch_bounds__(256, 2) void gemm_f16(
    const float* __restrict__ A, const uint32_t* __restrict__ Bp,
    const float* __restrict__ bias, float* __restrict__ C,
    int lda, int ldc, int K, int nsplit, int gap)
{
    __shared__ uint32_t As[2][GF_BUF];
    __shared__ uint32_t Bs[2][GF_BUF];

    const int tid = threadIdx.x;
    const int bx = blockIdx.x, by = blockIdx.y;
    const int bcol = bx * 128 + ((bx >= nsplit) ? gap : 0);
    const int lane = tid & 31, wid = tid >> 5;
    const int g = lane >> 2, tg = lane & 3;
    const int wm = (wid >> 2) * 64, wn = (wid & 3) * 32;

    const int arow = tid >> 1, akb = (tid & 1) * 16;    // 16 k floats per thread
    const int brow = tid >> 1, bkp = (tid & 1) * 8;     // 8 kp words per thread
    const float*    Ap  = A  + (size_t)(by * 128 + arow) * lda + akb;
    const uint32_t* Bpp = Bp + (size_t)(bx * 128 + brow) * 512 + bkp;

    float acc[4][4][4];
    #pragma unroll
    for (int mt = 0; mt < 4; mt++)
        #pragma unroll
        for (int nt = 0; nt < 4; nt++)
            #pragma unroll
            for (int i = 0; i < 4; i++) acc[mt][nt][i] = 0.0f;

    float4 pa[4];
    uint4  pbv[2];
    #pragma unroll
    for (int q = 0; q < 4; q++) pa[q] = *(const float4*)(Ap + q * 4);
    pbv[0] = *(const uint4*)(Bpp);
    pbv[1] = *(const uint4*)(Bpp + 4);

    const int ntiles = K >> 5;
    int buf = 0;
    {
        uint4 ua0 = make_uint4(pack_h2(pa[0].x, pa[0].y), pack_h2(pa[0].z, pa[0].w),
                               pack_h2(pa[1].x, pa[1].y), pack_h2(pa[1].z, pa[1].w));
        uint4 ua1 = make_uint4(pack_h2(pa[2].x, pa[2].y), pack_h2(pa[2].z, pa[2].w),
                               pack_h2(pa[3].x, pa[3].y), pack_h2(pa[3].z, pa[3].w));
        *(uint4*)&As[0][arow * GF_S + akb / 2]     = ua0;
        *(uint4*)&As[0][arow * GF_S + akb / 2 + 4] = ua1;
        *(uint4*)&Bs[0][brow * GF_S + bkp]     = pbv[0];
        *(uint4*)&Bs[0][brow * GF_S + bkp + 4] = pbv[1];
    }
    __syncthreads();

    for (int t = 0; t < ntiles; ++t) {
        if (t + 1 < ntiles) {
            #pragma unroll
            for (int q = 0; q < 4; q++)
                pa[q] = *(const float4*)(Ap + (t + 1) * 32 + q * 4);
            pbv[0] = *(const uint4*)(Bpp + (t + 1) * 16);
            pbv[1] = *(const uint4*)(Bpp + (t + 1) * 16 + 4);
        }

        const uint32_t* as = As[buf];
        const uint32_t* bs = Bs[buf];

        #pragma unroll
        for (int ks = 0; ks < 2; ++ks) {
            const int kb = ks * 8;
            uint32_t af[4][4], bf[4][2];
            #pragma unroll
            for (int mt = 0; mt < 4; mt++) {
                const int m0 = wm + mt * 16;
                af[mt][0] = as[(m0 + g) * GF_S + kb + tg];
                af[mt][1] = as[(m0 + g + 8) * GF_S + kb + tg];
                af[mt][2] = as[(m0 + g) * GF_S + kb + tg + 4];
                af[mt][3] = as[(m0 + g + 8) * GF_S + kb + tg + 4];
            }
            #pragma unroll
            for (int nt = 0; nt < 4; nt++) {
                const int n0 = wn + nt * 8;
                bf[nt][0] = bs[(n0 + g) * GF_S + kb + tg];
                bf[nt][1] = bs[(n0 + g) * GF_S + kb + tg + 4];
            }
            #pragma unroll
            for (int mt = 0; mt < 4; mt++)
                #pragma unroll
                for (int nt = 0; nt < 4; nt++)
                    mma16f(acc[mt][nt], af[mt], bf[nt]);
        }

        if (t + 1 < ntiles) {
            const int nb = buf ^ 1;
            uint4 ua0 = make_uint4(pack_h2(pa[0].x, pa[0].y), pack_h2(pa[0].z, pa[0].w),
                                   pack_h2(pa[1].x, pa[1].y), pack_h2(pa[1].z, pa[1].w));
            uint4 ua1 = make_uint4(pack_h2(pa[2].x, pa[2].y), pack_h2(pa[2].z, pa[2].w),
                                   pack_h2(pa[3].x, pa[3].y), pack_h2(pa[3].z, pa[3].w));
            __syncthreads();
            *(uint4*)&As[nb][arow * GF_S + akb / 2]     = ua0;
            *(uint4*)&As[nb][arow * GF_S + akb / 2 + 4] = ua1;
            *(uint4*)&Bs[nb][brow * GF_S + bkp]     = pbv[0];
            *(uint4*)&Bs[nb][brow * GF_S + bkp + 4] = pbv[1];
            __syncthreads();
            buf = nb;
        }
    }

    #pragma unroll
    for (int mt = 0; mt < 4; mt++) {
        #pragma unroll
        for (int nt = 0; nt < 4; nt++) {
            const int col = bcol + wn + nt * 8 + 2 * tg;
            const float bv0 = bias[col], bv1 = bias[col + 1];
            const int row0 = by * 128 + wm + mt * 16 + g;
            float2 v0 = make_float2(acc[mt][nt][0] + bv0, acc[mt][nt][1] + bv1);
            float2 v1 = make_float2(acc[mt][nt][2] + bv0, acc[mt][nt][3] + bv1);
            *(float2*)(C + (size_t)row0 * ldc + col)       = v0;
            *(float2*)(C + (size_t)(row0 + 8) * ldc + col) = v1;
        }
    }
}

// ---------------- bf16x3 GEMM for the K section (unchanged, known-good) ----------------
#define G3_S 12
#define G3_BUF (128 * G3_S)
#define G3_SMEM_BYTES (8 * G3_BUF * 4)

__global__ __launch_bounds__(256, 2) void gemm_bf16k(
    const float* __restrict__ A, const uint32_t* __restrict__ Bhg,
    const uint32_t* __restrict__ Blg, const float* __restrict__ bias,
    float* __restrict__ C, int lda, int ldc, int K)
{
    extern __shared__ uint32_t s3[];
    uint32_t* Ah = s3;
    uint32_t* Al = Ah + 2 * G3_BUF;
    uint32_t* Bh = Al + 2 * G3_BUF;
    uint32_t* Bl = Bh + 2 * G3_BUF;

    const int tid = threadIdx.x;
    const int bx = blockIdx.x, by = blockIdx.y;
    const int lane = tid & 31, wid = tid >> 5;
    const int g = lane >> 2, tg = lane & 3;
    const int wm = (wid >> 2) * 64, wn = (wid & 3) * 32;

    const int arow = tid >> 1, akb = (tid & 1) * 8;
    const int brow = tid >> 1, bkp = (tid & 1) * 4;
    const float*    Ap  = A + (size_t)(by * 128 + arow) * lda + akb;
    const uint32_t* Bhp = Bhg + (size_t)(bx * 128 + brow) * 512 + bkp;
    const uint32_t* Blp = Blg + (size_t)(bx * 128 + brow) * 512 + bkp;

    float acc[4][4][4];
    #pragma unroll
    for (int mt = 0; mt < 4; mt++)
        #pragma unroll
        for (int nt = 0; nt < 4; nt++)
            #pragma unroll
            for (int i = 0; i < 4; i++) acc[mt][nt][i] = 0.0f;

    float4 pa0 = *(const float4*)(Ap);
    float4 pa1 = *(const float4*)(Ap + 4);
    uint4  pbh = *(const uint4*)(Bhp);
    uint4  pbl = *(const uint4*)(Blp);

    const int ntiles = K >> 4;
    int buf = 0;
    {
        float hv[8], lv[8];
        float src[8] = {pa0.x, pa0.y, pa0.z, pa0.w, pa1.x, pa1.y, pa1.z, pa1.w};
        #pragma unroll
        for (int j = 0; j < 8; j++) split_bf(src[j], hv[j], lv[j]);
        uint4 uh = make_uint4(pack_bf2(hv[0], hv[1]), pack_bf2(hv[2], hv[3]),
                              pack_bf2(hv[4], hv[5]), pack_bf2(hv[6], hv[7]));
        uint4 ul = make_uint4(pack_bf2(lv[0], lv[1]), pack_bf2(lv[2], lv[3]),
                              pack_bf2(lv[4], lv[5]), pack_bf2(lv[6], lv[7]));
        *(uint4*)&Ah[arow * G3_S + akb / 2] = uh;
        *(uint4*)&Al[arow * G3_S + akb / 2] = ul;
        *(uint4*)&Bh[brow * G3_S + bkp] = pbh;
        *(uint4*)&Bl[brow * G3_S + bkp] = pbl;
    }
    __syncthreads();

    for (int t = 0; t < ntiles; ++t) {
        if (t + 1 < ntiles) {
            pa0 = *(const float4*)(Ap + (t + 1) * 16);
            pa1 = *(const float4*)(Ap + (t + 1) * 16 + 4);
            pbh = *(const uint4*)(Bhp + (t + 1) * 8);
            pbl = *(const uint4*)(Blp + (t + 1) * 8);
        }

        const uint32_t* ah = Ah + buf * G3_BUF;
        const uint32_t* al = Al + buf * G3_BUF;
        const uint32_t* bh = Bh + buf * G3_BUF;
        const uint32_t* bl = Bl + buf * G3_BUF;

        uint32_t afh[4][4], afl[4][4], bfh[4][2], bfl[4][2];
        #pragma unroll
        for (int mt = 0; mt < 4; mt++) {
            const int m0 = wm + mt * 16;
            afh[mt][0] = ah[(m0 + g) * G3_S + tg];
            afh[mt][1] = ah[(m0 + g + 8) * G3_S + tg];
            afh[mt][2] = ah[(m0 + g) * G3_S + tg + 4];
            afh[mt][3] = ah[(m0 + g + 8) * G3_S + tg + 4];
            afl[mt][0] = al[(m0 + g) * G3_S + tg];
            afl[mt][1] = al[(m0 + g + 8) * G3_S + tg];
            afl[mt][2] = al[(m0 + g) * G3_S + tg + 4];
            afl[mt][3] = al[(m0 + g + 8) * G3_S + tg + 4];
        }
        #pragma unroll
        for (int nt = 0; nt < 4; nt++) {
            const int n0 = wn + nt * 8;
            bfh[nt][0] = bh[(n0 + g) * G3_S + tg];
            bfh[nt][1] = bh[(n0 + g) * G3_S + tg + 4];
            bfl[nt][0] = bl[(n0 + g) * G3_S + tg];
            bfl[nt][1] = bl[(n0 + g) * G3_S + tg + 4];
        }
        #pragma unroll
        for (int mt = 0; mt < 4; mt++)
            #pragma unroll
            for (int nt = 0; nt < 4; nt++) {
                mma16bf(acc[mt][nt], afh[mt], bfh[nt]);
                mma16bf(acc[mt][nt], afh[mt], bfl[nt]);
                mma16bf(acc[mt][nt], afl[mt], bfh[nt]);
            }

        if (t + 1 < ntiles) {
            const int nb = buf ^ 1;
            float hv[8], lv[8];
            float src[8] = {pa0.x, pa0.y, pa0.z, pa0.w, pa1.x, pa1.y, pa1.z, pa1.w};
            #pragma unroll
            for (int j = 0; j < 8; j++) split_bf(src[j], hv[j], lv[j]);
            uint4 uh = make_uint4(pack_bf2(hv[0], hv[1]), pack_bf2(hv[2], hv[3]),
                                  pack_bf2(hv[4], hv[5]), pack_bf2(hv[6], hv[7]));
            uint4 ul = make_uint4(pack_bf2(lv[0], lv[1]), pack_bf2(lv[2], lv[3]),
                                  pack_bf2(lv[4], lv[5]), pack_bf2(lv[6], lv[7]));
            __syncthreads();
            *(uint4*)&Ah[nb * G3_BUF + arow * G3_S + akb / 2] = uh;
            *(uint4*)&Al[nb * G3_BUF + arow * G3_S + akb / 2] = ul;
            *(uint4*)&Bh[nb * G3_BUF + brow * G3_S + bkp] = pbh;
            *(uint4*)&Bl[nb * G3_BUF + brow * G3_S + bkp] = pbl;
            __syncthreads();
            buf = nb;
        }
    }

    #pragma unroll
    for (int mt = 0; mt < 4; mt++) {
        #pragma unroll
        for (int nt = 0; nt < 4; nt++) {
            const int coll = bx * 128 + wn + nt * 8 + 2 * tg;
            const float bv0 = bias[coll], bv1 = bias[coll + 1];
            const int row0 = by * 128 + wm + mt * 16 + g;
            const int col = EMB + coll;
            float2 v0 = make_float2(acc[mt][nt][0] + bv0, acc[mt][nt][1] + bv1);
            float2 v1 = make_float2(acc[mt][nt][2] + bv0, acc[mt][nt][3] + bv1);
            *(float2*)(C + (size_t)row0 * ldc + col)       = v0;
            *(float2*)(C + (size_t)(row0 + 8) * ldc + col) = v1;
        }
    }
}

// ---------------- Flash attention: all-fp16 mma, fused KIVI quant ----------------
// Q/K/P [row][kp] and Vt [dim][kp] all packed half2, stride 36 (=4 mod 32):
// every fragment LDS conflict-free. V loaded transposed straight from gmem.
#define SQH 36
#define ATT_FLOATS (128 * SQH + 64 * SQH + 128 * SQH + 64 * SQH + 64)

__global__ __launch_bounds__(256, 2) void attn_f16(
    const float* __restrict__ qkv, const float* __restrict__ mask,
    float* __restrict__ out)
{
    extern __shared__ uint32_t smu[];
    uint32_t* Qs = smu;                  // [128][36] q pairs
    uint32_t* Ks = Qs + 128 * SQH;       // [64][36]  k pairs (dequantized)
    uint32_t* Ps = Ks + 64 * SQH;        // [128][36] p pairs
    uint32_t* Vt = Ps + 128 * SQH;       // [64][36]  v^T: [dim][keypair]
    float*    Ms = (float*)(Vt + 64 * SQH);

    const int tid = threadIdx.x, lane = tid & 31, wid = tid >> 5;
    const int g = lane >> 2, tg = lane & 3;
    const int m0 = wid * 16;

    const int bid = blockIdx.x;
    const int qt = bid & 7;
    const int h  = (bid >> 3) & 15;
    const int b  = bid >> 7;

    const size_t qbase = ((size_t)(b * S_LEN) + qt * 128) * (3 * EMB) + h * HD;
    const size_t kbase = ((size_t)(b * S_LEN)) * (3 * EMB) + EMB + h * HD;
    const size_t vbase = ((size_t)(b * S_LEN)) * (3 * EMB) + 2 * EMB + h * HD;
    const float* mp = mask + b * S_LEN;

    // load Q tile (128x64) as packed fp16 pairs
    #pragma unroll
    for (int i = 0; i < 8; i++) {
        int f = tid + 256 * i;
        int row = f >> 4, d4 = (f & 15) * 4;
        float4 v = *(const float4*)(qkv + qbase + (size_t)row * (3 * EMB) + d4);
        uint2 u = make_uint2(pack_h2(v.x, v.y), pack_h2(v.z, v.w));
        *(uint2*)&Qs[row * SQH + d4 / 2] = u;
    }

    float m_i[2] = {-INFINITY, -INFINITY}, l_i[2] = {0.0f, 0.0f};
    float oa[8][4];
    #pragma unroll
    for (int nt = 0; nt < 8; nt++)
        #pragma unroll
        for (int i = 0; i < 4; i++) oa[nt][i] = 0.0f;

    for (int kt = 0; kt < S_LEN / 64; ++kt) {
        // K tile: fused KIVI quant, packed fp16 [row][kp]
        #pragma unroll
        for (int i = 0; i < 4; i++) {
            int f = tid + 256 * i;
            int row = f >> 4, d4 = (f & 15) * 4;
            int key = (kt << 6) + row;
            float4 kv = *(const float4*)(qkv + kbase + (size_t)key * (3 * EMB) + d4);
            float ma = fmaxf(fmaxf(fabsf(kv.x), fabsf(kv.y)),
                             fmaxf(fabsf(kv.z), fabsf(kv.w)));
            float scale = ma * (1.0f / 1.5f);
            float safe = (scale == 0.0f) ? 1.0f : scale;
            float cx = fminf(fmaxf(rintf(kv.x / safe + 1.5f), 0.0f), 3.0f);
            float cy = fminf(fmaxf(rintf(kv.y / safe + 1.5f), 0.0f), 3.0f);
            float cz = fminf(fmaxf(rintf(kv.z / safe + 1.5f), 0.0f), 3.0f);
            float cw = fminf(fmaxf(rintf(kv.w / safe + 1.5f), 0.0f), 3.0f);
            uint2 uk = make_uint2(pack_h2((cx - 1.5f) * scale, (cy - 1.5f) * scale),
                                  pack_h2((cz - 1.5f) * scale, (cw - 1.5f) * scale));
            *(uint2*)&Ks[row * SQH + d4 / 2] = uk;
        }
        // V tile transposed: Vt[dim][kp] = {V[2kp][dim], V[2kp+1][dim]}
        #pragma unroll
        for (int i = 0; i < 8; i++) {
            int f = tid + 256 * i;
            int dim = f & 63, kp = f >> 6;   // kp in [0,32)
            int key = (kt << 6) + 2 * kp;
            float v0 = qkv[vbase + (size_t)key * (3 * EMB) + dim];
            float v1 = qkv[vbase + (size_t)(key + 1) * (3 * EMB) + dim];
            Vt[dim * SQH + kp] = pack_h2(v0, v1);
        }
        if (tid < 64) Ms[tid] = mp[(kt << 6) + tid];
        __syncthreads();

        // ---- S = Q K^T : m=16, n=64 (8 nt), k=64 (4 k16), fp16 ----
        float sacc[8][4];
        #pragma unroll
        for (int nt = 0; nt < 8; nt++)
            #pragma unroll
            for (int i = 0; i < 4; i++) sacc[nt][i] = 0.0f;

        #pragma unroll
        for (int ks = 0; ks < 4; ++ks) {
            const int kb = ks * 8;
            uint32_t af[4];
            af[0] = Qs[(m0 + g) * SQH + kb + tg];
            af[1] = Qs[(m0 + g + 8) * SQH + kb + tg];
            af[2] = Qs[(m0 + g) * SQH + kb + tg + 4];
            af[3] = Qs[(m0 + g + 8) * SQH + kb + tg + 4];
            #pragma unroll
            for (int nt = 0; nt < 8; ++nt) {
                uint32_t bf[2];
                bf[0] = Ks[(nt * 8 + g) * SQH + kb + tg];
                bf[1] = Ks[(nt * 8 + g) * SQH + kb + tg + 4];
                mma16f(sacc[nt], af, bf);
            }
        }

        // ---- online softmax; P written as packed fp16 pairs ----
        #pragma unroll
        for (int rr = 0; rr < 2; ++rr) {
            float mx = -INFINITY;
            #pragma unroll
            for (int nt = 0; nt < 8; nt++) {
                const int c0 = nt * 8 + 2 * tg;
                float s0 = (sacc[nt][rr * 2 + 0] + Ms[c0]) * 0.125f;
                float s1 = (sacc[nt][rr * 2 + 1] + Ms[c0 + 1]) * 0.125f;
                sacc[nt][rr * 2 + 0] = s0;
                sacc[nt][rr * 2 + 1] = s1;
                mx = fmaxf(mx, fmaxf(s0, s1));
            }
            mx = fmaxf(mx, __shfl_xor_sync(0xffffffffu, mx, 1));
            mx = fmaxf(mx, __shfl_xor_sync(0xffffffffu, mx, 2));
            const float mnew = fmaxf(m_i[rr], mx);
            const float alpha = __expf(m_i[rr] - mnew);
            float rs = 0.0f;
            const int row = m0 + g + rr * 8;
            #pragma unroll
            for (int nt = 0; nt < 8; nt++) {
                float p0 = __expf(sacc[nt][rr * 2 + 0] - mnew);
                float p1 = __expf(sacc[nt][rr * 2 + 1] - mnew);
                rs += p0 + p1;
                Ps[row * SQH + nt * 4 + tg] = pack_h2(p0, p1);
            }
            rs += __shfl_xor_sync(0xffffffffu, rs, 1);
            rs += __shfl_xor_sync(0xffffffffu, rs, 2);
            l_i[rr] = l_i[rr] * alpha + rs;
            m_i[rr] = mnew;
            #pragma unroll
            for (int nt = 0; nt < 8; nt++) {
                oa[nt][rr * 2 + 0] *= alpha;
                oa[nt][rr * 2 + 1] *= alpha;
            }
        }
        __syncwarp();   // P rows are warp-private

        // ---- O += P V : fp16, k=64 keys (4 k16), n=64 dims (8 nt) ----
        #pragma unroll
        for (int ks = 0; ks < 4; ++ks) {
            const int kb = ks * 8;
            uint32_t ap[4];
            ap[0] = Ps[(m0 + g) * SQH + kb + tg];
            ap[1] = Ps[(m0 + g + 8) * SQH + kb + tg];
            ap[2] = Ps[(m0 + g) * SQH + kb + tg + 4];
            ap[3] = Ps[(m0 + g + 8) * SQH + kb + tg + 4];
            #pragma unroll
            for (int nt = 0; nt < 8; ++nt) {
                uint32_t bf[2];
                bf[0] = Vt[(nt * 8 + g) * SQH + kb + tg];
                bf[1] = Vt[(nt * 8 + g) * SQH + kb + tg + 4];
                mma16f(oa[nt], ap, bf);
            }
        }
        __syncthreads();
    }

    #pragma unroll
    for (int rr = 0; rr < 2; ++rr) {
        const float inv = 1.0f / l_i[rr];
        const int srow = qt * 128 + m0 + g + rr * 8;
        float* op = out + ((size_t)(b * S_LEN + srow)) * EMB + h * HD;
        #pragma unroll
        for (int nt = 0; nt < 8; nt++) {
            float2 v = make_float2(oa[nt][rr * 2 + 0] * inv, oa[nt][rr * 2 + 1] * inv);
            *(float2*)(op + nt * 8 + 2 * tg) = v;
        }
    }
}

// ---------------- launch ----------------
extern "C" void kernel_launch(void* const* d_in, const int* in_sizes, int n_in,
                              void* d_out, int out_size)
{
    const float* hidden = (const float*)d_in[0];
    const float* mask   = (const float*)d_in[1];
    const float* w_attn = (const float*)d_in[2];
    const float* b_attn = (const float*)d_in[3];
    const float* w_proj = (const float*)d_in[4];
    const float* b_proj = (const float*)d_in[5];
    float* out = (float*)d_out;

    float *qkv, *attn;
    uint32_t *wkh, *wkl, *wqv, *wp;
    cudaGetSymbolAddress((void**)&qkv,  g_qkv);
    cudaGetSymbolAddress((void**)&attn, g_attn);
    cudaGetSymbolAddress((void**)&wkh,  g_wkh);
    cudaGetSymbolAddress((void**)&wkl,  g_wkl);
    cudaGetSymbolAddress((void**)&wqv,  g_wqv);
    cudaGetSymbolAddress((void**)&wp,   g_wp);

    const int att_smem = ATT_FLOATS * (int)sizeof(float);
    cudaFuncSetAttribute(attn_f16,
                         cudaFuncAttributeMaxDynamicSharedMemorySize, att_smem);
    cudaFuncSetAttribute(gemm_bf16k,
                         cudaFuncAttributeMaxDynamicSharedMemorySize, G3_SMEM_BYTES);

    // 0) prep packed weights
    prep_wk<<<EMB * (EMB / 2) / 256, 256>>>(w_attn, wkh, wkl);
    prep_pack_f16<<<2048 * 512 / 256, 256>>>(w_attn, 3 * EMB, 2047, 11, 1024, wqv);
    prep_pack_f16<<<1024 * 512 / 256, 256>>>(w_proj, EMB, 1023, 10, 4096, wp);

    // 1) Q and V sections, fp16 (bx>=8 -> V cols at [2048,3072))
    dim3 gqv(16, BATCH * S_LEN / 128);
    gemm_f16<<<gqv, 256>>>(hidden, wqv, b_attn, qkv,
                           EMB, 3 * EMB, EMB, 8, 1024);

    // 2) K section, bf16x3
    dim3 gk(EMB / 128, BATCH * S_LEN / 128);
    gemm_bf16k<<<gk, 256, G3_SMEM_BYTES>>>(hidden, wkh, wkl, b_attn + EMB,
                                           qkv, EMB, 3 * EMB, EMB);

    // 3) attention (all-fp16 mma, fused KIVI quant, transposed V load)
    attn_f16<<<BATCH * NH * (S_LEN / 128), 256, att_smem>>>(qkv, mask, attn);

    // 4) out projection, fp16
    dim3 gp(EMB / 128, BATCH * S_LEN / 128);
    gemm_f16<<<gp, 256>>>(attn, wp, b_proj, out,
                          EMB, EMB, EMB, 16, 0);
}

// round 10
// speedup vs baseline: 3.7323x; 1.0867x over previous
#include <cuda_runtime.h>
#include <cuda_bf16.h>
#include <cuda_fp16.h>
#include <math.h>
#include <stdint.h>

#define BATCH 4
#define S_LEN 1024
#define EMB   1024
#define NH    16
#define HD    64

// ---------------- scratch (no allocations allowed) ----------------
__device__ float    g_qkv [BATCH * S_LEN * 3 * EMB];   // [B,S,3E]
__device__ float    g_attn[BATCH * S_LEN * EMB];       // [B,S,E]
__device__ uint32_t g_wkh [EMB * (EMB / 2)];           // Wk bf16 hi, [n][kpair]
__device__ uint32_t g_wkl [EMB * (EMB / 2)];           // Wk bf16 lo, [n][kpair]
__device__ uint32_t g_wqv [2048 * (EMB / 2)];          // Wq|Wv fp16,  [n][kpair]
__device__ uint32_t g_wp  [EMB * (EMB / 2)];           // Wproj fp16,  [n][kpair]

// ---------------- helpers ----------------
__device__ __forceinline__ void mma16bf(float* d, const uint32_t* a, const uint32_t* b) {
    asm volatile(
        "mma.sync.aligned.m16n8k16.row.col.f32.bf16.bf16.f32 "
        "{%0,%1,%2,%3}, {%4,%5,%6,%7}, {%8,%9}, {%0,%1,%2,%3};"
        : "+f"(d[0]), "+f"(d[1]), "+f"(d[2]), "+f"(d[3])
        : "r"(a[0]), "r"(a[1]), "r"(a[2]), "r"(a[3]), "r"(b[0]), "r"(b[1]));
}

__device__ __forceinline__ void mma16f(float* d, const uint32_t* a, const uint32_t* b) {
    asm volatile(
        "mma.sync.aligned.m16n8k16.row.col.f32.f16.f16.f32 "
        "{%0,%1,%2,%3}, {%4,%5,%6,%7}, {%8,%9}, {%0,%1,%2,%3};"
        : "+f"(d[0]), "+f"(d[1]), "+f"(d[2]), "+f"(d[3])
        : "r"(a[0]), "r"(a[1]), "r"(a[2]), "r"(a[3]), "r"(b[0]), "r"(b[1]));
}

__device__ __forceinline__ void ldsm_x4(uint32_t* r, uint32_t addr) {
    asm volatile("ldmatrix.sync.aligned.m8n8.x4.shared.b16 {%0,%1,%2,%3}, [%4];"
        : "=r"(r[0]), "=r"(r[1]), "=r"(r[2]), "=r"(r[3]) : "r"(addr));
}

__device__ __forceinline__ void ldsm_x2(uint32_t* r, uint32_t addr) {
    asm volatile("ldmatrix.sync.aligned.m8n8.x2.shared.b16 {%0,%1}, [%2];"
        : "=r"(r[0]), "=r"(r[1]) : "r"(addr));
}

__device__ __forceinline__ uint32_t pack_bf2(float x0, float x1) {
    __nv_bfloat162 p = __floats2bfloat162_rn(x0, x1);   // .x = low half
    return *(uint32_t*)&p;
}

__device__ __forceinline__ uint32_t pack_h2(float x0, float x1) {
    __half2 p = __floats2half2_rn(x0, x1);              // .x = low half
    return *(uint32_t*)&p;
}

__device__ __forceinline__ void split_bf(float x, float& h, float& l) {
    __nv_bfloat16 hb = __float2bfloat16_rn(x);
    h = __bfloat162float(hb);
    l = x - h;
}

// ---------------- prep: Wk (cols [1024,2048)) -> packed bf16 hi/lo ----------------
__global__ __launch_bounds__(256) void prep_wk(
    const float* __restrict__ w, uint32_t* __restrict__ wh, uint32_t* __restrict__ wl)
{
    int idx = blockIdx.x * 256 + threadIdx.x;
    int n  = idx & 1023;
    int kp = idx >> 10;
    float x0 = w[(size_t)(2 * kp)     * (3 * EMB) + EMB + n];
    float x1 = w[(size_t)(2 * kp + 1) * (3 * EMB) + EMB + n];
    float h0, l0, h1, l1;
    split_bf(x0, h0, l0);
    split_bf(x1, h1, l1);
    wh[(size_t)n * 512 + kp] = pack_bf2(h0, h1);
    wl[(size_t)n * 512 + kp] = pack_bf2(l0, l1);
}

// ---------------- prep: pack a weight section to fp16 [n][kpair] ----------------
__global__ __launch_bounds__(256) void prep_pack_f16(
    const float* __restrict__ w, int ldw, int nmask, int nshift, int nswitch,
    uint32_t* __restrict__ out)
{
    int idx = blockIdx.x * 256 + threadIdx.x;
    int n  = idx & nmask;
    int kp = idx >> nshift;
    int col = n + ((n >= nswitch) ? 1024 : 0);
    float x0 = w[(size_t)(2 * kp)     * ldw + col];
    float x1 = w[(size_t)(2 * kp + 1) * ldw + col];
    out[(size_t)n * 512 + kp] = pack_h2(x0, x1);
}

// ---------------- fp16 GEMM: C = A*B + bias, B pre-packed [n][kp] ----------------
// BM=BN=128, BK=32 (2 k16 steps/tile), 256 threads (8 warps 2x4), warp 64x32.
// Tiles [row][kp] stride 20 (=4 mod 32): LDSM conflict-free.
#define GF_S 20
#define GF_BUF (128 * GF_S)

__global__ __launch_bounds__(256, 2) void gemm_f16(
    const float* __restrict__ A, const uint32_t* __restrict__ Bp,
    const float* __restrict__ bias, float* __restrict__ C,
    int lda, int ldc, int K, int nsplit, int gap)
{
    __shared__ uint32_t As[2][GF_BUF];
    __shared__ uint32_t Bs[2][GF_BUF];

    const int tid = threadIdx.x;
    const int bx = blockIdx.x, by = blockIdx.y;
    const int bcol = bx * 128 + ((bx >= nsplit) ? gap : 0);
    const int lane = tid & 31, wid = tid >> 5;
    const int g = lane >> 2, tg = lane & 3;
    const int wm = (wid >> 2) * 64, wn = (wid & 3) * 32;

    // ldmatrix per-lane row/chunk selectors
    const int la_row = lane & 15, la_chunk = (lane >> 4) * 4;        // A: .x4
    const int lb_row = lane & 7,  lb_chunk = ((lane >> 3) & 1) * 4;  // B: .x2

    const uint32_t as_base = (uint32_t)__cvta_generic_to_shared(As);
    const uint32_t bs_base = (uint32_t)__cvta_generic_to_shared(Bs);

    const int arow = tid >> 1, akb = (tid & 1) * 16;
    const int brow = tid >> 1, bkp = (tid & 1) * 8;
    const float*    Ap  = A  + (size_t)(by * 128 + arow) * lda + akb;
    const uint32_t* Bpp = Bp + (size_t)(bx * 128 + brow) * 512 + bkp;

    float acc[4][4][4];
    #pragma unroll
    for (int mt = 0; mt < 4; mt++)
        #pragma unroll
        for (int nt = 0; nt < 4; nt++)
            #pragma unroll
            for (int i = 0; i < 4; i++) acc[mt][nt][i] = 0.0f;

    float4 pa[4];
    uint4  pbv[2];
    #pragma unroll
    for (int q = 0; q < 4; q++) pa[q] = *(const float4*)(Ap + q * 4);
    pbv[0] = *(const uint4*)(Bpp);
    pbv[1] = *(const uint4*)(Bpp + 4);

    const int ntiles = K >> 5;
    int buf = 0;
    {
        uint4 ua0 = make_uint4(pack_h2(pa[0].x, pa[0].y), pack_h2(pa[0].z, pa[0].w),
                               pack_h2(pa[1].x, pa[1].y), pack_h2(pa[1].z, pa[1].w));
        uint4 ua1 = make_uint4(pack_h2(pa[2].x, pa[2].y), pack_h2(pa[2].z, pa[2].w),
                               pack_h2(pa[3].x, pa[3].y), pack_h2(pa[3].z, pa[3].w));
        *(uint4*)&As[0][arow * GF_S + akb / 2]     = ua0;
        *(uint4*)&As[0][arow * GF_S + akb / 2 + 4] = ua1;
        *(uint4*)&Bs[0][brow * GF_S + bkp]     = pbv[0];
        *(uint4*)&Bs[0][brow * GF_S + bkp + 4] = pbv[1];
    }
    __syncthreads();

    for (int t = 0; t < ntiles; ++t) {
        if (t + 1 < ntiles) {
            #pragma unroll
            for (int q = 0; q < 4; q++)
                pa[q] = *(const float4*)(Ap + (t + 1) * 32 + q * 4);
            pbv[0] = *(const uint4*)(Bpp + (t + 1) * 16);
            pbv[1] = *(const uint4*)(Bpp + (t + 1) * 16 + 4);
        }

        const uint32_t as0 = as_base + (buf * GF_BUF) * 4;
        const uint32_t bs0 = bs_base + (buf * GF_BUF) * 4;

        #pragma unroll
        for (int ks = 0; ks < 2; ++ks) {
            const int kb = ks * 8;
            uint32_t af[4][4], bf[4][2];
            #pragma unroll
            for (int mt = 0; mt < 4; mt++)
                ldsm_x4(af[mt], as0 + ((wm + mt * 16 + la_row) * GF_S + kb + la_chunk) * 4);
            #pragma unroll
            for (int nt = 0; nt < 4; nt++)
                ldsm_x2(bf[nt], bs0 + ((wn + nt * 8 + lb_row) * GF_S + kb + lb_chunk) * 4);
            #pragma unroll
            for (int mt = 0; mt < 4; mt++)
                #pragma unroll
                for (int nt = 0; nt < 4; nt++)
                    mma16f(acc[mt][nt], af[mt], bf[nt]);
        }

        if (t + 1 < ntiles) {
            const int nb = buf ^ 1;
            uint4 ua0 = make_uint4(pack_h2(pa[0].x, pa[0].y), pack_h2(pa[0].z, pa[0].w),
                                   pack_h2(pa[1].x, pa[1].y), pack_h2(pa[1].z, pa[1].w));
            uint4 ua1 = make_uint4(pack_h2(pa[2].x, pa[2].y), pack_h2(pa[2].z, pa[2].w),
                                   pack_h2(pa[3].x, pa[3].y), pack_h2(pa[3].z, pa[3].w));
            __syncthreads();
            *(uint4*)&As[nb][arow * GF_S + akb / 2]     = ua0;
            *(uint4*)&As[nb][arow * GF_S + akb / 2 + 4] = ua1;
            *(uint4*)&Bs[nb][brow * GF_S + bkp]     = pbv[0];
            *(uint4*)&Bs[nb][brow * GF_S + bkp + 4] = pbv[1];
            __syncthreads();
            buf = nb;
        }
    }

    #pragma unroll
    for (int mt = 0; mt < 4; mt++) {
        #pragma unroll
        for (int nt = 0; nt < 4; nt++) {
            const int col = bcol + wn + nt * 8 + 2 * tg;
            const float bv0 = bias[col], bv1 = bias[col + 1];
            const int row0 = by * 128 + wm + mt * 16 + g;
            float2 v0 = make_float2(acc[mt][nt][0] + bv0, acc[mt][nt][1] + bv1);
            float2 v1 = make_float2(acc[mt][nt][2] + bv0, acc[mt][nt][3] + bv1);
            *(float2*)(C + (size_t)row0 * ldc + col)       = v0;
            *(float2*)(C + (size_t)(row0 + 8) * ldc + col) = v1;
        }
    }
}

// ---------------- bf16x3 GEMM for the K section (ldmatrix fragments) ----------------
// Stride 12 words: rows land in distinct 4-word bank groups -> LDSM conflict-free.
#define G3_S 12
#define G3_BUF (128 * G3_S)
#define G3_SMEM_BYTES (8 * G3_BUF * 4)

__global__ __launch_bounds__(256, 2) void gemm_bf16k(
    const float* __restrict__ A, const uint32_t* __restrict__ Bhg,
    const uint32_t* __restrict__ Blg, const float* __restrict__ bias,
    float* __restrict__ C, int lda, int ldc, int K)
{
    extern __shared__ uint32_t s3[];
    uint32_t* Ah = s3;
    uint32_t* Al = Ah + 2 * G3_BUF;
    uint32_t* Bh = Al + 2 * G3_BUF;
    uint32_t* Bl = Bh + 2 * G3_BUF;

    const int tid = threadIdx.x;
    const int bx = blockIdx.x, by = blockIdx.y;
    const int lane = tid & 31, wid = tid >> 5;
    const int g = lane >> 2, tg = lane & 3;
    const int wm = (wid >> 2) * 64, wn = (wid & 3) * 32;

    const int la_row = lane & 15, la_chunk = (lane >> 4) * 4;
    const int lb_row = lane & 7,  lb_chunk = ((lane >> 3) & 1) * 4;

    const uint32_t ah_base = (uint32_t)__cvta_generic_to_shared(Ah);
    const uint32_t al_base = (uint32_t)__cvta_generic_to_shared(Al);
    const uint32_t bh_base = (uint32_t)__cvta_generic_to_shared(Bh);
    const uint32_t bl_base = (uint32_t)__cvta_generic_to_shared(Bl);

    const int arow = tid >> 1, akb = (tid & 1) * 8;
    const int brow = tid >> 1, bkp = (tid & 1) * 4;
    const float*    Ap  = A + (size_t)(by * 128 + arow) * lda + akb;
    const uint32_t* Bhp = Bhg + (size_t)(bx * 128 + brow) * 512 + bkp;
    const uint32_t* Blp = Blg + (size_t)(bx * 128 + brow) * 512 + bkp;

    float acc[4][4][4];
    #pragma unroll
    for (int mt = 0; mt < 4; mt++)
        #pragma unroll
        for (int nt = 0; nt < 4; nt++)
            #pragma unroll
            for (int i = 0; i < 4; i++) acc[mt][nt][i] = 0.0f;

    float4 pa0 = *(const float4*)(Ap);
    float4 pa1 = *(const float4*)(Ap + 4);
    uint4  pbh = *(const uint4*)(Bhp);
    uint4  pbl = *(const uint4*)(Blp);

    const int ntiles = K >> 4;
    int buf = 0;
    {
        float hv[8], lv[8];
        float src[8] = {pa0.x, pa0.y, pa0.z, pa0.w, pa1.x, pa1.y, pa1.z, pa1.w};
        #pragma unroll
        for (int j = 0; j < 8; j++) split_bf(src[j], hv[j], lv[j]);
        uint4 uh = make_uint4(pack_bf2(hv[0], hv[1]), pack_bf2(hv[2], hv[3]),
                              pack_bf2(hv[4], hv[5]), pack_bf2(hv[6], hv[7]));
        uint4 ul = make_uint4(pack_bf2(lv[0], lv[1]), pack_bf2(lv[2], lv[3]),
                              pack_bf2(lv[4], lv[5]), pack_bf2(lv[6], lv[7]));
        *(uint4*)&Ah[arow * G3_S + akb / 2] = uh;
        *(uint4*)&Al[arow * G3_S + akb / 2] = ul;
        *(uint4*)&Bh[brow * G3_S + bkp] = pbh;
        *(uint4*)&Bl[brow * G3_S + bkp] = pbl;
    }
    __syncthreads();

    for (int t = 0; t < ntiles; ++t) {
        if (t + 1 < ntiles) {
            pa0 = *(const float4*)(Ap + (t + 1) * 16);
            pa1 = *(const float4*)(Ap + (t + 1) * 16 + 4);
            pbh = *(const uint4*)(Bhp + (t + 1) * 8);
            pbl = *(const uint4*)(Blp + (t + 1) * 8);
        }

        const uint32_t ah0 = ah_base + (buf * G3_BUF) * 4;
        const uint32_t al0 = al_base + (buf * G3_BUF) * 4;
        const uint32_t bh0 = bh_base + (buf * G3_BUF) * 4;
        const uint32_t bl0 = bl_base + (buf * G3_BUF) * 4;

        uint32_t afh[4][4], afl[4][4], bfh[4][2], bfl[4][2];
        #pragma unroll
        for (int mt = 0; mt < 4; mt++) {
            const uint32_t off = ((wm + mt * 16 + la_row) * G3_S + la_chunk) * 4;
            ldsm_x4(afh[mt], ah0 + off);
            ldsm_x4(afl[mt], al0 + off);
        }
        #pragma unroll
        for (int nt = 0; nt < 4; nt++) {
            const uint32_t off = ((wn + nt * 8 + lb_row) * G3_S + lb_chunk) * 4;
            ldsm_x2(bfh[nt], bh0 + off);
            ldsm_x2(bfl[nt], bl0 + off);
        }
        #pragma unroll
        for (int mt = 0; mt < 4; mt++)
            #pragma unroll
            for (int nt = 0; nt < 4; nt++) {
                mma16bf(acc[mt][nt], afh[mt], bfh[nt]);
                mma16bf(acc[mt][nt], afh[mt], bfl[nt]);
                mma16bf(acc[mt][nt], afl[mt], bfh[nt]);
            }

        if (t + 1 < ntiles) {
            const int nb = buf ^ 1;
            float hv[8], lv[8];
            float src[8] = {pa0.x, pa0.y, pa0.z, pa0.w, pa1.x, pa1.y, pa1.z, pa1.w};
            #pragma unroll
            for (int j = 0; j < 8; j++) split_bf(src[j], hv[j], lv[j]);
            uint4 uh = make_uint4(pack_bf2(hv[0], hv[1]), pack_bf2(hv[2], hv[3]),
                                  pack_bf2(hv[4], hv[5]), pack_bf2(hv[6], hv[7]));
            uint4 ul = make_uint4(pack_bf2(lv[0], lv[1]), pack_bf2(lv[2], lv[3]),
                                  pack_bf2(lv[4], lv[5]), pack_bf2(lv[6], lv[7]));
            __syncthreads();
            *(uint4*)&Ah[nb * G3_BUF + arow * G3_S + akb / 2] = uh;
            *(uint4*)&Al[nb * G3_BUF + arow * G3_S + akb / 2] = ul;
            *(uint4*)&Bh[nb * G3_BUF + brow * G3_S + bkp] = pbh;
            *(uint4*)&Bl[nb * G3_BUF + brow * G3_S + bkp] = pbl;
            __syncthreads();
            buf = nb;
        }
    }

    #pragma unroll
    for (int mt = 0; mt < 4; mt++) {
        #pragma unroll
        for (int nt = 0; nt < 4; nt++) {
            const int coll = bx * 128 + wn + nt * 8 + 2 * tg;
            const float bv0 = bias[coll], bv1 = bias[coll + 1];
            const int row0 = by * 128 + wm + mt * 16 + g;
            const int col = EMB + coll;
            float2 v0 = make_float2(acc[mt][nt][0] + bv0, acc[mt][nt][1] + bv1);
            float2 v1 = make_float2(acc[mt][nt][2] + bv0, acc[mt][nt][3] + bv1);
            *(float2*)(C + (size_t)row0 * ldc + col)       = v0;
            *(float2*)(C + (size_t)(row0 + 8) * ldc + col) = v1;
        }
    }
}

// ---------------- Flash attention: all-fp16 mma + ldmatrix, fused KIVI quant ----------------
#define SQH 36
#define ATT_FLOATS (128 * SQH + 64 * SQH + 128 * SQH + 64 * SQH + 64)

__global__ __launch_bounds__(256, 2) void attn_f16(
    const float* __restrict__ qkv, const float* __restrict__ mask,
    float* __restrict__ out)
{
    extern __shared__ uint32_t smu[];
    uint32_t* Qs = smu;                  // [128][36] q pairs
    uint32_t* Ks = Qs + 128 * SQH;       // [64][36]  k pairs (dequantized)
    uint32_t* Ps = Ks + 64 * SQH;        // [128][36] p pairs
    uint32_t* Vt = Ps + 128 * SQH;       // [64][36]  v^T: [dim][keypair]
    float*    Ms = (float*)(Vt + 64 * SQH);

    const int tid = threadIdx.x, lane = tid & 31, wid = tid >> 5;
    const int g = lane >> 2, tg = lane & 3;
    const int m0 = wid * 16;

    const int la_row = lane & 15, la_chunk = (lane >> 4) * 4;
    const int lb_row = lane & 7,  lb_chunk = ((lane >> 3) & 1) * 4;

    const uint32_t qs_base = (uint32_t)__cvta_generic_to_shared(Qs);
    const uint32_t ks_base = (uint32_t)__cvta_generic_to_shared(Ks);
    const uint32_t ps_base = (uint32_t)__cvta_generic_to_shared(Ps);
    const uint32_t vt_base = (uint32_t)__cvta_generic_to_shared(Vt);

    const int bid = blockIdx.x;
    const int qt = bid & 7;
    const int h  = (bid >> 3) & 15;
    const int b  = bid >> 7;

    const size_t qbase = ((size_t)(b * S_LEN) + qt * 128) * (3 * EMB) + h * HD;
    const size_t kbase = ((size_t)(b * S_LEN)) * (3 * EMB) + EMB + h * HD;
    const size_t vbase = ((size_t)(b * S_LEN)) * (3 * EMB) + 2 * EMB + h * HD;
    const float* mp = mask + b * S_LEN;

    // load Q tile (128x64) as packed fp16 pairs
    #pragma unroll
    for (int i = 0; i < 8; i++) {
        int f = tid + 256 * i;
        int row = f >> 4, d4 = (f & 15) * 4;
        float4 v = *(const float4*)(qkv + qbase + (size_t)row * (3 * EMB) + d4);
        uint2 u = make_uint2(pack_h2(v.x, v.y), pack_h2(v.z, v.w));
        *(uint2*)&Qs[row * SQH + d4 / 2] = u;
    }

    float m_i[2] = {-INFINITY, -INFINITY}, l_i[2] = {0.0f, 0.0f};
    float oa[8][4];
    #pragma unroll
    for (int nt = 0; nt < 8; nt++)
        #pragma unroll
        for (int i = 0; i < 4; i++) oa[nt][i] = 0.0f;

    for (int kt = 0; kt < S_LEN / 64; ++kt) {
        // K tile: fused KIVI quant, packed fp16 [row][kp]
        #pragma unroll
        for (int i = 0; i < 4; i++) {
            int f = tid + 256 * i;
            int row = f >> 4, d4 = (f & 15) * 4;
            int key = (kt << 6) + row;
            float4 kv = *(const float4*)(qkv + kbase + (size_t)key * (3 * EMB) + d4);
            float ma = fmaxf(fmaxf(fabsf(kv.x), fabsf(kv.y)),
                             fmaxf(fabsf(kv.z), fabsf(kv.w)));
            float scale = ma * (1.0f / 1.5f);
            float safe = (scale == 0.0f) ? 1.0f : scale;
            float cx = fminf(fmaxf(rintf(kv.x / safe + 1.5f), 0.0f), 3.0f);
            float cy = fminf(fmaxf(rintf(kv.y / safe + 1.5f), 0.0f), 3.0f);
            float cz = fminf(fmaxf(rintf(kv.z / safe + 1.5f), 0.0f), 3.0f);
            float cw = fminf(fmaxf(rintf(kv.w / safe + 1.5f), 0.0f), 3.0f);
            uint2 uk = make_uint2(pack_h2((cx - 1.5f) * scale, (cy - 1.5f) * scale),
                                  pack_h2((cz - 1.5f) * scale, (cw - 1.5f) * scale));
            *(uint2*)&Ks[row * SQH + d4 / 2] = uk;
        }
        // V tile transposed: Vt[dim][kp] = {V[2kp][dim], V[2kp+1][dim]}
        #pragma unroll
        for (int i = 0; i < 8; i++) {
            int f = tid + 256 * i;
            int dim = f & 63, kp = f >> 6;
            int key = (kt << 6) + 2 * kp;
            float v0 = qkv[vbase + (size_t)key * (3 * EMB) + dim];
            float v1 = qkv[vbase + (size_t)(key + 1) * (3 * EMB) + dim];
            Vt[dim * SQH + kp] = pack_h2(v0, v1);
        }
        if (tid < 64) Ms[tid] = mp[(kt << 6) + tid];
        __syncthreads();

        // ---- S = Q K^T : m=16, n=64 (8 nt), k=64 (4 k16), fp16 + ldmatrix ----
        float sacc[8][4];
        #pragma unroll
        for (int nt = 0; nt < 8; nt++)
            #pragma unroll
            for (int i = 0; i < 4; i++) sacc[nt][i] = 0.0f;

        #pragma unroll
        for (int ks = 0; ks < 4; ++ks) {
            const int kb = ks * 8;
            uint32_t af[4];
            ldsm_x4(af, qs_base + ((m0 + la_row) * SQH + kb + la_chunk) * 4);
            #pragma unroll
            for (int nt = 0; nt < 8; ++nt) {
                uint32_t bf[2];
                ldsm_x2(bf, ks_base + ((nt * 8 + lb_row) * SQH + kb + lb_chunk) * 4);
                mma16f(sacc[nt], af, bf);
            }
        }

        // ---- online softmax; P written as packed fp16 pairs ----
        #pragma unroll
        for (int rr = 0; rr < 2; ++rr) {
            float mx = -INFINITY;
            #pragma unroll
            for (int nt = 0; nt < 8; nt++) {
                const int c0 = nt * 8 + 2 * tg;
                float s0 = (sacc[nt][rr * 2 + 0] + Ms[c0]) * 0.125f;
                float s1 = (sacc[nt][rr * 2 + 1] + Ms[c0 + 1]) * 0.125f;
                sacc[nt][rr * 2 + 0] = s0;
                sacc[nt][rr * 2 + 1] = s1;
                mx = fmaxf(mx, fmaxf(s0, s1));
            }
            mx = fmaxf(mx, __shfl_xor_sync(0xffffffffu, mx, 1));
            mx = fmaxf(mx, __shfl_xor_sync(0xffffffffu, mx, 2));
            const float mnew = fmaxf(m_i[rr], mx);
            const float alpha = __expf(m_i[rr] - mnew);
            float rs = 0.0f;
            const int row = m0 + g + rr * 8;
            #pragma unroll
            for (int nt = 0; nt < 8; nt++) {
                float p0 = __expf(sacc[nt][rr * 2 + 0] - mnew);
                float p1 = __expf(sacc[nt][rr * 2 + 1] - mnew);
                rs += p0 + p1;
                Ps[row * SQH + nt * 4 + tg] = pack_h2(p0, p1);
            }
            rs += __shfl_xor_sync(0xffffffffu, rs, 1);
            rs += __shfl_xor_sync(0xffffffffu, rs, 2);
            l_i[rr] = l_i[rr] * alpha + rs;
            m_i[rr] = mnew;
            #pragma unroll
            for (int nt = 0; nt < 8; nt++) {
                oa[nt][rr * 2 + 0] *= alpha;
                oa[nt][rr * 2 + 1] *= alpha;
            }
        }
        __syncwarp();   // P rows are warp-private

        // ---- O += P V : fp16 + ldmatrix, k=64 keys (4 k16), n=64 dims (8 nt) ----
        #pragma unroll
        for (int ks = 0; ks < 4; ++ks) {
            const int kb = ks * 8;
            uint32_t ap[4];
            ldsm_x4(ap, ps_base + ((m0 + la_row) * SQH + kb + la_chunk) * 4);
            #pragma unroll
            for (int nt = 0; nt < 8; ++nt) {
                uint32_t bf[2];
                ldsm_x2(bf, vt_base + ((nt * 8 + lb_row) * SQH + kb + lb_chunk) * 4);
                mma16f(oa[nt], ap, bf);
            }
        }
        __syncthreads();
    }

    #pragma unroll
    for (int rr = 0; rr < 2; ++rr) {
        const float inv = 1.0f / l_i[rr];
        const int srow = qt * 128 + m0 + g + rr * 8;
        float* op = out + ((size_t)(b * S_LEN + srow)) * EMB + h * HD;
        #pragma unroll
        for (int nt = 0; nt < 8; nt++) {
            float2 v = make_float2(oa[nt][rr * 2 + 0] * inv, oa[nt][rr * 2 + 1] * inv);
            *(float2*)(op + nt * 8 + 2 * tg) = v;
        }
    }
}

// ---------------- launch ----------------
extern "C" void kernel_launch(void* const* d_in, const int* in_sizes, int n_in,
                              void* d_out, int out_size)
{
    const float* hidden = (const float*)d_in[0];
    const float* mask   = (const float*)d_in[1];
    const float* w_attn = (const float*)d_in[2];
    const float* b_attn = (const float*)d_in[3];
    const float* w_proj = (const float*)d_in[4];
    const float* b_proj = (const float*)d_in[5];
    float* out = (float*)d_out;

    float *qkv, *attn;
    uint32_t *wkh, *wkl, *wqv, *wp;
    cudaGetSymbolAddress((void**)&qkv,  g_qkv);
    cudaGetSymbolAddress((void**)&attn, g_attn);
    cudaGetSymbolAddress((void**)&wkh,  g_wkh);
    cudaGetSymbolAddress((void**)&wkl,  g_wkl);
    cudaGetSymbolAddress((void**)&wqv,  g_wqv);
    cudaGetSymbolAddress((void**)&wp,   g_wp);

    const int att_smem = ATT_FLOATS * (int)sizeof(float);
    cudaFuncSetAttribute(attn_f16,
                         cudaFuncAttributeMaxDynamicSharedMemorySize, att_smem);
    cudaFuncSetAttribute(gemm_bf16k,
                         cudaFuncAttributeMaxDynamicSharedMemorySize, G3_SMEM_BYTES);

    // 0) prep packed weights
    prep_wk<<<EMB * (EMB / 2) / 256, 256>>>(w_attn, wkh, wkl);
    prep_pack_f16<<<2048 * 512 / 256, 256>>>(w_attn, 3 * EMB, 2047, 11, 1024, wqv);
    prep_pack_f16<<<1024 * 512 / 256, 256>>>(w_proj, EMB, 1023, 10, 4096, wp);

    // 1) Q and V sections, fp16 (bx>=8 -> V cols at [2048,3072))
    dim3 gqv(16, BATCH * S_LEN / 128);
    gemm_f16<<<gqv, 256>>>(hidden, wqv, b_attn, qkv,
                           EMB, 3 * EMB, EMB, 8, 1024);

    // 2) K section, bf16x3
    dim3 gk(EMB / 128, BATCH * S_LEN / 128);
    gemm_bf16k<<<gk, 256, G3_SMEM_BYTES>>>(hidden, wkh, wkl, b_attn + EMB,
                                           qkv, EMB, 3 * EMB, EMB);

    // 3) attention (all-fp16 mma + ldmatrix, fused KIVI quant)
    attn_f16<<<BATCH * NH * (S_LEN / 128), 256, att_smem>>>(qkv, mask, attn);

    // 4) out projection, fp16
    dim3 gp(EMB / 128, BATCH * S_LEN / 128);
    gemm_f16<<<gp, 256>>>(attn, wp, b_proj, out,
                          EMB, EMB, EMB, 16, 0);
}

// round 11
// speedup vs baseline: 4.0078x; 1.0738x over previous
#include <cuda_runtime.h>
#include <cuda_bf16.h>
#include <cuda_fp16.h>
#include <math.h>
#include <stdint.h>

#define BATCH 4
#define S_LEN 1024
#define EMB   1024
#define NH    16
#define HD    64
#define NROWS (BATCH * S_LEN)

// ---------------- scratch (no allocations allowed) ----------------
__device__ uint32_t g_hf16[NROWS * 512];        // hidden fp16 pairs [m][kp]
__device__ uint32_t g_hbh [NROWS * 512];        // hidden bf16 hi    [m][kp]
__device__ uint32_t g_hbl [NROWS * 512];        // hidden bf16 lo    [m][kp]
__device__ uint32_t g_qvh [NROWS * 1024];       // Q|V fp16 pairs: [row][kp], Q kp<512, V kp>=512
__device__ float    g_kf32[NROWS * EMB];        // K section fp32 [row][1024]
__device__ uint32_t g_oh  [NROWS * 512];        // attention out fp16 pairs [row][kp]
__device__ uint32_t g_wkh [EMB * 512];          // Wk bf16 hi, [n][kp]
__device__ uint32_t g_wkl [EMB * 512];          // Wk bf16 lo, [n][kp]
__device__ uint32_t g_wqv [2048 * 512];         // Wq|Wv fp16, [n][kp]
__device__ uint32_t g_wp  [EMB * 512];          // Wproj fp16, [n][kp]

// ---------------- helpers ----------------
__device__ __forceinline__ void mma16bf(float* d, const uint32_t* a, const uint32_t* b) {
    asm volatile(
        "mma.sync.aligned.m16n8k16.row.col.f32.bf16.bf16.f32 "
        "{%0,%1,%2,%3}, {%4,%5,%6,%7}, {%8,%9}, {%0,%1,%2,%3};"
        : "+f"(d[0]), "+f"(d[1]), "+f"(d[2]), "+f"(d[3])
        : "r"(a[0]), "r"(a[1]), "r"(a[2]), "r"(a[3]), "r"(b[0]), "r"(b[1]));
}

__device__ __forceinline__ void mma16f(float* d, const uint32_t* a, const uint32_t* b) {
    asm volatile(
        "mma.sync.aligned.m16n8k16.row.col.f32.f16.f16.f32 "
        "{%0,%1,%2,%3}, {%4,%5,%6,%7}, {%8,%9}, {%0,%1,%2,%3};"
        : "+f"(d[0]), "+f"(d[1]), "+f"(d[2]), "+f"(d[3])
        : "r"(a[0]), "r"(a[1]), "r"(a[2]), "r"(a[3]), "r"(b[0]), "r"(b[1]));
}

__device__ __forceinline__ void ldsm_x4(uint32_t* r, uint32_t addr) {
    asm volatile("ldmatrix.sync.aligned.m8n8.x4.shared.b16 {%0,%1,%2,%3}, [%4];"
        : "=r"(r[0]), "=r"(r[1]), "=r"(r[2]), "=r"(r[3]) : "r"(addr));
}

__device__ __forceinline__ void ldsm_x2(uint32_t* r, uint32_t addr) {
    asm volatile("ldmatrix.sync.aligned.m8n8.x2.shared.b16 {%0,%1}, [%2];"
        : "=r"(r[0]), "=r"(r[1]) : "r"(addr));
}

__device__ __forceinline__ void ldsm_x2_trans(uint32_t* r, uint32_t addr) {
    asm volatile("ldmatrix.sync.aligned.m8n8.x2.trans.shared.b16 {%0,%1}, [%2];"
        : "=r"(r[0]), "=r"(r[1]) : "r"(addr));
}

__device__ __forceinline__ uint32_t pack_bf2(float x0, float x1) {
    __nv_bfloat162 p = __floats2bfloat162_rn(x0, x1);
    return *(uint32_t*)&p;
}

__device__ __forceinline__ uint32_t pack_h2(float x0, float x1) {
    __half2 p = __floats2half2_rn(x0, x1);
    return *(uint32_t*)&p;
}

__device__ __forceinline__ void split_bf(float x, float& h, float& l) {
    __nv_bfloat16 hb = __float2bfloat16_rn(x);
    h = __bfloat162float(hb);
    l = x - h;
}

// ---------------- prep: hidden -> fp16 pairs + bf16 hi/lo pairs ----------------
__global__ __launch_bounds__(256) void prep_hidden(
    const float* __restrict__ hid, uint32_t* __restrict__ hf,
    uint32_t* __restrict__ hh, uint32_t* __restrict__ hl)
{
    int idx = blockIdx.x * 256 + threadIdx.x;   // 0 .. NROWS*512-1
    int kp = idx & 511;
    int m  = idx >> 9;
    float2 v = *(const float2*)(hid + (size_t)m * EMB + 2 * kp);
    hf[idx] = pack_h2(v.x, v.y);
    float h0, l0, h1, l1;
    split_bf(v.x, h0, l0);
    split_bf(v.y, h1, l1);
    hh[idx] = pack_bf2(h0, h1);
    hl[idx] = pack_bf2(l0, l1);
}

// ---------------- prep: Wk -> packed bf16 hi/lo ----------------
__global__ __launch_bounds__(256) void prep_wk(
    const float* __restrict__ w, uint32_t* __restrict__ wh, uint32_t* __restrict__ wl)
{
    int idx = blockIdx.x * 256 + threadIdx.x;
    int n  = idx & 1023;
    int kp = idx >> 10;
    float x0 = w[(size_t)(2 * kp)     * (3 * EMB) + EMB + n];
    float x1 = w[(size_t)(2 * kp + 1) * (3 * EMB) + EMB + n];
    float h0, l0, h1, l1;
    split_bf(x0, h0, l0);
    split_bf(x1, h1, l1);
    wh[(size_t)n * 512 + kp] = pack_bf2(h0, h1);
    wl[(size_t)n * 512 + kp] = pack_bf2(l0, l1);
}

// ---------------- prep: pack a weight section to fp16 [n][kp] ----------------
__global__ __launch_bounds__(256) void prep_pack_f16(
    const float* __restrict__ w, int ldw, int nmask, int nshift, int nswitch,
    uint32_t* __restrict__ out)
{
    int idx = blockIdx.x * 256 + threadIdx.x;
    int n  = idx & nmask;
    int kp = idx >> nshift;
    int col = n + ((n >= nswitch) ? 1024 : 0);
    float x0 = w[(size_t)(2 * kp)     * ldw + col];
    float x1 = w[(size_t)(2 * kp + 1) * ldw + col];
    out[(size_t)n * 512 + kp] = pack_h2(x0, x1);
}

// ---------------- fp16 GEMM: A,B pre-packed [.][kp] ----------------
// BM=BN=128, BK=32 (2 k16/tile), 256 threads (8 warps 2x4), warp 64x32.
// pack_out=1: write fp16 pairs to Cp (QV); else fp32 to C (proj).
#define GF_S 20
#define GF_BUF (128 * GF_S)

__global__ __launch_bounds__(256, 2) void gemm_f16(
    const uint32_t* __restrict__ Apk, const uint32_t* __restrict__ Bp,
    const float* __restrict__ bias, float* __restrict__ C,
    uint32_t* __restrict__ Cp, int ldc, int K, int nsplit, int gap, int pack_out)
{
    __shared__ uint32_t As[2][GF_BUF];
    __shared__ uint32_t Bs[2][GF_BUF];

    const int tid = threadIdx.x;
    const int bx = blockIdx.x, by = blockIdx.y;
    const int bcol = bx * 128 + ((bx >= nsplit) ? gap : 0);
    const int lane = tid & 31, wid = tid >> 5;
    const int g = lane >> 2, tg = lane & 3;
    const int wm = (wid >> 2) * 64, wn = (wid & 3) * 32;

    const int la_row = lane & 15, la_chunk = (lane >> 4) * 4;
    const int lb_row = lane & 7,  lb_chunk = ((lane >> 3) & 1) * 4;

    const uint32_t as_base = (uint32_t)__cvta_generic_to_shared(As);
    const uint32_t bs_base = (uint32_t)__cvta_generic_to_shared(Bs);

    const int arow = tid >> 1, akp = (tid & 1) * 8;
    const uint32_t* App = Apk + (size_t)(by * 128 + arow) * 512 + akp;
    const uint32_t* Bpp = Bp  + (size_t)(bx * 128 + arow) * 512 + akp;

    float acc[4][4][4];
    #pragma unroll
    for (int mt = 0; mt < 4; mt++)
        #pragma unroll
        for (int nt = 0; nt < 4; nt++)
            #pragma unroll
            for (int i = 0; i < 4; i++) acc[mt][nt][i] = 0.0f;

    uint4 pav[2], pbv[2];
    pav[0] = *(const uint4*)(App);
    pav[1] = *(const uint4*)(App + 4);
    pbv[0] = *(const uint4*)(Bpp);
    pbv[1] = *(const uint4*)(Bpp + 4);

    const int ntiles = K >> 5;
    int buf = 0;
    {
        *(uint4*)&As[0][arow * GF_S + akp]     = pav[0];
        *(uint4*)&As[0][arow * GF_S + akp + 4] = pav[1];
        *(uint4*)&Bs[0][arow * GF_S + akp]     = pbv[0];
        *(uint4*)&Bs[0][arow * GF_S + akp + 4] = pbv[1];
    }
    __syncthreads();

    for (int t = 0; t < ntiles; ++t) {
        if (t + 1 < ntiles) {
            pav[0] = *(const uint4*)(App + (t + 1) * 16);
            pav[1] = *(const uint4*)(App + (t + 1) * 16 + 4);
            pbv[0] = *(const uint4*)(Bpp + (t + 1) * 16);
            pbv[1] = *(const uint4*)(Bpp + (t + 1) * 16 + 4);
        }

        const uint32_t as0 = as_base + (buf * GF_BUF) * 4;
        const uint32_t bs0 = bs_base + (buf * GF_BUF) * 4;

        #pragma unroll
        for (int ks = 0; ks < 2; ++ks) {
            const int kb = ks * 8;
            uint32_t af[4][4], bf[4][2];
            #pragma unroll
            for (int mt = 0; mt < 4; mt++)
                ldsm_x4(af[mt], as0 + ((wm + mt * 16 + la_row) * GF_S + kb + la_chunk) * 4);
            #pragma unroll
            for (int nt = 0; nt < 4; nt++)
                ldsm_x2(bf[nt], bs0 + ((wn + nt * 8 + lb_row) * GF_S + kb + lb_chunk) * 4);
            #pragma unroll
            for (int mt = 0; mt < 4; mt++)
                #pragma unroll
                for (int nt = 0; nt < 4; nt++)
                    mma16f(acc[mt][nt], af[mt], bf[nt]);
        }

        if (t + 1 < ntiles) {
            const int nb = buf ^ 1;
            __syncthreads();
            *(uint4*)&As[nb][arow * GF_S + akp]     = pav[0];
            *(uint4*)&As[nb][arow * GF_S + akp + 4] = pav[1];
            *(uint4*)&Bs[nb][arow * GF_S + akp]     = pbv[0];
            *(uint4*)&Bs[nb][arow * GF_S + akp + 4] = pbv[1];
            __syncthreads();
            buf = nb;
        }
    }

    #pragma unroll
    for (int mt = 0; mt < 4; mt++) {
        #pragma unroll
        for (int nt = 0; nt < 4; nt++) {
            const int col = bcol + wn + nt * 8 + 2 * tg;
            const float bv0 = bias[col], bv1 = bias[col + 1];
            const int row0 = by * 128 + wm + mt * 16 + g;
            float o00 = acc[mt][nt][0] + bv0, o01 = acc[mt][nt][1] + bv1;
            float o10 = acc[mt][nt][2] + bv0, o11 = acc[mt][nt][3] + bv1;
            if (pack_out) {
                // Q kp = col/2 (<512); V (col>=2048) kp = 512 + (col-2048)/2
                const int kp = (col >= 2048) ? (512 + ((col - 2048) >> 1)) : (col >> 1);
                Cp[(size_t)row0 * 1024 + kp]       = pack_h2(o00, o01);
                Cp[(size_t)(row0 + 8) * 1024 + kp] = pack_h2(o10, o11);
            } else {
                *(float2*)(C + (size_t)row0 * ldc + col)       = make_float2(o00, o01);
                *(float2*)(C + (size_t)(row0 + 8) * ldc + col) = make_float2(o10, o11);
            }
        }
    }
}

// ---------------- bf16x3 GEMM for K: A,B pre-split/packed ----------------
#define G3_S 12
#define G3_BUF (128 * G3_S)
#define G3_SMEM_BYTES (8 * G3_BUF * 4)

__global__ __launch_bounds__(256, 2) void gemm_bf16k(
    const uint32_t* __restrict__ Ahg, const uint32_t* __restrict__ Alg,
    const uint32_t* __restrict__ Bhg, const uint32_t* __restrict__ Blg,
    const float* __restrict__ bias, float* __restrict__ C, int ldc, int K)
{
    extern __shared__ uint32_t s3[];
    uint32_t* Ah = s3;
    uint32_t* Al = Ah + 2 * G3_BUF;
    uint32_t* Bh = Al + 2 * G3_BUF;
    uint32_t* Bl = Bh + 2 * G3_BUF;

    const int tid = threadIdx.x;
    const int bx = blockIdx.x, by = blockIdx.y;
    const int lane = tid & 31, wid = tid >> 5;
    const int g = lane >> 2, tg = lane & 3;
    const int wm = (wid >> 2) * 64, wn = (wid & 3) * 32;

    const int la_row = lane & 15, la_chunk = (lane >> 4) * 4;
    const int lb_row = lane & 7,  lb_chunk = ((lane >> 3) & 1) * 4;

    const uint32_t ah_base = (uint32_t)__cvta_generic_to_shared(Ah);
    const uint32_t al_base = (uint32_t)__cvta_generic_to_shared(Al);
    const uint32_t bh_base = (uint32_t)__cvta_generic_to_shared(Bh);
    const uint32_t bl_base = (uint32_t)__cvta_generic_to_shared(Bl);

    const int arow = tid >> 1, akp = (tid & 1) * 4;
    const uint32_t* Ahp = Ahg + (size_t)(by * 128 + arow) * 512 + akp;
    const uint32_t* Alp = Alg + (size_t)(by * 128 + arow) * 512 + akp;
    const uint32_t* Bhp = Bhg + (size_t)(bx * 128 + arow) * 512 + akp;
    const uint32_t* Blp = Blg + (size_t)(bx * 128 + arow) * 512 + akp;

    float acc[4][4][4];
    #pragma unroll
    for (int mt = 0; mt < 4; mt++)
        #pragma unroll
        for (int nt = 0; nt < 4; nt++)
            #pragma unroll
            for (int i = 0; i < 4; i++) acc[mt][nt][i] = 0.0f;

    uint4 pah = *(const uint4*)(Ahp);
    uint4 pal = *(const uint4*)(Alp);
    uint4 pbh = *(const uint4*)(Bhp);
    uint4 pbl = *(const uint4*)(Blp);

    const int ntiles = K >> 4;
    int buf = 0;
    {
        *(uint4*)&Ah[arow * G3_S + akp] = pah;
        *(uint4*)&Al[arow * G3_S + akp] = pal;
        *(uint4*)&Bh[arow * G3_S + akp] = pbh;
        *(uint4*)&Bl[arow * G3_S + akp] = pbl;
    }
    __syncthreads();

    for (int t = 0; t < ntiles; ++t) {
        if (t + 1 < ntiles) {
            pah = *(const uint4*)(Ahp + (t + 1) * 8);
            pal = *(const uint4*)(Alp + (t + 1) * 8);
            pbh = *(const uint4*)(Bhp + (t + 1) * 8);
            pbl = *(const uint4*)(Blp + (t + 1) * 8);
        }

        const uint32_t ah0 = ah_base + (buf * G3_BUF) * 4;
        const uint32_t al0 = al_base + (buf * G3_BUF) * 4;
        const uint32_t bh0 = bh_base + (buf * G3_BUF) * 4;
        const uint32_t bl0 = bl_base + (buf * G3_BUF) * 4;

        uint32_t afh[4][4], afl[4][4], bfh[4][2], bfl[4][2];
        #pragma unroll
        for (int mt = 0; mt < 4; mt++) {
            const uint32_t off = ((wm + mt * 16 + la_row) * G3_S + la_chunk) * 4;
            ldsm_x4(afh[mt], ah0 + off);
            ldsm_x4(afl[mt], al0 + off);
        }
        #pragma unroll
        for (int nt = 0; nt < 4; nt++) {
            const uint32_t off = ((wn + nt * 8 + lb_row) * G3_S + lb_chunk) * 4;
            ldsm_x2(bfh[nt], bh0 + off);
            ldsm_x2(bfl[nt], bl0 + off);
        }
        #pragma unroll
        for (int mt = 0; mt < 4; mt++)
            #pragma unroll
            for (int nt = 0; nt < 4; nt++) {
                mma16bf(acc[mt][nt], afh[mt], bfh[nt]);
                mma16bf(acc[mt][nt], afh[mt], bfl[nt]);
                mma16bf(acc[mt][nt], afl[mt], bfh[nt]);
            }

        if (t + 1 < ntiles) {
            const int nb = buf ^ 1;
            __syncthreads();
            *(uint4*)&Ah[nb * G3_BUF + arow * G3_S + akp] = pah;
            *(uint4*)&Al[nb * G3_BUF + arow * G3_S + akp] = pal;
            *(uint4*)&Bh[nb * G3_BUF + arow * G3_S + akp] = pbh;
            *(uint4*)&Bl[nb * G3_BUF + arow * G3_S + akp] = pbl;
            __syncthreads();
            buf = nb;
        }
    }

    #pragma unroll
    for (int mt = 0; mt < 4; mt++) {
        #pragma unroll
        for (int nt = 0; nt < 4; nt++) {
            const int col = bx * 128 + wn + nt * 8 + 2 * tg;
            const float bv0 = bias[col], bv1 = bias[col + 1];
            const int row0 = by * 128 + wm + mt * 16 + g;
            float2 v0 = make_float2(acc[mt][nt][0] + bv0, acc[mt][nt][1] + bv1);
            float2 v1 = make_float2(acc[mt][nt][2] + bv0, acc[mt][nt][3] + bv1);
            *(float2*)(C + (size_t)row0 * ldc + col)       = v0;
            *(float2*)(C + (size_t)(row0 + 8) * ldc + col) = v1;
        }
    }
}

// ---------------- Flash attention: fp16 + ldmatrix(.trans), fused KIVI quant ----------------
// Q from packed qvh; K from fp32 kf32 (quantized on load); V packed row-major,
// PV B-fragment via ldmatrix.trans. Output packed fp16 [row][kp].
#define SQH 36
#define ATT_FLOATS (128 * SQH + 64 * SQH + 128 * SQH + 64 * SQH + 64)

__global__ __launch_bounds__(256, 2) void attn_f16(
    const uint32_t* __restrict__ qvh, const float* __restrict__ kf32,
    const float* __restrict__ mask, uint32_t* __restrict__ outp)
{
    extern __shared__ uint32_t smu[];
    uint32_t* Qs = smu;                  // [128][36] q pairs
    uint32_t* Ks = Qs + 128 * SQH;       // [64][36]  k pairs (dequantized)
    uint32_t* Ps = Ks + 64 * SQH;        // [128][36] p pairs
    uint32_t* Vs = Ps + 128 * SQH;       // [64][36]  v pairs row-major [key][dimpair]
    float*    Ms = (float*)(Vs + 64 * SQH);

    const int tid = threadIdx.x, lane = tid & 31, wid = tid >> 5;
    const int g = lane >> 2, tg = lane & 3;
    const int m0 = wid * 16;

    const int la_row = lane & 15, la_chunk = (lane >> 4) * 4;
    const int lb_row = lane & 7,  lb_chunk = ((lane >> 3) & 1) * 4;
    const int lt_row = lane & 15;   // trans: 16 key rows

    const uint32_t qs_base = (uint32_t)__cvta_generic_to_shared(Qs);
    const uint32_t ks_base = (uint32_t)__cvta_generic_to_shared(Ks);
    const uint32_t ps_base = (uint32_t)__cvta_generic_to_shared(Ps);
    const uint32_t vs_base = (uint32_t)__cvta_generic_to_shared(Vs);

    const int bid = blockIdx.x;
    const int qt = bid & 7;
    const int h  = (bid >> 3) & 15;
    const int b  = bid >> 7;

    const uint32_t* qp = qvh + ((size_t)(b * S_LEN) + qt * 128) * 1024 + h * 32;
    const uint32_t* vp = qvh + ((size_t)(b * S_LEN)) * 1024 + 512 + h * 32;
    const float*    kp = kf32 + ((size_t)(b * S_LEN)) * EMB + h * HD;
    const float*    mp = mask + b * S_LEN;

    // load Q tile (128 rows x 32 words), direct copy
    #pragma unroll
    for (int i = 0; i < 4; i++) {
        int f = tid + 256 * i;
        int row = f >> 3, w4 = (f & 7) * 4;
        uint4 u = *(const uint4*)(qp + (size_t)row * 1024 + w4);
        *(uint4*)&Qs[row * SQH + w4] = u;
    }

    float m_i[2] = {-INFINITY, -INFINITY}, l_i[2] = {0.0f, 0.0f};
    float oa[8][4];
    #pragma unroll
    for (int nt = 0; nt < 8; nt++)
        #pragma unroll
        for (int i = 0; i < 4; i++) oa[nt][i] = 0.0f;

    for (int kt = 0; kt < S_LEN / 64; ++kt) {
        // K tile: fused KIVI quant from fp32, packed fp16 [row][kp]
        #pragma unroll
        for (int i = 0; i < 4; i++) {
            int f = tid + 256 * i;
            int row = f >> 4, d4 = (f & 15) * 4;
            int key = (kt << 6) + row;
            float4 kv = *(const float4*)(kp + (size_t)key * EMB + d4);
            float ma = fmaxf(fmaxf(fabsf(kv.x), fabsf(kv.y)),
                             fmaxf(fabsf(kv.z), fabsf(kv.w)));
            float scale = ma * (1.0f / 1.5f);
            float safe = (scale == 0.0f) ? 1.0f : scale;
            float cx = fminf(fmaxf(rintf(kv.x / safe + 1.5f), 0.0f), 3.0f);
            float cy = fminf(fmaxf(rintf(kv.y / safe + 1.5f), 0.0f), 3.0f);
            float cz = fminf(fmaxf(rintf(kv.z / safe + 1.5f), 0.0f), 3.0f);
            float cw = fminf(fmaxf(rintf(kv.w / safe + 1.5f), 0.0f), 3.0f);
            uint2 uk = make_uint2(pack_h2((cx - 1.5f) * scale, (cy - 1.5f) * scale),
                                  pack_h2((cz - 1.5f) * scale, (cw - 1.5f) * scale));
            *(uint2*)&Ks[row * SQH + d4 / 2] = uk;
        }
        // V tile: direct packed copy, row-major [key][dimpair]
        #pragma unroll
        for (int i = 0; i < 2; i++) {
            int f = tid + 256 * i;
            int row = f >> 3, w4 = (f & 7) * 4;
            int key = (kt << 6) + row;
            uint4 u = *(const uint4*)(vp + (size_t)key * 1024 + w4);
            *(uint4*)&Vs[row * SQH + w4] = u;
        }
        if (tid < 64) Ms[tid] = mp[(kt << 6) + tid];
        __syncthreads();

        // ---- S = Q K^T : m=16, n=64 (8 nt), k=64 (4 k16) ----
        float sacc[8][4];
        #pragma unroll
        for (int nt = 0; nt < 8; nt++)
            #pragma unroll
            for (int i = 0; i < 4; i++) sacc[nt][i] = 0.0f;

        #pragma unroll
        for (int ks = 0; ks < 4; ++ks) {
            const int kb = ks * 8;
            uint32_t af[4];
            ldsm_x4(af, qs_base + ((m0 + la_row) * SQH + kb + la_chunk) * 4);
            #pragma unroll
            for (int nt = 0; nt < 8; ++nt) {
                uint32_t bf[2];
                ldsm_x2(bf, ks_base + ((nt * 8 + lb_row) * SQH + kb + lb_chunk) * 4);
                mma16f(sacc[nt], af, bf);
            }
        }

        // ---- online softmax; P written as packed fp16 pairs ----
        #pragma unroll
        for (int rr = 0; rr < 2; ++rr) {
            float mx = -INFINITY;
            #pragma unroll
            for (int nt = 0; nt < 8; nt++) {
                const int c0 = nt * 8 + 2 * tg;
                float s0 = (sacc[nt][rr * 2 + 0] + Ms[c0]) * 0.125f;
                float s1 = (sacc[nt][rr * 2 + 1] + Ms[c0 + 1]) * 0.125f;
                sacc[nt][rr * 2 + 0] = s0;
                sacc[nt][rr * 2 + 1] = s1;
                mx = fmaxf(mx, fmaxf(s0, s1));
            }
            mx = fmaxf(mx, __shfl_xor_sync(0xffffffffu, mx, 1));
            mx = fmaxf(mx, __shfl_xor_sync(0xffffffffu, mx, 2));
            const float mnew = fmaxf(m_i[rr], mx);
            const float alpha = __expf(m_i[rr] - mnew);
            float rs = 0.0f;
            const int row = m0 + g + rr * 8;
            #pragma unroll
            for (int nt = 0; nt < 8; nt++) {
                float p0 = __expf(sacc[nt][rr * 2 + 0] - mnew);
                float p1 = __expf(sacc[nt][rr * 2 + 1] - mnew);
                rs += p0 + p1;
                Ps[row * SQH + nt * 4 + tg] = pack_h2(p0, p1);
            }
            rs += __shfl_xor_sync(0xffffffffu, rs, 1);
            rs += __shfl_xor_sync(0xffffffffu, rs, 2);
            l_i[rr] = l_i[rr] * alpha + rs;
            m_i[rr] = mnew;
            #pragma unroll
            for (int nt = 0; nt < 8; nt++) {
                oa[nt][rr * 2 + 0] *= alpha;
                oa[nt][rr * 2 + 1] *= alpha;
            }
        }
        __syncwarp();   // P rows are warp-private

        // ---- O += P V : B fragment via ldmatrix.trans on row-major V ----
        #pragma unroll
        for (int ks = 0; ks < 4; ++ks) {
            const int kb = ks * 8;
            uint32_t ap[4];
            ldsm_x4(ap, ps_base + ((m0 + la_row) * SQH + kb + la_chunk) * 4);
            #pragma unroll
            for (int nt = 0; nt < 8; ++nt) {
                uint32_t bf[2];
                ldsm_x2_trans(bf, vs_base + ((ks * 16 + lt_row) * SQH + nt * 4) * 4);
                mma16f(oa[nt], ap, bf);
            }
        }
        __syncthreads();
    }

    // ---- epilogue: packed fp16 output [row][kp] for the proj GEMM ----
    #pragma unroll
    for (int rr = 0; rr < 2; ++rr) {
        const float inv = 1.0f / l_i[rr];
        const int srow = qt * 128 + m0 + g + rr * 8;
        uint32_t* op = outp + ((size_t)(b * S_LEN + srow)) * 512 + h * 32;
        #pragma unroll
        for (int nt = 0; nt < 8; nt++)
            op[nt * 4 + tg] = pack_h2(oa[nt][rr * 2 + 0] * inv, oa[nt][rr * 2 + 1] * inv);
    }
}

// ---------------- launch ----------------
extern "C" void kernel_launch(void* const* d_in, const int* in_sizes, int n_in,
                              void* d_out, int out_size)
{
    const float* hidden = (const float*)d_in[0];
    const float* mask   = (const float*)d_in[1];
    const float* w_attn = (const float*)d_in[2];
    const float* b_attn = (const float*)d_in[3];
    const float* w_proj = (const float*)d_in[4];
    const float* b_proj = (const float*)d_in[5];
    float* out = (float*)d_out;

    uint32_t *hf16, *hbh, *hbl, *qvh, *oh, *wkh, *wkl, *wqv, *wp;
    float *kf32;
    cudaGetSymbolAddress((void**)&hf16, g_hf16);
    cudaGetSymbolAddress((void**)&hbh,  g_hbh);
    cudaGetSymbolAddress((void**)&hbl,  g_hbl);
    cudaGetSymbolAddress((void**)&qvh,  g_qvh);
    cudaGetSymbolAddress((void**)&kf32, g_kf32);
    cudaGetSymbolAddress((void**)&oh,   g_oh);
    cudaGetSymbolAddress((void**)&wkh,  g_wkh);
    cudaGetSymbolAddress((void**)&wkl,  g_wkl);
    cudaGetSymbolAddress((void**)&wqv,  g_wqv);
    cudaGetSymbolAddress((void**)&wp,   g_wp);

    const int att_smem = ATT_FLOATS * (int)sizeof(float);
    cudaFuncSetAttribute(attn_f16,
                         cudaFuncAttributeMaxDynamicSharedMemorySize, att_smem);
    cudaFuncSetAttribute(gemm_bf16k,
                         cudaFuncAttributeMaxDynamicSharedMemorySize, G3_SMEM_BYTES);

    // 0) prep: activations + weights
    prep_hidden<<<NROWS * 512 / 256, 256>>>(hidden, hf16, hbh, hbl);
    prep_wk<<<EMB * 512 / 256, 256>>>(w_attn, wkh, wkl);
    prep_pack_f16<<<2048 * 512 / 256, 256>>>(w_attn, 3 * EMB, 2047, 11, 1024, wqv);
    prep_pack_f16<<<1024 * 512 / 256, 256>>>(w_proj, EMB, 1023, 10, 4096, wp);

    // 1) Q and V sections, fp16, packed output (bx>=8 -> V cols [2048,3072))
    dim3 gqv(16, NROWS / 128);
    gemm_f16<<<gqv, 256>>>(hf16, wqv, b_attn, nullptr, qvh,
                           0, EMB, 8, 1024, 1);

    // 2) K section, bf16x3, fp32 output [row][1024]
    dim3 gk(EMB / 128, NROWS / 128);
    gemm_bf16k<<<gk, 256, G3_SMEM_BYTES>>>(hbh, hbl, wkh, wkl, b_attn + EMB,
                                           kf32, EMB, EMB);

    // 3) attention (packed in/out, fused KIVI quant, trans-V PV)
    attn_f16<<<BATCH * NH * (S_LEN / 128), 256, att_smem>>>(qvh, kf32, mask, oh);

    // 4) out projection, fp16, fp32 output
    dim3 gp(EMB / 128, NROWS / 128);
    gemm_f16<<<gp, 256>>>(oh, wp, b_proj, out, nullptr,
                          EMB, EMB, 16, 0, 0);
}

// round 12
// speedup vs baseline: 4.4353x; 1.1067x over previous
#include <cuda_runtime.h>
#include <cuda_bf16.h>
#include <cuda_fp16.h>
#include <math.h>
#include <stdint.h>

#define BATCH 4
#define S_LEN 1024
#define EMB   1024
#define NH    16
#define HD    64
#define NROWS (BATCH * S_LEN)

// ---------------- scratch (no allocations allowed) ----------------
__device__ uint32_t g_hf16[NROWS * 512];        // hidden fp16 pairs [m][kp]
__device__ uint32_t g_hbh [NROWS * 512];        // hidden bf16 hi    [m][kp]
__device__ uint32_t g_hbl [NROWS * 512];        // hidden bf16 lo    [m][kp]
__device__ uint32_t g_qvh [NROWS * 1024];       // Q|V fp16 pairs: [row][kp], Q kp<512, V kp>=512
__device__ uint32_t g_kh  [NROWS * 512];        // K quantized fp16 pairs [row][kp]
__device__ uint32_t g_oh  [NROWS * 512];        // attention out fp16 pairs [row][kp]
__device__ uint32_t g_wkh [EMB * 512];          // Wk bf16 hi, [n][kp]
__device__ uint32_t g_wkl [EMB * 512];          // Wk bf16 lo, [n][kp]
__device__ uint32_t g_wqv [2048 * 512];         // Wq|Wv fp16, [n][kp]
__device__ uint32_t g_wp  [EMB * 512];          // Wproj fp16, [n][kp]

// ---------------- helpers ----------------
__device__ __forceinline__ void mma16bf(float* d, const uint32_t* a, const uint32_t* b) {
    asm volatile(
        "mma.sync.aligned.m16n8k16.row.col.f32.bf16.bf16.f32 "
        "{%0,%1,%2,%3}, {%4,%5,%6,%7}, {%8,%9}, {%0,%1,%2,%3};"
        : "+f"(d[0]), "+f"(d[1]), "+f"(d[2]), "+f"(d[3])
        : "r"(a[0]), "r"(a[1]), "r"(a[2]), "r"(a[3]), "r"(b[0]), "r"(b[1]));
}

__device__ __forceinline__ void mma16f(float* d, const uint32_t* a, uint32_t b0, uint32_t b1) {
    asm volatile(
        "mma.sync.aligned.m16n8k16.row.col.f32.f16.f16.f32 "
        "{%0,%1,%2,%3}, {%4,%5,%6,%7}, {%8,%9}, {%0,%1,%2,%3};"
        : "+f"(d[0]), "+f"(d[1]), "+f"(d[2]), "+f"(d[3])
        : "r"(a[0]), "r"(a[1]), "r"(a[2]), "r"(a[3]), "r"(b0), "r"(b1));
}

__device__ __forceinline__ void ldsm_x4(uint32_t* r, uint32_t addr) {
    asm volatile("ldmatrix.sync.aligned.m8n8.x4.shared.b16 {%0,%1,%2,%3}, [%4];"
        : "=r"(r[0]), "=r"(r[1]), "=r"(r[2]), "=r"(r[3]) : "r"(addr));
}

__device__ __forceinline__ void ldsm_x4_trans(uint32_t* r, uint32_t addr) {
    asm volatile("ldmatrix.sync.aligned.m8n8.x4.trans.shared.b16 {%0,%1,%2,%3}, [%4];"
        : "=r"(r[0]), "=r"(r[1]), "=r"(r[2]), "=r"(r[3]) : "r"(addr));
}

__device__ __forceinline__ uint32_t pack_bf2(float x0, float x1) {
    __nv_bfloat162 p = __floats2bfloat162_rn(x0, x1);
    return *(uint32_t*)&p;
}

__device__ __forceinline__ uint32_t pack_h2(float x0, float x1) {
    __half2 p = __floats2half2_rn(x0, x1);
    return *(uint32_t*)&p;
}

__device__ __forceinline__ void split_bf(float x, float& h, float& l) {
    __nv_bfloat16 hb = __float2bfloat16_rn(x);
    h = __bfloat162float(hb);
    l = x - h;
}

// quantize a 2-element half of a KIVI group given the group max
__device__ __forceinline__ uint32_t kivi2(float v0, float v1, float ma) {
    float scale = ma * (1.0f / 1.5f);
    float safe = (scale == 0.0f) ? 1.0f : scale;
    float c0 = fminf(fmaxf(rintf(v0 / safe + 1.5f), 0.0f), 3.0f);
    float c1 = fminf(fmaxf(rintf(v1 / safe + 1.5f), 0.0f), 3.0f);
    return pack_h2((c0 - 1.5f) * scale, (c1 - 1.5f) * scale);
}

// ---------------- prep kernels ----------------
__global__ __launch_bounds__(256) void prep_hidden(
    const float* __restrict__ hid, uint32_t* __restrict__ hf,
    uint32_t* __restrict__ hh, uint32_t* __restrict__ hl)
{
    int idx = blockIdx.x * 256 + threadIdx.x;
    int kp = idx & 511;
    int m  = idx >> 9;
    float2 v = *(const float2*)(hid + (size_t)m * EMB + 2 * kp);
    hf[idx] = pack_h2(v.x, v.y);
    float h0, l0, h1, l1;
    split_bf(v.x, h0, l0);
    split_bf(v.y, h1, l1);
    hh[idx] = pack_bf2(h0, h1);
    hl[idx] = pack_bf2(l0, l1);
}

__global__ __launch_bounds__(256) void prep_wk(
    const float* __restrict__ w, uint32_t* __restrict__ wh, uint32_t* __restrict__ wl)
{
    int idx = blockIdx.x * 256 + threadIdx.x;
    int n  = idx & 1023;
    int kp = idx >> 10;
    float x0 = w[(size_t)(2 * kp)     * (3 * EMB) + EMB + n];
    float x1 = w[(size_t)(2 * kp + 1) * (3 * EMB) + EMB + n];
    float h0, l0, h1, l1;
    split_bf(x0, h0, l0);
    split_bf(x1, h1, l1);
    wh[(size_t)n * 512 + kp] = pack_bf2(h0, h1);
    wl[(size_t)n * 512 + kp] = pack_bf2(l0, l1);
}

__global__ __launch_bounds__(256) void prep_pack_f16(
    const float* __restrict__ w, int ldw, int nmask, int nshift, int nswitch,
    uint32_t* __restrict__ out)
{
    int idx = blockIdx.x * 256 + threadIdx.x;
    int n  = idx & nmask;
    int kp = idx >> nshift;
    int col = n + ((n >= nswitch) ? 1024 : 0);
    float x0 = w[(size_t)(2 * kp)     * ldw + col];
    float x1 = w[(size_t)(2 * kp + 1) * ldw + col];
    out[(size_t)n * 512 + kp] = pack_h2(x0, x1);
}

// ---------------- fp16 GEMM: A,B pre-packed [.][kp] ----------------
#define GF_S 20
#define GF_BUF (128 * GF_S)

__global__ __launch_bounds__(256, 2) void gemm_f16(
    const uint32_t* __restrict__ Apk, const uint32_t* __restrict__ Bp,
    const float* __restrict__ bias, float* __restrict__ C,
    uint32_t* __restrict__ Cp, int ldc, int K, int nsplit, int gap, int pack_out)
{
    __shared__ uint32_t As[2][GF_BUF];
    __shared__ uint32_t Bs[2][GF_BUF];

    const int tid = threadIdx.x;
    const int bx = blockIdx.x, by = blockIdx.y;
    const int bcol = bx * 128 + ((bx >= nsplit) ? gap : 0);
    const int lane = tid & 31, wid = tid >> 5;
    const int g = lane >> 2, tg = lane & 3;
    const int wm = (wid >> 2) * 64, wn = (wid & 3) * 32;

    const int la_row = lane & 15, la_chunk = (lane >> 4) * 4;

    const uint32_t as_base = (uint32_t)__cvta_generic_to_shared(As);
    const uint32_t bs_base = (uint32_t)__cvta_generic_to_shared(Bs);

    const int arow = tid >> 1, akp = (tid & 1) * 8;
    const uint32_t* App = Apk + (size_t)(by * 128 + arow) * 512 + akp;
    const uint32_t* Bpp = Bp  + (size_t)(bx * 128 + arow) * 512 + akp;

    float acc[4][4][4];
    #pragma unroll
    for (int mt = 0; mt < 4; mt++)
        #pragma unroll
        for (int nt = 0; nt < 4; nt++)
            #pragma unroll
            for (int i = 0; i < 4; i++) acc[mt][nt][i] = 0.0f;

    uint4 pav[2], pbv[2];
    pav[0] = *(const uint4*)(App);
    pav[1] = *(const uint4*)(App + 4);
    pbv[0] = *(const uint4*)(Bpp);
    pbv[1] = *(const uint4*)(Bpp + 4);

    const int ntiles = K >> 5;
    int buf = 0;
    {
        *(uint4*)&As[0][arow * GF_S + akp]     = pav[0];
        *(uint4*)&As[0][arow * GF_S + akp + 4] = pav[1];
        *(uint4*)&Bs[0][arow * GF_S + akp]     = pbv[0];
        *(uint4*)&Bs[0][arow * GF_S + akp + 4] = pbv[1];
    }
    __syncthreads();

    for (int t = 0; t < ntiles; ++t) {
        if (t + 1 < ntiles) {
            pav[0] = *(const uint4*)(App + (t + 1) * 16);
            pav[1] = *(const uint4*)(App + (t + 1) * 16 + 4);
            pbv[0] = *(const uint4*)(Bpp + (t + 1) * 16);
            pbv[1] = *(const uint4*)(Bpp + (t + 1) * 16 + 4);
        }

        const uint32_t as0 = as_base + (buf * GF_BUF) * 4;
        const uint32_t bs0 = bs_base + (buf * GF_BUF) * 4;

        #pragma unroll
        for (int ks = 0; ks < 2; ++ks) {
            const int kb = ks * 8;
            uint32_t af[4][4], bq[2][4];
            #pragma unroll
            for (int mt = 0; mt < 4; mt++)
                ldsm_x4(af[mt], as0 + ((wm + mt * 16 + la_row) * GF_S + kb + la_chunk) * 4);
            #pragma unroll
            for (int np = 0; np < 2; np++)
                ldsm_x4(bq[np], bs0 + ((wn + np * 16 + la_row) * GF_S + kb + la_chunk) * 4);
            // bq[np] = {bf[2np][0], bf[2np+1][0], bf[2np][1], bf[2np+1][1]}
            #pragma unroll
            for (int mt = 0; mt < 4; mt++)
                #pragma unroll
                for (int np = 0; np < 2; np++) {
                    mma16f(acc[mt][2 * np + 0], af[mt], bq[np][0], bq[np][2]);
                    mma16f(acc[mt][2 * np + 1], af[mt], bq[np][1], bq[np][3]);
                }
        }

        if (t + 1 < ntiles) {
            const int nb = buf ^ 1;
            __syncthreads();
            *(uint4*)&As[nb][arow * GF_S + akp]     = pav[0];
            *(uint4*)&As[nb][arow * GF_S + akp + 4] = pav[1];
            *(uint4*)&Bs[nb][arow * GF_S + akp]     = pbv[0];
            *(uint4*)&Bs[nb][arow * GF_S + akp + 4] = pbv[1];
            __syncthreads();
            buf = nb;
        }
    }

    #pragma unroll
    for (int mt = 0; mt < 4; mt++) {
        #pragma unroll
        for (int nt = 0; nt < 4; nt++) {
            const int col = bcol + wn + nt * 8 + 2 * tg;
            const float bv0 = bias[col], bv1 = bias[col + 1];
            const int row0 = by * 128 + wm + mt * 16 + g;
            float o00 = acc[mt][nt][0] + bv0, o01 = acc[mt][nt][1] + bv1;
            float o10 = acc[mt][nt][2] + bv0, o11 = acc[mt][nt][3] + bv1;
            if (pack_out) {
                const int kp = (col >= 2048) ? (512 + ((col - 2048) >> 1)) : (col >> 1);
                Cp[(size_t)row0 * 1024 + kp]       = pack_h2(o00, o01);
                Cp[(size_t)(row0 + 8) * 1024 + kp] = pack_h2(o10, o11);
            } else {
                *(float2*)(C + (size_t)row0 * ldc + col)       = make_float2(o00, o01);
                *(float2*)(C + (size_t)(row0 + 8) * ldc + col) = make_float2(o10, o11);
            }
        }
    }
}

// ---------------- bf16x3 GEMM for K with FUSED KIVI quant epilogue ----------------
// Writes quantized K directly as packed fp16 [row][kp].
#define G3_S 12
#define G3_BUF (128 * G3_S)
#define G3_SMEM_BYTES (8 * G3_BUF * 4)

__global__ __launch_bounds__(256, 2) void gemm_bf16k(
    const uint32_t* __restrict__ Ahg, const uint32_t* __restrict__ Alg,
    const uint32_t* __restrict__ Bhg, const uint32_t* __restrict__ Blg,
    const float* __restrict__ bias, uint32_t* __restrict__ Kp, int K)
{
    extern __shared__ uint32_t s3[];
    uint32_t* Ah = s3;
    uint32_t* Al = Ah + 2 * G3_BUF;
    uint32_t* Bh = Al + 2 * G3_BUF;
    uint32_t* Bl = Bh + 2 * G3_BUF;

    const int tid = threadIdx.x;
    const int bx = blockIdx.x, by = blockIdx.y;
    const int lane = tid & 31, wid = tid >> 5;
    const int g = lane >> 2, tg = lane & 3;
    const int wm = (wid >> 2) * 64, wn = (wid & 3) * 32;

    const int la_row = lane & 15, la_chunk = (lane >> 4) * 4;

    const uint32_t ah_base = (uint32_t)__cvta_generic_to_shared(Ah);
    const uint32_t al_base = (uint32_t)__cvta_generic_to_shared(Al);
    const uint32_t bh_base = (uint32_t)__cvta_generic_to_shared(Bh);
    const uint32_t bl_base = (uint32_t)__cvta_generic_to_shared(Bl);

    const int arow = tid >> 1, akp = (tid & 1) * 4;
    const uint32_t* Ahp = Ahg + (size_t)(by * 128 + arow) * 512 + akp;
    const uint32_t* Alp = Alg + (size_t)(by * 128 + arow) * 512 + akp;
    const uint32_t* Bhp = Bhg + (size_t)(bx * 128 + arow) * 512 + akp;
    const uint32_t* Blp = Blg + (size_t)(bx * 128 + arow) * 512 + akp;

    float acc[4][4][4];
    #pragma unroll
    for (int mt = 0; mt < 4; mt++)
        #pragma unroll
        for (int nt = 0; nt < 4; nt++)
            #pragma unroll
            for (int i = 0; i < 4; i++) acc[mt][nt][i] = 0.0f;

    uint4 pah = *(const uint4*)(Ahp);
    uint4 pal = *(const uint4*)(Alp);
    uint4 pbh = *(const uint4*)(Bhp);
    uint4 pbl = *(const uint4*)(Blp);

    const int ntiles = K >> 4;
    int buf = 0;
    {
        *(uint4*)&Ah[arow * G3_S + akp] = pah;
        *(uint4*)&Al[arow * G3_S + akp] = pal;
        *(uint4*)&Bh[arow * G3_S + akp] = pbh;
        *(uint4*)&Bl[arow * G3_S + akp] = pbl;
    }
    __syncthreads();

    for (int t = 0; t < ntiles; ++t) {
        if (t + 1 < ntiles) {
            pah = *(const uint4*)(Ahp + (t + 1) * 8);
            pal = *(const uint4*)(Alp + (t + 1) * 8);
            pbh = *(const uint4*)(Bhp + (t + 1) * 8);
            pbl = *(const uint4*)(Blp + (t + 1) * 8);
        }

        const uint32_t ah0 = ah_base + (buf * G3_BUF) * 4;
        const uint32_t al0 = al_base + (buf * G3_BUF) * 4;
        const uint32_t bh0 = bh_base + (buf * G3_BUF) * 4;
        const uint32_t bl0 = bl_base + (buf * G3_BUF) * 4;

        uint32_t afh[4][4], afl[4][4], bqh[2][4], bql[2][4];
        #pragma unroll
        for (int mt = 0; mt < 4; mt++) {
            const uint32_t off = ((wm + mt * 16 + la_row) * G3_S + la_chunk) * 4;
            ldsm_x4(afh[mt], ah0 + off);
            ldsm_x4(afl[mt], al0 + off);
        }
        #pragma unroll
        for (int np = 0; np < 2; np++) {
            const uint32_t off = ((wn + np * 16 + la_row) * G3_S + la_chunk) * 4;
            ldsm_x4(bqh[np], bh0 + off);
            ldsm_x4(bql[np], bl0 + off);
        }
        #pragma unroll
        for (int mt = 0; mt < 4; mt++)
            #pragma unroll
            for (int np = 0; np < 2; np++) {
                float* a0 = acc[mt][2 * np + 0];
                float* a1 = acc[mt][2 * np + 1];
                uint32_t h0[2] = {bqh[np][0], bqh[np][2]};
                uint32_t h1[2] = {bqh[np][1], bqh[np][3]};
                uint32_t l0[2] = {bql[np][0], bql[np][2]};
                uint32_t l1[2] = {bql[np][1], bql[np][3]};
                mma16bf(a0, afh[mt], h0);
                mma16bf(a0, afh[mt], l0);
                mma16bf(a0, afl[mt], h0);
                mma16bf(a1, afh[mt], h1);
                mma16bf(a1, afh[mt], l1);
                mma16bf(a1, afl[mt], h1);
            }

        if (t + 1 < ntiles) {
            const int nb = buf ^ 1;
            __syncthreads();
            *(uint4*)&Ah[nb * G3_BUF + arow * G3_S + akp] = pah;
            *(uint4*)&Al[nb * G3_BUF + arow * G3_S + akp] = pal;
            *(uint4*)&Bh[nb * G3_BUF + arow * G3_S + akp] = pbh;
            *(uint4*)&Bl[nb * G3_BUF + arow * G3_S + akp] = pbl;
            __syncthreads();
            buf = nb;
        }
    }

    // ---- epilogue: bias + KIVI 2-bit quant (group of 4 = tg-pair) + pack fp16 ----
    #pragma unroll
    for (int mt = 0; mt < 4; mt++) {
        #pragma unroll
        for (int nt = 0; nt < 4; nt++) {
            const int col = bx * 128 + wn + nt * 8 + 2 * tg;
            const float bv0 = bias[col], bv1 = bias[col + 1];
            const int row0 = by * 128 + wm + mt * 16 + g;
            float v00 = acc[mt][nt][0] + bv0, v01 = acc[mt][nt][1] + bv1;  // row g
            float v10 = acc[mt][nt][2] + bv0, v11 = acc[mt][nt][3] + bv1;  // row g+8
            float ma0 = fmaxf(fabsf(v00), fabsf(v01));
            float ma1 = fmaxf(fabsf(v10), fabsf(v11));
            ma0 = fmaxf(ma0, __shfl_xor_sync(0xffffffffu, ma0, 1));
            ma1 = fmaxf(ma1, __shfl_xor_sync(0xffffffffu, ma1, 1));
            const int kp = col >> 1;
            Kp[(size_t)row0 * 512 + kp]       = kivi2(v00, v01, ma0);
            Kp[(size_t)(row0 + 8) * 512 + kp] = kivi2(v10, v11, ma1);
        }
    }
}

// ---------------- Flash attention: all packed fp16, pre-quantized K ----------------
#define SQH 36
#define ATT_FLOATS (128 * SQH + 64 * SQH + 128 * SQH + 64 * SQH + 64)

__global__ __launch_bounds__(256, 2) void attn_f16(
    const uint32_t* __restrict__ qvh, const uint32_t* __restrict__ kh,
    const float* __restrict__ mask, uint32_t* __restrict__ outp)
{
    extern __shared__ uint32_t smu[];
    uint32_t* Qs = smu;                  // [128][36] q pairs
    uint32_t* Ks = Qs + 128 * SQH;       // [64][36]  k pairs (pre-quantized)
    uint32_t* Ps = Ks + 64 * SQH;        // [128][36] p pairs
    uint32_t* Vs = Ps + 128 * SQH;       // [64][36]  v pairs row-major [key][dimpair]
    float*    Ms = (float*)(Vs + 64 * SQH);

    const int tid = threadIdx.x, lane = tid & 31, wid = tid >> 5;
    const int g = lane >> 2, tg = lane & 3;
    const int m0 = wid * 16;

    const int la_row = lane & 15, la_chunk = (lane >> 4) * 4;

    const uint32_t qs_base = (uint32_t)__cvta_generic_to_shared(Qs);
    const uint32_t ks_base = (uint32_t)__cvta_generic_to_shared(Ks);
    const uint32_t ps_base = (uint32_t)__cvta_generic_to_shared(Ps);
    const uint32_t vs_base = (uint32_t)__cvta_generic_to_shared(Vs);

    const int bid = blockIdx.x;
    const int qt = bid & 7;
    const int h  = (bid >> 3) & 15;
    const int b  = bid >> 7;

    const uint32_t* qp = qvh + ((size_t)(b * S_LEN) + qt * 128) * 1024 + h * 32;
    const uint32_t* vp = qvh + ((size_t)(b * S_LEN)) * 1024 + 512 + h * 32;
    const uint32_t* kp = kh  + ((size_t)(b * S_LEN)) * 512 + h * 32;
    const float*    mp = mask + b * S_LEN;

    // Q tile: direct packed copy (128 rows x 32 words)
    #pragma unroll
    for (int i = 0; i < 4; i++) {
        int f = tid + 256 * i;
        int row = f >> 3, w4 = (f & 7) * 4;
        uint4 u = *(const uint4*)(qp + (size_t)row * 1024 + w4);
        *(uint4*)&Qs[row * SQH + w4] = u;
    }

    float m_i[2] = {-INFINITY, -INFINITY}, l_i[2] = {0.0f, 0.0f};
    float oa[8][4];
    #pragma unroll
    for (int nt = 0; nt < 8; nt++)
        #pragma unroll
        for (int i = 0; i < 4; i++) oa[nt][i] = 0.0f;

    for (int kt = 0; kt < S_LEN / 64; ++kt) {
        // K + V tiles: direct packed copies (64 rows x 32 words each)
        #pragma unroll
        for (int i = 0; i < 2; i++) {
            int f = tid + 256 * i;
            int row = f >> 3, w4 = (f & 7) * 4;
            int key = (kt << 6) + row;
            uint4 uk = *(const uint4*)(kp + (size_t)key * 512 + w4);
            *(uint4*)&Ks[row * SQH + w4] = uk;
            uint4 uv = *(const uint4*)(vp + (size_t)key * 1024 + w4);
            *(uint4*)&Vs[row * SQH + w4] = uv;
        }
        if (tid < 64) Ms[tid] = mp[(kt << 6) + tid];
        __syncthreads();

        // ---- S = Q K^T : m=16, n=64, k=64 (4 k16); B pairs via x4 ----
        float sacc[8][4];
        #pragma unroll
        for (int nt = 0; nt < 8; nt++)
            #pragma unroll
            for (int i = 0; i < 4; i++) sacc[nt][i] = 0.0f;

        #pragma unroll
        for (int ks = 0; ks < 4; ++ks) {
            const int kb = ks * 8;
            uint32_t af[4];
            ldsm_x4(af, qs_base + ((m0 + la_row) * SQH + kb + la_chunk) * 4);
            #pragma unroll
            for (int np = 0; np < 4; ++np) {
                uint32_t bq[4];
                ldsm_x4(bq, ks_base + ((np * 16 + la_row) * SQH + kb + la_chunk) * 4);
                mma16f(sacc[2 * np + 0], af, bq[0], bq[2]);
                mma16f(sacc[2 * np + 1], af, bq[1], bq[3]);
            }
        }

        // ---- online softmax; P written as packed fp16 pairs ----
        #pragma unroll
        for (int rr = 0; rr < 2; ++rr) {
            float mx = -INFINITY;
            #pragma unroll
            for (int nt = 0; nt < 8; nt++) {
                const int c0 = nt * 8 + 2 * tg;
                float s0 = (sacc[nt][rr * 2 + 0] + Ms[c0]) * 0.125f;
                float s1 = (sacc[nt][rr * 2 + 1] + Ms[c0 + 1]) * 0.125f;
                sacc[nt][rr * 2 + 0] = s0;
                sacc[nt][rr * 2 + 1] = s1;
                mx = fmaxf(mx, fmaxf(s0, s1));
            }
            mx = fmaxf(mx, __shfl_xor_sync(0xffffffffu, mx, 1));
            mx = fmaxf(mx, __shfl_xor_sync(0xffffffffu, mx, 2));
            const float mnew = fmaxf(m_i[rr], mx);
            const float alpha = __expf(m_i[rr] - mnew);
            float rs = 0.0f;
            const int row = m0 + g + rr * 8;
            #pragma unroll
            for (int nt = 0; nt < 8; nt++) {
                float p0 = __expf(sacc[nt][rr * 2 + 0] - mnew);
                float p1 = __expf(sacc[nt][rr * 2 + 1] - mnew);
                rs += p0 + p1;
                Ps[row * SQH + nt * 4 + tg] = pack_h2(p0, p1);
            }
            rs += __shfl_xor_sync(0xffffffffu, rs, 1);
            rs += __shfl_xor_sync(0xffffffffu, rs, 2);
            l_i[rr] = l_i[rr] * alpha + rs;
            m_i[rr] = mnew;
            #pragma unroll
            for (int nt = 0; nt < 8; nt++) {
                oa[nt][rr * 2 + 0] *= alpha;
                oa[nt][rr * 2 + 1] *= alpha;
            }
        }
        __syncwarp();   // P rows are warp-private

        // ---- O += P V : B pairs via x4.trans on row-major V ----
        #pragma unroll
        for (int ks = 0; ks < 4; ++ks) {
            const int kb = ks * 8;
            uint32_t ap[4];
            ldsm_x4(ap, ps_base + ((m0 + la_row) * SQH + kb + la_chunk) * 4);
            #pragma unroll
            for (int np = 0; np < 4; ++np) {
                uint32_t bv[4];
                // lanes 0-15 -> dims 2np*8..; lanes 16-31 -> dims (2np+1)*8..
                ldsm_x4_trans(bv, vs_base +
                    ((ks * 16 + la_row) * SQH + (2 * np + (lane >> 4)) * 4) * 4);
                // bv = {bf[2np][0], bf[2np][1], bf[2np+1][0], bf[2np+1][1]}
                mma16f(oa[2 * np + 0], ap, bv[0], bv[1]);
                mma16f(oa[2 * np + 1], ap, bv[2], bv[3]);
            }
        }
        __syncthreads();
    }

    // ---- epilogue: packed fp16 output [row][kp] for the proj GEMM ----
    #pragma unroll
    for (int rr = 0; rr < 2; ++rr) {
        const float inv = 1.0f / l_i[rr];
        const int srow = qt * 128 + m0 + g + rr * 8;
        uint32_t* op = outp + ((size_t)(b * S_LEN + srow)) * 512 + h * 32;
        #pragma unroll
        for (int nt = 0; nt < 8; nt++)
            op[nt * 4 + tg] = pack_h2(oa[nt][rr * 2 + 0] * inv, oa[nt][rr * 2 + 1] * inv);
    }
}

// ---------------- launch ----------------
extern "C" void kernel_launch(void* const* d_in, const int* in_sizes, int n_in,
                              void* d_out, int out_size)
{
    const float* hidden = (const float*)d_in[0];
    const float* mask   = (const float*)d_in[1];
    const float* w_attn = (const float*)d_in[2];
    const float* b_attn = (const float*)d_in[3];
    const float* w_proj = (const float*)d_in[4];
    const float* b_proj = (const float*)d_in[5];
    float* out = (float*)d_out;

    uint32_t *hf16, *hbh, *hbl, *qvh, *kh, *oh, *wkh, *wkl, *wqv, *wp;
    cudaGetSymbolAddress((void**)&hf16, g_hf16);
    cudaGetSymbolAddress((void**)&hbh,  g_hbh);
    cudaGetSymbolAddress((void**)&hbl,  g_hbl);
    cudaGetSymbolAddress((void**)&qvh,  g_qvh);
    cudaGetSymbolAddress((void**)&kh,   g_kh);
    cudaGetSymbolAddress((void**)&oh,   g_oh);
    cudaGetSymbolAddress((void**)&wkh,  g_wkh);
    cudaGetSymbolAddress((void**)&wkl,  g_wkl);
    cudaGetSymbolAddress((void**)&wqv,  g_wqv);
    cudaGetSymbolAddress((void**)&wp,   g_wp);

    const int att_smem = ATT_FLOATS * (int)sizeof(float);
    cudaFuncSetAttribute(attn_f16,
                         cudaFuncAttributeMaxDynamicSharedMemorySize, att_smem);
    cudaFuncSetAttribute(gemm_bf16k,
                         cudaFuncAttributeMaxDynamicSharedMemorySize, G3_SMEM_BYTES);

    // 0) prep: activations + weights
    prep_hidden<<<NROWS * 512 / 256, 256>>>(hidden, hf16, hbh, hbl);
    prep_wk<<<EMB * 512 / 256, 256>>>(w_attn, wkh, wkl);
    prep_pack_f16<<<2048 * 512 / 256, 256>>>(w_attn, 3 * EMB, 2047, 11, 1024, wqv);
    prep_pack_f16<<<1024 * 512 / 256, 256>>>(w_proj, EMB, 1023, 10, 4096, wp);

    // 1) Q and V sections, fp16, packed output
    dim3 gqv(16, NROWS / 128);
    gemm_f16<<<gqv, 256>>>(hf16, wqv, b_attn, nullptr, qvh,
                           0, EMB, 8, 1024, 1);

    // 2) K section, bf16x3, FUSED KIVI quant -> packed fp16
    dim3 gk(EMB / 128, NROWS / 128);
    gemm_bf16k<<<gk, 256, G3_SMEM_BYTES>>>(hbh, hbl, wkh, wkl, b_attn + EMB,
                                           kh, EMB);

    // 3) attention (all packed, pre-quantized K)
    attn_f16<<<BATCH * NH * (S_LEN / 128), 256, att_smem>>>(qvh, kh, mask, oh);

    // 4) out projection, fp16, fp32 output
    dim3 gp(EMB / 128, NROWS / 128);
    gemm_f16<<<gp, 256>>>(oh, wp, b_proj, out, nullptr,
                          EMB, EMB, 16, 0, 0);
}

// round 13
// speedup vs baseline: 4.5703x; 1.0304x over previous
#include <cuda_runtime.h>
#include <cuda_bf16.h>
#include <cuda_fp16.h>
#include <math.h>
#include <stdint.h>

#define BATCH 4
#define S_LEN 1024
#define EMB   1024
#define NH    16
#define HD    64
#define NROWS (BATCH * S_LEN)

// ---------------- scratch (no allocations allowed) ----------------
__device__ uint32_t g_hf16[NROWS * 512];        // hidden fp16 pairs [m][kp]
__device__ uint32_t g_hbh [NROWS * 512];        // hidden bf16 hi    [m][kp]
__device__ uint32_t g_hbl [NROWS * 512];        // hidden bf16 lo    [m][kp]
__device__ uint32_t g_qvh [NROWS * 1024];       // Q|V fp16 pairs: [row][kp], Q kp<512, V kp>=512
__device__ uint32_t g_kh  [NROWS * 512];        // K quantized fp16 pairs [row][kp]
__device__ uint32_t g_oh  [NROWS * 512];        // attention out fp16 pairs [row][kp]
__device__ uint32_t g_wkh [EMB * 512];          // Wk bf16 hi, [n][kp]
__device__ uint32_t g_wkl [EMB * 512];          // Wk bf16 lo, [n][kp]
__device__ uint32_t g_wqv [2048 * 512];         // Wq|Wv fp16, [n][kp]
__device__ uint32_t g_wp  [EMB * 512];          // Wproj fp16, [n][kp]

// ---------------- helpers ----------------
__device__ __forceinline__ void mma16bf(float* d, const uint32_t* a, const uint32_t* b) {
    asm volatile(
        "mma.sync.aligned.m16n8k16.row.col.f32.bf16.bf16.f32 "
        "{%0,%1,%2,%3}, {%4,%5,%6,%7}, {%8,%9}, {%0,%1,%2,%3};"
        : "+f"(d[0]), "+f"(d[1]), "+f"(d[2]), "+f"(d[3])
        : "r"(a[0]), "r"(a[1]), "r"(a[2]), "r"(a[3]), "r"(b[0]), "r"(b[1]));
}

__device__ __forceinline__ void mma16f(float* d, const uint32_t* a, uint32_t b0, uint32_t b1) {
    asm volatile(
        "mma.sync.aligned.m16n8k16.row.col.f32.f16.f16.f32 "
        "{%0,%1,%2,%3}, {%4,%5,%6,%7}, {%8,%9}, {%0,%1,%2,%3};"
        : "+f"(d[0]), "+f"(d[1]), "+f"(d[2]), "+f"(d[3])
        : "r"(a[0]), "r"(a[1]), "r"(a[2]), "r"(a[3]), "r"(b0), "r"(b1));
}

__device__ __forceinline__ void ldsm_x4(uint32_t* r, uint32_t addr) {
    asm volatile("ldmatrix.sync.aligned.m8n8.x4.shared.b16 {%0,%1,%2,%3}, [%4];"
        : "=r"(r[0]), "=r"(r[1]), "=r"(r[2]), "=r"(r[3]) : "r"(addr));
}

__device__ __forceinline__ void ldsm_x4_trans(uint32_t* r, uint32_t addr) {
    asm volatile("ldmatrix.sync.aligned.m8n8.x4.trans.shared.b16 {%0,%1,%2,%3}, [%4];"
        : "=r"(r[0]), "=r"(r[1]), "=r"(r[2]), "=r"(r[3]) : "r"(addr));
}

#define CP_ASYNC16(saddr, gptr) \
    asm volatile("cp.async.cg.shared.global [%0], [%1], 16;" \
        :: "r"(saddr), "l"(gptr) : "memory")
#define CP_COMMIT() asm volatile("cp.async.commit_group;" ::: "memory")
#define CP_WAIT0()  asm volatile("cp.async.wait_group 0;" ::: "memory")

__device__ __forceinline__ uint32_t pack_bf2(float x0, float x1) {
    __nv_bfloat162 p = __floats2bfloat162_rn(x0, x1);
    return *(uint32_t*)&p;
}

__device__ __forceinline__ uint32_t pack_h2(float x0, float x1) {
    __half2 p = __floats2half2_rn(x0, x1);
    return *(uint32_t*)&p;
}

__device__ __forceinline__ void split_bf(float x, float& h, float& l) {
    __nv_bfloat16 hb = __float2bfloat16_rn(x);
    h = __bfloat162float(hb);
    l = x - h;
}

__device__ __forceinline__ uint32_t kivi2(float v0, float v1, float ma) {
    float scale = ma * (1.0f / 1.5f);
    float safe = (scale == 0.0f) ? 1.0f : scale;
    float c0 = fminf(fmaxf(rintf(v0 / safe + 1.5f), 0.0f), 3.0f);
    float c1 = fminf(fmaxf(rintf(v1 / safe + 1.5f), 0.0f), 3.0f);
    return pack_h2((c0 - 1.5f) * scale, (c1 - 1.5f) * scale);
}

// ---------------- prep kernels ----------------
__global__ __launch_bounds__(256) void prep_hidden(
    const float* __restrict__ hid, uint32_t* __restrict__ hf,
    uint32_t* __restrict__ hh, uint32_t* __restrict__ hl)
{
    int idx = blockIdx.x * 256 + threadIdx.x;
    int kp = idx & 511;
    int m  = idx >> 9;
    float2 v = *(const float2*)(hid + (size_t)m * EMB + 2 * kp);
    hf[idx] = pack_h2(v.x, v.y);
    float h0, l0, h1, l1;
    split_bf(v.x, h0, l0);
    split_bf(v.y, h1, l1);
    hh[idx] = pack_bf2(h0, h1);
    hl[idx] = pack_bf2(l0, l1);
}

// fused weight prep: blocks [0,2048) Wk bf16 hi/lo; [2048,6144) Wqv fp16; [6144,8192) Wp fp16
__global__ __launch_bounds__(256) void prep_weights(
    const float* __restrict__ wa, const float* __restrict__ wpj,
    uint32_t* __restrict__ wkh, uint32_t* __restrict__ wkl,
    uint32_t* __restrict__ wqv, uint32_t* __restrict__ wp)
{
    int bidx = blockIdx.x;
    if (bidx < 2048) {
        int idx = bidx * 256 + threadIdx.x;
        int n  = idx & 1023;
        int kp = idx >> 10;
        float x0 = wa[(size_t)(2 * kp)     * (3 * EMB) + EMB + n];
        float x1 = wa[(size_t)(2 * kp + 1) * (3 * EMB) + EMB + n];
        float h0, l0, h1, l1;
        split_bf(x0, h0, l0);
        split_bf(x1, h1, l1);
        wkh[(size_t)n * 512 + kp] = pack_bf2(h0, h1);
        wkl[(size_t)n * 512 + kp] = pack_bf2(l0, l1);
    } else if (bidx < 6144) {
        int idx = (bidx - 2048) * 256 + threadIdx.x;
        int n  = idx & 2047;
        int kp = idx >> 11;
        int col = n + ((n >= 1024) ? 1024 : 0);   // n<1024 -> Q col n; else V col n+1024
        float x0 = wa[(size_t)(2 * kp)     * (3 * EMB) + col];
        float x1 = wa[(size_t)(2 * kp + 1) * (3 * EMB) + col];
        wqv[(size_t)n * 512 + kp] = pack_h2(x0, x1);
    } else {
        int idx = (bidx - 6144) * 256 + threadIdx.x;
        int n  = idx & 1023;
        int kp = idx >> 10;
        float x0 = wpj[(size_t)(2 * kp)     * EMB + n];
        float x1 = wpj[(size_t)(2 * kp + 1) * EMB + n];
        wp[(size_t)n * 512 + kp] = pack_h2(x0, x1);
    }
}

// ---------------- fp16 GEMM: A,B pre-packed [.][kp] ----------------
#define GF_S 20
#define GF_BUF (128 * GF_S)

__global__ __launch_bounds__(256, 2) void gemm_f16(
    const uint32_t* __restrict__ Apk, const uint32_t* __restrict__ Bp,
    const float* __restrict__ bias, float* __restrict__ C,
    uint32_t* __restrict__ Cp, int ldc, int K, int nsplit, int gap, int pack_out)
{
    __shared__ uint32_t As[2][GF_BUF];
    __shared__ uint32_t Bs[2][GF_BUF];

    const int tid = threadIdx.x;
    const int bx = blockIdx.x, by = blockIdx.y;
    const int bcol = bx * 128 + ((bx >= nsplit) ? gap : 0);
    const int lane = tid & 31, wid = tid >> 5;
    const int g = lane >> 2, tg = lane & 3;
    const int wm = (wid >> 2) * 64, wn = (wid & 3) * 32;

    const int la_row = lane & 15, la_chunk = (lane >> 4) * 4;

    const uint32_t as_base = (uint32_t)__cvta_generic_to_shared(As);
    const uint32_t bs_base = (uint32_t)__cvta_generic_to_shared(Bs);

    const int arow = tid >> 1, akp = (tid & 1) * 8;
    const uint32_t* App = Apk + (size_t)(by * 128 + arow) * 512 + akp;
    const uint32_t* Bpp = Bp  + (size_t)(bx * 128 + arow) * 512 + akp;

    float acc[4][4][4];
    #pragma unroll
    for (int mt = 0; mt < 4; mt++)
        #pragma unroll
        for (int nt = 0; nt < 4; nt++)
            #pragma unroll
            for (int i = 0; i < 4; i++) acc[mt][nt][i] = 0.0f;

    uint4 pav[2], pbv[2];
    pav[0] = *(const uint4*)(App);
    pav[1] = *(const uint4*)(App + 4);
    pbv[0] = *(const uint4*)(Bpp);
    pbv[1] = *(const uint4*)(Bpp + 4);

    const int ntiles = K >> 5;
    int buf = 0;
    {
        *(uint4*)&As[0][arow * GF_S + akp]     = pav[0];
        *(uint4*)&As[0][arow * GF_S + akp + 4] = pav[1];
        *(uint4*)&Bs[0][arow * GF_S + akp]     = pbv[0];
        *(uint4*)&Bs[0][arow * GF_S + akp + 4] = pbv[1];
    }
    __syncthreads();

    for (int t = 0; t < ntiles; ++t) {
        if (t + 1 < ntiles) {
            pav[0] = *(const uint4*)(App + (t + 1) * 16);
            pav[1] = *(const uint4*)(App + (t + 1) * 16 + 4);
            pbv[0] = *(const uint4*)(Bpp + (t + 1) * 16);
            pbv[1] = *(const uint4*)(Bpp + (t + 1) * 16 + 4);
        }

        const uint32_t as0 = as_base + (buf * GF_BUF) * 4;
        const uint32_t bs0 = bs_base + (buf * GF_BUF) * 4;

        #pragma unroll
        for (int ks = 0; ks < 2; ++ks) {
            const int kb = ks * 8;
            uint32_t af[4][4], bq[2][4];
            #pragma unroll
            for (int mt = 0; mt < 4; mt++)
                ldsm_x4(af[mt], as0 + ((wm + mt * 16 + la_row) * GF_S + kb + la_chunk) * 4);
            #pragma unroll
            for (int np = 0; np < 2; np++)
                ldsm_x4(bq[np], bs0 + ((wn + np * 16 + la_row) * GF_S + kb + la_chunk) * 4);
            #pragma unroll
            for (int mt = 0; mt < 4; mt++)
                #pragma unroll
                for (int np = 0; np < 2; np++) {
                    mma16f(acc[mt][2 * np + 0], af[mt], bq[np][0], bq[np][2]);
                    mma16f(acc[mt][2 * np + 1], af[mt], bq[np][1], bq[np][3]);
                }
        }

        if (t + 1 < ntiles) {
            const int nb = buf ^ 1;
            __syncthreads();
            *(uint4*)&As[nb][arow * GF_S + akp]     = pav[0];
            *(uint4*)&As[nb][arow * GF_S + akp + 4] = pav[1];
            *(uint4*)&Bs[nb][arow * GF_S + akp]     = pbv[0];
            *(uint4*)&Bs[nb][arow * GF_S + akp + 4] = pbv[1];
            __syncthreads();
            buf = nb;
        }
    }

    #pragma unroll
    for (int mt = 0; mt < 4; mt++) {
        #pragma unroll
        for (int nt = 0; nt < 4; nt++) {
            const int col = bcol + wn + nt * 8 + 2 * tg;
            const float bv0 = bias[col], bv1 = bias[col + 1];
            const int row0 = by * 128 + wm + mt * 16 + g;
            float o00 = acc[mt][nt][0] + bv0, o01 = acc[mt][nt][1] + bv1;
            float o10 = acc[mt][nt][2] + bv0, o11 = acc[mt][nt][3] + bv1;
            if (pack_out) {
                const int kp = (col >= 2048) ? (512 + ((col - 2048) >> 1)) : (col >> 1);
                Cp[(size_t)row0 * 1024 + kp]       = pack_h2(o00, o01);
                Cp[(size_t)(row0 + 8) * 1024 + kp] = pack_h2(o10, o11);
            } else {
                *(float2*)(C + (size_t)row0 * ldc + col)       = make_float2(o00, o01);
                *(float2*)(C + (size_t)(row0 + 8) * ldc + col) = make_float2(o10, o11);
            }
        }
    }
}

// ---------------- bf16x3 GEMM for K with FUSED KIVI quant epilogue ----------------
#define G3_S 12
#define G3_BUF (128 * G3_S)
#define G3_SMEM_BYTES (8 * G3_BUF * 4)

__global__ __launch_bounds__(256, 2) void gemm_bf16k(
    const uint32_t* __restrict__ Ahg, const uint32_t* __restrict__ Alg,
    const uint32_t* __restrict__ Bhg, const uint32_t* __restrict__ Blg,
    const float* __restrict__ bias, uint32_t* __restrict__ Kp, int K)
{
    extern __shared__ uint32_t s3[];
    uint32_t* Ah = s3;
    uint32_t* Al = Ah + 2 * G3_BUF;
    uint32_t* Bh = Al + 2 * G3_BUF;
    uint32_t* Bl = Bh + 2 * G3_BUF;

    const int tid = threadIdx.x;
    const int bx = blockIdx.x, by = blockIdx.y;
    const int lane = tid & 31, wid = tid >> 5;
    const int g = lane >> 2, tg = lane & 3;
    const int wm = (wid >> 2) * 64, wn = (wid & 3) * 32;

    const int la_row = lane & 15, la_chunk = (lane >> 4) * 4;

    const uint32_t ah_base = (uint32_t)__cvta_generic_to_shared(Ah);
    const uint32_t al_base = (uint32_t)__cvta_generic_to_shared(Al);
    const uint32_t bh_base = (uint32_t)__cvta_generic_to_shared(Bh);
    const uint32_t bl_base = (uint32_t)__cvta_generic_to_shared(Bl);

    const int arow = tid >> 1, akp = (tid & 1) * 4;
    const uint32_t* Ahp = Ahg + (size_t)(by * 128 + arow) * 512 + akp;
    const uint32_t* Alp = Alg + (size_t)(by * 128 + arow) * 512 + akp;
    const uint32_t* Bhp = Bhg + (size_t)(bx * 128 + arow) * 512 + akp;
    const uint32_t* Blp = Blg + (size_t)(bx * 128 + arow) * 512 + akp;

    float acc[4][4][4];
    #pragma unroll
    for (int mt = 0; mt < 4; mt++)
        #pragma unroll
        for (int nt = 0; nt < 4; nt++)
            #pragma unroll
            for (int i = 0; i < 4; i++) acc[mt][nt][i] = 0.0f;

    uint4 pah = *(const uint4*)(Ahp);
    uint4 pal = *(const uint4*)(Alp);
    uint4 pbh = *(const uint4*)(Bhp);
    uint4 pbl = *(const uint4*)(Blp);

    const int ntiles = K >> 4;
    int buf = 0;
    {
        *(uint4*)&Ah[arow * G3_S + akp] = pah;
        *(uint4*)&Al[arow * G3_S + akp] = pal;
        *(uint4*)&Bh[arow * G3_S + akp] = pbh;
        *(uint4*)&Bl[arow * G3_S + akp] = pbl;
    }
    __syncthreads();

    for (int t = 0; t < ntiles; ++t) {
        if (t + 1 < ntiles) {
            pah = *(const uint4*)(Ahp + (t + 1) * 8);
            pal = *(const uint4*)(Alp + (t + 1) * 8);
            pbh = *(const uint4*)(Bhp + (t + 1) * 8);
            pbl = *(const uint4*)(Blp + (t + 1) * 8);
        }

        const uint32_t ah0 = ah_base + (buf * G3_BUF) * 4;
        const uint32_t al0 = al_base + (buf * G3_BUF) * 4;
        const uint32_t bh0 = bh_base + (buf * G3_BUF) * 4;
        const uint32_t bl0 = bl_base + (buf * G3_BUF) * 4;

        uint32_t afh[4][4], afl[4][4], bqh[2][4], bql[2][4];
        #pragma unroll
        for (int mt = 0; mt < 4; mt++) {
            const uint32_t off = ((wm + mt * 16 + la_row) * G3_S + la_chunk) * 4;
            ldsm_x4(afh[mt], ah0 + off);
            ldsm_x4(afl[mt], al0 + off);
        }
        #pragma unroll
        for (int np = 0; np < 2; np++) {
            const uint32_t off = ((wn + np * 16 + la_row) * G3_S + la_chunk) * 4;
            ldsm_x4(bqh[np], bh0 + off);
            ldsm_x4(bql[np], bl0 + off);
        }
        #pragma unroll
        for (int mt = 0; mt < 4; mt++)
            #pragma unroll
            for (int np = 0; np < 2; np++) {
                float* a0 = acc[mt][2 * np + 0];
                float* a1 = acc[mt][2 * np + 1];
                uint32_t h0[2] = {bqh[np][0], bqh[np][2]};
                uint32_t h1[2] = {bqh[np][1], bqh[np][3]};
                uint32_t l0[2] = {bql[np][0], bql[np][2]};
                uint32_t l1[2] = {bql[np][1], bql[np][3]};
                mma16bf(a0, afh[mt], h0);
                mma16bf(a0, afh[mt], l0);
                mma16bf(a0, afl[mt], h0);
                mma16bf(a1, afh[mt], h1);
                mma16bf(a1, afh[mt], l1);
                mma16bf(a1, afl[mt], h1);
            }

        if (t + 1 < ntiles) {
            const int nb = buf ^ 1;
            __syncthreads();
            *(uint4*)&Ah[nb * G3_BUF + arow * G3_S + akp] = pah;
            *(uint4*)&Al[nb * G3_BUF + arow * G3_S + akp] = pal;
            *(uint4*)&Bh[nb * G3_BUF + arow * G3_S + akp] = pbh;
            *(uint4*)&Bl[nb * G3_BUF + arow * G3_S + akp] = pbl;
            __syncthreads();
            buf = nb;
        }
    }

    #pragma unroll
    for (int mt = 0; mt < 4; mt++) {
        #pragma unroll
        for (int nt = 0; nt < 4; nt++) {
            const int col = bx * 128 + wn + nt * 8 + 2 * tg;
            const float bv0 = bias[col], bv1 = bias[col + 1];
            const int row0 = by * 128 + wm + mt * 16 + g;
            float v00 = acc[mt][nt][0] + bv0, v01 = acc[mt][nt][1] + bv1;
            float v10 = acc[mt][nt][2] + bv0, v11 = acc[mt][nt][3] + bv1;
            float ma0 = fmaxf(fabsf(v00), fabsf(v01));
            float ma1 = fmaxf(fabsf(v10), fabsf(v11));
            ma0 = fmaxf(ma0, __shfl_xor_sync(0xffffffffu, ma0, 1));
            ma1 = fmaxf(ma1, __shfl_xor_sync(0xffffffffu, ma1, 1));
            const int kp = col >> 1;
            Kp[(size_t)row0 * 512 + kp]       = kivi2(v00, v01, ma0);
            Kp[(size_t)(row0 + 8) * 512 + kp] = kivi2(v10, v11, ma1);
        }
    }
}

// ---------------- Flash attention: cp.async double-buffered KV pipeline ----------------
#define SQH 36
#define ATT_FLOATS (128 * SQH + 2 * 64 * SQH + 128 * SQH + 2 * 64 * SQH + 2 * 64)

__global__ __launch_bounds__(256, 2) void attn_f16(
    const uint32_t* __restrict__ qvh, const uint32_t* __restrict__ kh,
    const float* __restrict__ mask, uint32_t* __restrict__ outp)
{
    extern __shared__ uint32_t smu[];
    uint32_t* Qs = smu;                       // [128][36]
    uint32_t* Ks = Qs + 128 * SQH;            // [2][64][36]
    uint32_t* Ps = Ks + 2 * 64 * SQH;         // [128][36]
    uint32_t* Vs = Ps + 128 * SQH;            // [2][64][36]
    float*    Ms = (float*)(Vs + 2 * 64 * SQH);  // [2][64]

    const int tid = threadIdx.x, lane = tid & 31, wid = tid >> 5;
    const int g = lane >> 2, tg = lane & 3;
    const int m0 = wid * 16;

    const int la_row = lane & 15, la_chunk = (lane >> 4) * 4;

    const uint32_t qs_base = (uint32_t)__cvta_generic_to_shared(Qs);
    const uint32_t ks_base = (uint32_t)__cvta_generic_to_shared(Ks);
    const uint32_t ps_base = (uint32_t)__cvta_generic_to_shared(Ps);
    const uint32_t vs_base = (uint32_t)__cvta_generic_to_shared(Vs);
    const uint32_t ms_base = (uint32_t)__cvta_generic_to_shared(Ms);

    const int bid = blockIdx.x;
    const int qt = bid & 7;
    const int h  = (bid >> 3) & 15;
    const int b  = bid >> 7;

    const uint32_t* qp = qvh + ((size_t)(b * S_LEN) + qt * 128) * 1024 + h * 32;
    const uint32_t* vp = qvh + ((size_t)(b * S_LEN)) * 1024 + 512 + h * 32;
    const uint32_t* kp = kh  + ((size_t)(b * S_LEN)) * 512 + h * 32;
    const float*    mp = mask + b * S_LEN;

    // async tile loader: K/V/mask tile ktn -> buffer bb
    auto load_tile = [&](int ktn, int bb) {
        #pragma unroll
        for (int i = 0; i < 2; i++) {
            int f = tid + 256 * i;
            int row = f >> 3, w4 = (f & 7) * 4;
            int key = (ktn << 6) + row;
            CP_ASYNC16(ks_base + ((bb * 64 + row) * SQH + w4) * 4,
                       kp + (size_t)key * 512 + w4);
            CP_ASYNC16(vs_base + ((bb * 64 + row) * SQH + w4) * 4,
                       vp + (size_t)key * 1024 + w4);
        }
        if (tid < 16)
            CP_ASYNC16(ms_base + (bb * 64 + tid * 4) * 4, mp + (ktn << 6) + tid * 4);
    };

    // preload tile 0 (async) + Q tile (sync copy)
    load_tile(0, 0);
    CP_COMMIT();
    #pragma unroll
    for (int i = 0; i < 4; i++) {
        int f = tid + 256 * i;
        int row = f >> 3, w4 = (f & 7) * 4;
        uint4 u = *(const uint4*)(qp + (size_t)row * 1024 + w4);
        *(uint4*)&Qs[row * SQH + w4] = u;
    }

    float m_i[2] = {-INFINITY, -INFINITY}, l_i[2] = {0.0f, 0.0f};
    float oa[8][4];
    #pragma unroll
    for (int nt = 0; nt < 8; nt++)
        #pragma unroll
        for (int i = 0; i < 4; i++) oa[nt][i] = 0.0f;

    CP_WAIT0();
    __syncthreads();

    int buf = 0;
    const int NT = S_LEN / 64;
    for (int kt = 0; kt < NT; ++kt) {
        // prefetch next tile into the other buffer (overlaps with compute below)
        if (kt + 1 < NT) {
            load_tile(kt + 1, buf ^ 1);
            CP_COMMIT();
        }

        const uint32_t ksb = ks_base + (buf * 64 * SQH) * 4;
        const uint32_t vsb = vs_base + (buf * 64 * SQH) * 4;
        const float*   msb = Ms + buf * 64;

        // ---- S = Q K^T ----
        float sacc[8][4];
        #pragma unroll
        for (int nt = 0; nt < 8; nt++)
            #pragma unroll
            for (int i = 0; i < 4; i++) sacc[nt][i] = 0.0f;

        #pragma unroll
        for (int ks = 0; ks < 4; ++ks) {
            const int kb = ks * 8;
            uint32_t af[4];
            ldsm_x4(af, qs_base + ((m0 + la_row) * SQH + kb + la_chunk) * 4);
            #pragma unroll
            for (int np = 0; np < 4; ++np) {
                uint32_t bq[4];
                ldsm_x4(bq, ksb + ((np * 16 + la_row) * SQH + kb + la_chunk) * 4);
                mma16f(sacc[2 * np + 0], af, bq[0], bq[2]);
                mma16f(sacc[2 * np + 1], af, bq[1], bq[3]);
            }
        }

        // ---- online softmax ----
        #pragma unroll
        for (int rr = 0; rr < 2; ++rr) {
            float mx = -INFINITY;
            #pragma unroll
            for (int nt = 0; nt < 8; nt++) {
                const int c0 = nt * 8 + 2 * tg;
                float s0 = (sacc[nt][rr * 2 + 0] + msb[c0]) * 0.125f;
                float s1 = (sacc[nt][rr * 2 + 1] + msb[c0 + 1]) * 0.125f;
                sacc[nt][rr * 2 + 0] = s0;
                sacc[nt][rr * 2 + 1] = s1;
                mx = fmaxf(mx, fmaxf(s0, s1));
            }
            mx = fmaxf(mx, __shfl_xor_sync(0xffffffffu, mx, 1));
            mx = fmaxf(mx, __shfl_xor_sync(0xffffffffu, mx, 2));
            const float mnew = fmaxf(m_i[rr], mx);
            const float alpha = __expf(m_i[rr] - mnew);
            float rs = 0.0f;
            const int row = m0 + g + rr * 8;
            #pragma unroll
            for (int nt = 0; nt < 8; nt++) {
                float p0 = __expf(sacc[nt][rr * 2 + 0] - mnew);
                float p1 = __expf(sacc[nt][rr * 2 + 1] - mnew);
                rs += p0 + p1;
                Ps[row * SQH + nt * 4 + tg] = pack_h2(p0, p1);
            }
            rs += __shfl_xor_sync(0xffffffffu, rs, 1);
            rs += __shfl_xor_sync(0xffffffffu, rs, 2);
            l_i[rr] = l_i[rr] * alpha + rs;
            m_i[rr] = mnew;
            #pragma unroll
            for (int nt = 0; nt < 8; nt++) {
                oa[nt][rr * 2 + 0] *= alpha;
                oa[nt][rr * 2 + 1] *= alpha;
            }
        }
        __syncwarp();   // P rows are warp-private

        // ---- O += P V ----
        #pragma unroll
        for (int ks = 0; ks < 4; ++ks) {
            const int kb = ks * 8;
            uint32_t ap[4];
            ldsm_x4(ap, ps_base + ((m0 + la_row) * SQH + kb + la_chunk) * 4);
            #pragma unroll
            for (int np = 0; np < 4; ++np) {
                uint32_t bv[4];
                ldsm_x4_trans(bv, vsb +
                    ((ks * 16 + la_row) * SQH + (2 * np + (lane >> 4)) * 4) * 4);
                mma16f(oa[2 * np + 0], ap, bv[0], bv[1]);
                mma16f(oa[2 * np + 1], ap, bv[2], bv[3]);
            }
        }

        if (kt + 1 < NT) CP_WAIT0();
        __syncthreads();
        buf ^= 1;
    }

    // ---- epilogue: packed fp16 output [row][kp] for the proj GEMM ----
    #pragma unroll
    for (int rr = 0; rr < 2; ++rr) {
        const float inv = 1.0f / l_i[rr];
        const int srow = qt * 128 + m0 + g + rr * 8;
        uint32_t* op = outp + ((size_t)(b * S_LEN + srow)) * 512 + h * 32;
        #pragma unroll
        for (int nt = 0; nt < 8; nt++)
            op[nt * 4 + tg] = pack_h2(oa[nt][rr * 2 + 0] * inv, oa[nt][rr * 2 + 1] * inv);
    }
}

// ---------------- launch ----------------
extern "C" void kernel_launch(void* const* d_in, const int* in_sizes, int n_in,
                              void* d_out, int out_size)
{
    const float* hidden = (const float*)d_in[0];
    const float* mask   = (const float*)d_in[1];
    const float* w_attn = (const float*)d_in[2];
    const float* b_attn = (const float*)d_in[3];
    const float* w_proj = (const float*)d_in[4];
    const float* b_proj = (const float*)d_in[5];
    float* out = (float*)d_out;

    uint32_t *hf16, *hbh, *hbl, *qvh, *kh, *oh, *wkh, *wkl, *wqv, *wp;
    cudaGetSymbolAddress((void**)&hf16, g_hf16);
    cudaGetSymbolAddress((void**)&hbh,  g_hbh);
    cudaGetSymbolAddress((void**)&hbl,  g_hbl);
    cudaGetSymbolAddress((void**)&qvh,  g_qvh);
    cudaGetSymbolAddress((void**)&kh,   g_kh);
    cudaGetSymbolAddress((void**)&oh,   g_oh);
    cudaGetSymbolAddress((void**)&wkh,  g_wkh);
    cudaGetSymbolAddress((void**)&wkl,  g_wkl);
    cudaGetSymbolAddress((void**)&wqv,  g_wqv);
    cudaGetSymbolAddress((void**)&wp,   g_wp);

    const int att_smem = ATT_FLOATS * (int)sizeof(float);
    cudaFuncSetAttribute(attn_f16,
                         cudaFuncAttributeMaxDynamicSharedMemorySize, att_smem);
    cudaFuncSetAttribute(gemm_bf16k,
                         cudaFuncAttributeMaxDynamicSharedMemorySize, G3_SMEM_BYTES);

    // 0) prep: activations + fused weight packing
    prep_hidden<<<NROWS * 512 / 256, 256>>>(hidden, hf16, hbh, hbl);
    prep_weights<<<8192, 256>>>(w_attn, w_proj, wkh, wkl, wqv, wp);

    // 1) Q and V sections, fp16, packed output
    dim3 gqv(16, NROWS / 128);
    gemm_f16<<<gqv, 256>>>(hf16, wqv, b_attn, nullptr, qvh,
                           0, EMB, 8, 1024, 1);

    // 2) K section, bf16x3, FUSED KIVI quant -> packed fp16
    dim3 gk(EMB / 128, NROWS / 128);
    gemm_bf16k<<<gk, 256, G3_SMEM_BYTES>>>(hbh, hbl, wkh, wkl, b_attn + EMB,
                                           kh, EMB);

    // 3) attention (cp.async double-buffered KV)
    attn_f16<<<BATCH * NH * (S_LEN / 128), 256, att_smem>>>(qvh, kh, mask, oh);

    // 4) out projection, fp16, fp32 output
    dim3 gp(EMB / 128, NROWS / 128);
    gemm_f16<<<gp, 256>>>(oh, wp, b_proj, out, nullptr,
                          EMB, EMB, 16, 0, 0);
}